// round 1
// baseline (speedup 1.0000x reference)
#include <cuda_runtime.h>
#include <math.h>

// Problem constants (fixed by the dataset)
#define B   4
#define T   2048
#define D   512
#define H   8
#define DH  64
#define M_ROWS (B*T)        // 8192

// ---------------------------------------------------------------------------
// Scratch (device globals; allocation inside kernel_launch is forbidden)
// ---------------------------------------------------------------------------
__device__ float g_Qh[M_ROWS * D];    // [row, h*64+d]
__device__ float g_Kh[M_ROWS * D];
__device__ float g_Vh[M_ROWS * D];
__device__ float g_At[M_ROWS * D];    // attention output before final proj

// ---------------------------------------------------------------------------
// SGEMM: C[M,N] = A[M,K] @ W[K,N] + bias[N]   (row-major everywhere)
// Tile 128x64, K-tile 16, 256 threads, 8x4 per-thread microtile.
// ---------------------------------------------------------------------------
__global__ __launch_bounds__(256) void sgemm_bias_kernel(
    const float* __restrict__ A, const float* __restrict__ W,
    const float* __restrict__ bias, float* __restrict__ C,
    int M, int N, int K)
{
    __shared__ float As[16][132];   // transposed: As[k][m], padded vs bank conflicts
    __shared__ float Ws[16][64];

    const int tid = threadIdx.x;
    const int m0 = blockIdx.y * 128;
    const int n0 = blockIdx.x * 64;
    const int tx = tid & 15;        // column group: tx*4
    const int ty = tid >> 4;        // row group:    ty*8

    float acc[8][4];
#pragma unroll
    for (int i = 0; i < 8; i++)
#pragma unroll
        for (int j = 0; j < 4; j++) acc[i][j] = 0.f;

    for (int k0 = 0; k0 < K; k0 += 16) {
        // Load A tile: 128 rows x 16 k = 512 float4, 2 per thread
#pragma unroll
        for (int i = 0; i < 2; i++) {
            int idx = tid + i * 256;             // float4 index
            int row = idx >> 2;
            int k4  = (idx & 3) * 4;
            float4 v = *(const float4*)&A[(size_t)(m0 + row) * K + k0 + k4];
            As[k4 + 0][row] = v.x;
            As[k4 + 1][row] = v.y;
            As[k4 + 2][row] = v.z;
            As[k4 + 3][row] = v.w;
        }
        // Load W tile: 16 x 64 = 256 float4, 1 per thread
        {
            int k  = tid >> 4;
            int n4 = (tid & 15) * 4;
            *(float4*)&Ws[k][n4] = *(const float4*)&W[(size_t)(k0 + k) * N + n0 + n4];
        }
        __syncthreads();

#pragma unroll
        for (int k = 0; k < 16; k++) {
            float a[8], b[4];
            *(float4*)&a[0] = *(const float4*)&As[k][ty * 8];
            *(float4*)&a[4] = *(const float4*)&As[k][ty * 8 + 4];
            *(float4*)&b[0] = *(const float4*)&Ws[k][tx * 4];
#pragma unroll
            for (int i = 0; i < 8; i++)
#pragma unroll
                for (int j = 0; j < 4; j++)
                    acc[i][j] += a[i] * b[j];
        }
        __syncthreads();
    }

#pragma unroll
    for (int i = 0; i < 8; i++) {
        int m = m0 + ty * 8 + i;
#pragma unroll
        for (int j = 0; j < 4; j++) {
            int n = n0 + tx * 4 + j;
            C[(size_t)m * N + n] = acc[i][j] + bias[n];
        }
    }
}

// ---------------------------------------------------------------------------
// Fused RMSNorm (per 64-wide head) + RoPE, in place on [rows, H*64].
// One warp per (row, head); lane owns elements d=lane and d=lane+32.
// ---------------------------------------------------------------------------
__global__ __launch_bounds__(256) void rmsrope_kernel(
    float* __restrict__ X, const float* __restrict__ scale,
    const int* __restrict__ pos)
{
    const int warp = threadIdx.x >> 5;
    const int lane = threadIdx.x & 31;
    const long long gw = (long long)blockIdx.x * 8 + warp;   // 0..B*T*H-1
    const int h = (int)(gw & (H - 1));
    const long long row = gw >> 3;                           // b*T + t

    float* xp = X + row * D + h * DH;
    float x0 = xp[lane];
    float x1 = xp[lane + 32];

    float ss = x0 * x0 + x1 * x1;
#pragma unroll
    for (int o = 16; o; o >>= 1) ss += __shfl_xor_sync(0xffffffffu, ss, o);

    float r = rsqrtf(ss * (1.0f / 64.0f) + 1e-6f);
    float y0 = x0 * r * (1.0f + scale[lane]);
    float y1 = x1 * r * (1.0f + scale[lane + 32]);

    // RoPE: timescale = 10000^(lane/32); angle = pos / timescale
    double ts  = exp2((double)lane * (1.0 / 32.0) * 13.28771237954945);  // log2(10000)
    double ang = (double)pos[row] / ts;
    float sn = (float)sin(ang);
    float cs = (float)cos(ang);

    xp[lane]      = y0 * cs - y1 * sn;
    xp[lane + 32] = y1 * cs + y0 * sn;
}

// ---------------------------------------------------------------------------
// Causal flash attention. One thread = one query row, 128 queries/block,
// K/V streamed through smem in 64-key tiles. Each block processes two query
// tiles (qt, NQT-1-qt) so causal work is uniform (17 units) per block.
// ---------------------------------------------------------------------------
#define NQT   (T / 128)     // 16 query tiles
#define AT_BN 64

__global__ __launch_bounds__(128) void attn_kernel(
    const float* __restrict__ Q, const float* __restrict__ Km,
    const float* __restrict__ V, float* __restrict__ O)
{
    __shared__ float Ks[AT_BN][64];
    __shared__ float Vs[AT_BN][64];

    const int tid = threadIdx.x;
    const int bh  = blockIdx.y;
    const int b   = bh >> 3;
    const int h   = bh & 7;
    const float sc = 0.125f;   // 1/sqrt(64)

    for (int pass = 0; pass < 2; pass++) {
        const int qt = pass ? (NQT - 1 - (int)blockIdx.x) : (int)blockIdx.x;
        const int t  = qt * 128 + tid;
        const long long qrow = (long long)b * T + t;

        float qreg[64];
        const float* qptr = Q + qrow * D + h * DH;
#pragma unroll
        for (int i = 0; i < 16; i++)
            *(float4*)&qreg[i * 4] = *(const float4*)&qptr[i * 4];

        float o[64];
#pragma unroll
        for (int i = 0; i < 64; i++) o[i] = 0.f;
        float m = -INFINITY, l = 0.f;

        const int nmax = (qt + 1) * 128;
        for (int n0 = 0; n0 < nmax; n0 += AT_BN) {
            const float* kbase = Km + ((long long)b * T + n0) * D + h * DH;
            const float* vbase = V  + ((long long)b * T + n0) * D + h * DH;
#pragma unroll
            for (int i = 0; i < 8; i++) {
                int idx = tid + i * 128;        // 0..1023 float4 slots
                int row = idx >> 4;
                int c4  = (idx & 15) * 4;
                *(float4*)&Ks[row][c4] = *(const float4*)&kbase[(size_t)row * D + c4];
                *(float4*)&Vs[row][c4] = *(const float4*)&vbase[(size_t)row * D + c4];
            }
            __syncthreads();

            const bool full = (n0 + AT_BN) <= qt * 128;
            for (int j = 0; j < AT_BN; j++) {
                if (!full && (n0 + j) > t) break;   // causal cut (keys ascend)

                float s = 0.f;
                const float4* k4p = (const float4*)&Ks[j][0];
#pragma unroll
                for (int d4 = 0; d4 < 16; d4++) {
                    float4 kv = k4p[d4];
                    s += qreg[d4 * 4 + 0] * kv.x + qreg[d4 * 4 + 1] * kv.y
                       + qreg[d4 * 4 + 2] * kv.z + qreg[d4 * 4 + 3] * kv.w;
                }
                s *= sc;

                const float4* v4p = (const float4*)&Vs[j][0];
                float d = s - m;
                if (d <= 0.f) {
                    float p = __expf(d);
                    l += p;
#pragma unroll
                    for (int d4 = 0; d4 < 16; d4++) {
                        float4 vv = v4p[d4];
                        o[d4 * 4 + 0] += p * vv.x;
                        o[d4 * 4 + 1] += p * vv.y;
                        o[d4 * 4 + 2] += p * vv.z;
                        o[d4 * 4 + 3] += p * vv.w;
                    }
                } else {
                    float corr = __expf(-d);    // exp(old_m - s); 0 on first key
                    m = s;
                    l = l * corr + 1.f;
#pragma unroll
                    for (int d4 = 0; d4 < 16; d4++) {
                        float4 vv = v4p[d4];
                        o[d4 * 4 + 0] = o[d4 * 4 + 0] * corr + vv.x;
                        o[d4 * 4 + 1] = o[d4 * 4 + 1] * corr + vv.y;
                        o[d4 * 4 + 2] = o[d4 * 4 + 2] * corr + vv.z;
                        o[d4 * 4 + 3] = o[d4 * 4 + 3] * corr + vv.w;
                    }
                }
            }
            __syncthreads();   // protect smem before next tile / next pass
        }

        float inv = 1.0f / l;
        float* op = O + qrow * D + h * DH;
#pragma unroll
        for (int i = 0; i < 64; i++) op[i] = o[i] * inv;
    }
}

// ---------------------------------------------------------------------------
// Launcher
// Inputs: 0 q, 1 kv, 2 mask, 3 q_pos, 4 kv_pos, 5 wq, 6 bq, 7 wk, 8 bk,
//         9 wv, 10 bv, 11 scale_q, 12 scale_k, 13 wo, 14 bo
// ---------------------------------------------------------------------------
extern "C" void kernel_launch(void* const* d_in, const int* in_sizes, int n_in,
                              void* d_out, int out_size)
{
    const float* q   = (const float*)d_in[0];
    const float* kv  = (const float*)d_in[1];
    const int*   qp  = (const int*)d_in[3];
    const int*   kp  = (const int*)d_in[4];
    const float* wq  = (const float*)d_in[5];
    const float* bq  = (const float*)d_in[6];
    const float* wk  = (const float*)d_in[7];
    const float* bk  = (const float*)d_in[8];
    const float* wv  = (const float*)d_in[9];
    const float* bv  = (const float*)d_in[10];
    const float* sq  = (const float*)d_in[11];
    const float* sk  = (const float*)d_in[12];
    const float* wo  = (const float*)d_in[13];
    const float* bo  = (const float*)d_in[14];
    float* out = (float*)d_out;

    float *Qh, *Kh, *Vh, *At;
    cudaGetSymbolAddress((void**)&Qh, g_Qh);
    cudaGetSymbolAddress((void**)&Kh, g_Kh);
    cudaGetSymbolAddress((void**)&Vh, g_Vh);
    cudaGetSymbolAddress((void**)&At, g_At);

    dim3 gGemm(D / 64, M_ROWS / 128);
    sgemm_bias_kernel<<<gGemm, 256>>>(q,  wq, bq, Qh, M_ROWS, D, D);
    sgemm_bias_kernel<<<gGemm, 256>>>(kv, wk, bk, Kh, M_ROWS, D, D);
    sgemm_bias_kernel<<<gGemm, 256>>>(kv, wv, bv, Vh, M_ROWS, D, D);

    int nRowHeads = M_ROWS * H;          // 65536 warps
    rmsrope_kernel<<<nRowHeads / 8, 256>>>(Qh, sq, qp);
    rmsrope_kernel<<<nRowHeads / 8, 256>>>(Kh, sk, kp);

    dim3 gAttn(NQT / 2, B * H);
    attn_kernel<<<gAttn, 128>>>(Qh, Kh, Vh, At);

    sgemm_bias_kernel<<<gGemm, 256>>>(At, wo, bo, out, M_ROWS, D, D);
}

// round 3
// speedup vs baseline: 1.2143x; 1.2143x over previous
#include <cuda_runtime.h>
#include <cuda_bf16.h>
#include <math.h>
#include <cstdint>

// Problem constants (fixed by the dataset)
#define B   4
#define T   2048
#define D   512
#define H   8
#define DH  64
#define M_ROWS (B*T)        // 8192

// ---------------------------------------------------------------------------
// Scratch (device globals; allocation inside kernel_launch is forbidden)
// ---------------------------------------------------------------------------
__device__ float g_Qh[M_ROWS * D];
__device__ float g_Kh[M_ROWS * D];
__device__ float g_Vh[M_ROWS * D];
__device__ float g_At[M_ROWS * D];
__device__ __nv_bfloat16 g_Ahi[M_ROWS * D];   // split activation (reused)
__device__ __nv_bfloat16 g_Alo[M_ROWS * D];
__device__ __nv_bfloat16 g_Whi[D * D];        // split weight (reused)
__device__ __nv_bfloat16 g_Wlo[D * D];

// ---------------------------------------------------------------------------
// Split fp32 -> bf16 hi + bf16 lo (residual), elementwise, vectorized x4.
// ---------------------------------------------------------------------------
__global__ __launch_bounds__(256) void split_kernel(
    const float* __restrict__ X, __nv_bfloat16* __restrict__ hi,
    __nv_bfloat16* __restrict__ lo, int n4)
{
    int i = blockIdx.x * 256 + threadIdx.x;
    if (i >= n4) return;
    float4 v = ((const float4*)X)[i];
    float a[4] = {v.x, v.y, v.z, v.w};
    __nv_bfloat162 h2[2], l2[2];
#pragma unroll
    for (int j = 0; j < 2; j++) {
        __nv_bfloat16 h0 = __float2bfloat16_rn(a[2*j]);
        __nv_bfloat16 h1 = __float2bfloat16_rn(a[2*j+1]);
        __nv_bfloat16 l0 = __float2bfloat16_rn(a[2*j]   - __bfloat162float(h0));
        __nv_bfloat16 l1 = __float2bfloat16_rn(a[2*j+1] - __bfloat162float(h1));
        h2[j] = __nv_bfloat162(h0, h1);
        l2[j] = __nv_bfloat162(l0, l1);
    }
    ((uint2*)hi)[i] = *(uint2*)h2;
    ((uint2*)lo)[i] = *(uint2*)l2;
}

// ---------------------------------------------------------------------------
// HMMA GEMM with bf16 hi/lo split: C = A@W + bias, fp32-accurate.
// M=8192, N=512, K=512. CTA 128x128, BK=32, 8 warps of 64x32.
// A (hi/lo) in gmem [m][k] bf16; W (hi/lo) in gmem [k][n] bf16.
// ---------------------------------------------------------------------------
#define GK 512
#define GN 512
#define BK 32

__device__ __forceinline__ void mma16816(
    float& c0, float& c1, float& c2, float& c3,
    uint32_t a0, uint32_t a1, uint32_t a2, uint32_t a3,
    uint32_t b0, uint32_t b1)
{
    asm volatile(
        "mma.sync.aligned.m16n8k16.row.col.f32.bf16.bf16.f32 "
        "{%0,%1,%2,%3}, {%4,%5,%6,%7}, {%8,%9}, {%0,%1,%2,%3};"
        : "+f"(c0), "+f"(c1), "+f"(c2), "+f"(c3)
        : "r"(a0), "r"(a1), "r"(a2), "r"(a3), "r"(b0), "r"(b1));
}

__global__ __launch_bounds__(256, 2) void gemm_mma_kernel(
    const __nv_bfloat16* __restrict__ Ahi, const __nv_bfloat16* __restrict__ Alo,
    const __nv_bfloat16* __restrict__ Whi, const __nv_bfloat16* __restrict__ Wlo,
    const float* __restrict__ bias, float* __restrict__ C)
{
    __shared__ __align__(16) __nv_bfloat16 Ash[128][40];   // pad: 80B stride
    __shared__ __align__(16) __nv_bfloat16 Asl[128][40];
    __shared__ __align__(16) __nv_bfloat16 Bsh[BK][136];   // pad: 272B stride
    __shared__ __align__(16) __nv_bfloat16 Bsl[BK][136];

    const int tid  = threadIdx.x;
    const int lane = tid & 31;
    const int wid  = tid >> 5;
    const int wm   = wid >> 2;          // 0..1 -> 64 rows
    const int wn   = wid & 3;           // 0..3 -> 32 cols
    const int m0   = blockIdx.y * 128;
    const int n0   = blockIdx.x * 128;
    const int gid  = lane >> 2;         // groupID
    const int tig  = lane & 3;          // thread-in-group

    float c[4][4][4];
#pragma unroll
    for (int mf = 0; mf < 4; mf++)
#pragma unroll
        for (int nf = 0; nf < 4; nf++)
#pragma unroll
            for (int r = 0; r < 4; r++) c[mf][nf][r] = 0.f;

    for (int kc = 0; kc < GK; kc += BK) {
        // -- copy A tile (128x32 bf16, hi+lo): 512 uint4, 2/thread --
#pragma unroll
        for (int i = 0; i < 2; i++) {
            int idx = tid + i * 256;
            int row = idx >> 2;
            int c8  = (idx & 3) * 8;
            size_t g = (size_t)(m0 + row) * GK + kc + c8;
            *(uint4*)&Ash[row][c8] = *(const uint4*)&Ahi[g];
            *(uint4*)&Asl[row][c8] = *(const uint4*)&Alo[g];
        }
        // -- copy W tile (32x128 bf16, hi+lo): 512 uint4, 2/thread --
#pragma unroll
        for (int i = 0; i < 2; i++) {
            int idx = tid + i * 256;
            int k   = idx >> 4;
            int n8  = (idx & 15) * 8;
            size_t g = (size_t)(kc + k) * GN + n0 + n8;
            *(uint4*)&Bsh[k][n8] = *(const uint4*)&Whi[g];
            *(uint4*)&Bsl[k][n8] = *(const uint4*)&Wlo[g];
        }
        __syncthreads();

#pragma unroll
        for (int s = 0; s < 2; s++) {
            const int kb = s * 16 + tig * 2;
            // A fragments (hi & lo)
            uint32_t ah[4][4], al[4][4];
#pragma unroll
            for (int mf = 0; mf < 4; mf++) {
                int row = wm * 64 + mf * 16 + gid;
                ah[mf][0] = *(const uint32_t*)&Ash[row    ][kb    ];
                ah[mf][1] = *(const uint32_t*)&Ash[row + 8][kb    ];
                ah[mf][2] = *(const uint32_t*)&Ash[row    ][kb + 8];
                ah[mf][3] = *(const uint32_t*)&Ash[row + 8][kb + 8];
                al[mf][0] = *(const uint32_t*)&Asl[row    ][kb    ];
                al[mf][1] = *(const uint32_t*)&Asl[row + 8][kb    ];
                al[mf][2] = *(const uint32_t*)&Asl[row    ][kb + 8];
                al[mf][3] = *(const uint32_t*)&Asl[row + 8][kb + 8];
            }
            // B hi fragments
            uint32_t bh[4][2];
#pragma unroll
            for (int nf = 0; nf < 4; nf++) {
                int n  = wn * 32 + nf * 8 + gid;
                int k0 = s * 16 + tig * 2;
                unsigned short t0 = *(const unsigned short*)&Bsh[k0    ][n];
                unsigned short t1 = *(const unsigned short*)&Bsh[k0 + 1][n];
                unsigned short t2 = *(const unsigned short*)&Bsh[k0 + 8][n];
                unsigned short t3 = *(const unsigned short*)&Bsh[k0 + 9][n];
                bh[nf][0] = (uint32_t)t0 | ((uint32_t)t1 << 16);
                bh[nf][1] = (uint32_t)t2 | ((uint32_t)t3 << 16);
            }
            // Ahi*Bhi and Alo*Bhi
#pragma unroll
            for (int mf = 0; mf < 4; mf++)
#pragma unroll
                for (int nf = 0; nf < 4; nf++) {
                    mma16816(c[mf][nf][0], c[mf][nf][1], c[mf][nf][2], c[mf][nf][3],
                             ah[mf][0], ah[mf][1], ah[mf][2], ah[mf][3],
                             bh[nf][0], bh[nf][1]);
                    mma16816(c[mf][nf][0], c[mf][nf][1], c[mf][nf][2], c[mf][nf][3],
                             al[mf][0], al[mf][1], al[mf][2], al[mf][3],
                             bh[nf][0], bh[nf][1]);
                }
            // B lo fragments, Ahi*Blo
#pragma unroll
            for (int nf = 0; nf < 4; nf++) {
                int n  = wn * 32 + nf * 8 + gid;
                int k0 = s * 16 + tig * 2;
                unsigned short t0 = *(const unsigned short*)&Bsl[k0    ][n];
                unsigned short t1 = *(const unsigned short*)&Bsl[k0 + 1][n];
                unsigned short t2 = *(const unsigned short*)&Bsl[k0 + 8][n];
                unsigned short t3 = *(const unsigned short*)&Bsl[k0 + 9][n];
                uint32_t b0 = (uint32_t)t0 | ((uint32_t)t1 << 16);
                uint32_t b1 = (uint32_t)t2 | ((uint32_t)t3 << 16);
#pragma unroll
                for (int mf = 0; mf < 4; mf++)
                    mma16816(c[mf][nf][0], c[mf][nf][1], c[mf][nf][2], c[mf][nf][3],
                             ah[mf][0], ah[mf][1], ah[mf][2], ah[mf][3], b0, b1);
            }
        }
        __syncthreads();
    }

    // epilogue: += bias, store fp32
#pragma unroll
    for (int mf = 0; mf < 4; mf++) {
        int m = m0 + wm * 64 + mf * 16 + gid;
#pragma unroll
        for (int nf = 0; nf < 4; nf++) {
            int n = n0 + wn * 32 + nf * 8 + tig * 2;
            float b0 = __ldg(&bias[n]), b1 = __ldg(&bias[n + 1]);
            float2 v0 = make_float2(c[mf][nf][0] + b0, c[mf][nf][1] + b1);
            float2 v1 = make_float2(c[mf][nf][2] + b0, c[mf][nf][3] + b1);
            *(float2*)&C[(size_t)m * GN + n]       = v0;
            *(float2*)&C[(size_t)(m + 8) * GN + n] = v1;
        }
    }
}

// ---------------------------------------------------------------------------
// Fused RMSNorm (per 64-wide head) + RoPE, in place on [rows, H*64].
// ---------------------------------------------------------------------------
__global__ __launch_bounds__(256) void rmsrope_kernel(
    float* __restrict__ X, const float* __restrict__ scale,
    const int* __restrict__ pos)
{
    const int warp = threadIdx.x >> 5;
    const int lane = threadIdx.x & 31;
    const long long gw = (long long)blockIdx.x * 8 + warp;
    const int h = (int)(gw & (H - 1));
    const long long row = gw >> 3;

    float* xp = X + row * D + h * DH;
    float x0 = xp[lane];
    float x1 = xp[lane + 32];

    float ss = x0 * x0 + x1 * x1;
#pragma unroll
    for (int o = 16; o; o >>= 1) ss += __shfl_xor_sync(0xffffffffu, ss, o);

    float r = rsqrtf(ss * (1.0f / 64.0f) + 1e-6f);
    float y0 = x0 * r * (1.0f + scale[lane]);
    float y1 = x1 * r * (1.0f + scale[lane + 32]);

    double ts  = exp2((double)lane * (1.0 / 32.0) * 13.28771237954945);  // log2(10000)
    double ang = (double)pos[row] / ts;
    float sn = (float)sin(ang);
    float cs = (float)cos(ang);

    xp[lane]      = y0 * cs - y1 * sn;
    xp[lane + 32] = y1 * cs + y0 * sn;
}

// ---------------------------------------------------------------------------
// Causal flash attention (fp32 SIMT; HMMA port is the next target).
// ---------------------------------------------------------------------------
#define NQT   (T / 128)
#define AT_BN 64

__global__ __launch_bounds__(128) void attn_kernel(
    const float* __restrict__ Q, const float* __restrict__ Km,
    const float* __restrict__ V, float* __restrict__ O)
{
    __shared__ float Ks[AT_BN][64];
    __shared__ float Vs[AT_BN][64];

    const int tid = threadIdx.x;
    const int bh  = blockIdx.y;
    const int b   = bh >> 3;
    const int h   = bh & 7;
    const float sc = 0.125f;

    for (int pass = 0; pass < 2; pass++) {
        const int qt = pass ? (NQT - 1 - (int)blockIdx.x) : (int)blockIdx.x;
        const int t  = qt * 128 + tid;
        const long long qrow = (long long)b * T + t;

        float qreg[64];
        const float* qptr = Q + qrow * D + h * DH;
#pragma unroll
        for (int i = 0; i < 16; i++)
            *(float4*)&qreg[i * 4] = *(const float4*)&qptr[i * 4];

        float o[64];
#pragma unroll
        for (int i = 0; i < 64; i++) o[i] = 0.f;
        float m = -INFINITY, l = 0.f;

        const int nmax = (qt + 1) * 128;
        for (int n0 = 0; n0 < nmax; n0 += AT_BN) {
            const float* kbase = Km + ((long long)b * T + n0) * D + h * DH;
            const float* vbase = V  + ((long long)b * T + n0) * D + h * DH;
#pragma unroll
            for (int i = 0; i < 8; i++) {
                int idx = tid + i * 128;
                int row = idx >> 4;
                int c4  = (idx & 15) * 4;
                *(float4*)&Ks[row][c4] = *(const float4*)&kbase[(size_t)row * D + c4];
                *(float4*)&Vs[row][c4] = *(const float4*)&vbase[(size_t)row * D + c4];
            }
            __syncthreads();

            const bool full = (n0 + AT_BN) <= qt * 128;
            for (int j = 0; j < AT_BN; j++) {
                if (!full && (n0 + j) > t) break;

                float s = 0.f;
                const float4* k4p = (const float4*)&Ks[j][0];
#pragma unroll
                for (int d4 = 0; d4 < 16; d4++) {
                    float4 kv = k4p[d4];
                    s += qreg[d4 * 4 + 0] * kv.x + qreg[d4 * 4 + 1] * kv.y
                       + qreg[d4 * 4 + 2] * kv.z + qreg[d4 * 4 + 3] * kv.w;
                }
                s *= sc;

                const float4* v4p = (const float4*)&Vs[j][0];
                float d = s - m;
                if (d <= 0.f) {
                    float p = __expf(d);
                    l += p;
#pragma unroll
                    for (int d4 = 0; d4 < 16; d4++) {
                        float4 vv = v4p[d4];
                        o[d4 * 4 + 0] += p * vv.x;
                        o[d4 * 4 + 1] += p * vv.y;
                        o[d4 * 4 + 2] += p * vv.z;
                        o[d4 * 4 + 3] += p * vv.w;
                    }
                } else {
                    float corr = __expf(-d);
                    m = s;
                    l = l * corr + 1.f;
#pragma unroll
                    for (int d4 = 0; d4 < 16; d4++) {
                        float4 vv = v4p[d4];
                        o[d4 * 4 + 0] = o[d4 * 4 + 0] * corr + vv.x;
                        o[d4 * 4 + 1] = o[d4 * 4 + 1] * corr + vv.y;
                        o[d4 * 4 + 2] = o[d4 * 4 + 2] * corr + vv.z;
                        o[d4 * 4 + 3] = o[d4 * 4 + 3] * corr + vv.w;
                    }
                }
            }
            __syncthreads();
        }

        float inv = 1.0f / l;
        float* op = O + qrow * D + h * DH;
#pragma unroll
        for (int i = 0; i < 64; i++) op[i] = o[i] * inv;
    }
}

// ---------------------------------------------------------------------------
// Launcher
// Inputs: 0 q, 1 kv, 2 mask, 3 q_pos, 4 kv_pos, 5 wq, 6 bq, 7 wk, 8 bk,
//         9 wv, 10 bv, 11 scale_q, 12 scale_k, 13 wo, 14 bo
// ---------------------------------------------------------------------------
extern "C" void kernel_launch(void* const* d_in, const int* in_sizes, int n_in,
                              void* d_out, int out_size)
{
    const float* q   = (const float*)d_in[0];
    const float* kv  = (const float*)d_in[1];
    const int*   qp  = (const int*)d_in[3];
    const int*   kp  = (const int*)d_in[4];
    const float* wq  = (const float*)d_in[5];
    const float* bq  = (const float*)d_in[6];
    const float* wk  = (const float*)d_in[7];
    const float* bk  = (const float*)d_in[8];
    const float* wv  = (const float*)d_in[9];
    const float* bv  = (const float*)d_in[10];
    const float* sq  = (const float*)d_in[11];
    const float* sk  = (const float*)d_in[12];
    const float* wo  = (const float*)d_in[13];
    const float* bo  = (const float*)d_in[14];
    float* out = (float*)d_out;

    float *Qh, *Kh, *Vh, *At;
    __nv_bfloat16 *Ahi, *Alo, *Whi, *Wlo;
    cudaGetSymbolAddress((void**)&Qh, g_Qh);
    cudaGetSymbolAddress((void**)&Kh, g_Kh);
    cudaGetSymbolAddress((void**)&Vh, g_Vh);
    cudaGetSymbolAddress((void**)&At, g_At);
    cudaGetSymbolAddress((void**)&Ahi, g_Ahi);
    cudaGetSymbolAddress((void**)&Alo, g_Alo);
    cudaGetSymbolAddress((void**)&Whi, g_Whi);
    cudaGetSymbolAddress((void**)&Wlo, g_Wlo);

    const int nA4 = M_ROWS * D / 4;    // 1048576
    const int nW4 = D * D / 4;         // 65536
    dim3 gGemm(GN / 128, M_ROWS / 128);

    // Q projection
    split_kernel<<<nA4 / 256, 256>>>(q, Ahi, Alo, nA4);
    split_kernel<<<nW4 / 256, 256>>>(wq, Whi, Wlo, nW4);
    gemm_mma_kernel<<<gGemm, 256>>>(Ahi, Alo, Whi, Wlo, bq, Qh);
    // K/V projections (share kv split)
    split_kernel<<<nA4 / 256, 256>>>(kv, Ahi, Alo, nA4);
    split_kernel<<<nW4 / 256, 256>>>(wk, Whi, Wlo, nW4);
    gemm_mma_kernel<<<gGemm, 256>>>(Ahi, Alo, Whi, Wlo, bk, Kh);
    split_kernel<<<nW4 / 256, 256>>>(wv, Whi, Wlo, nW4);
    gemm_mma_kernel<<<gGemm, 256>>>(Ahi, Alo, Whi, Wlo, bv, Vh);

    int nRowHeads = M_ROWS * H;
    rmsrope_kernel<<<nRowHeads / 8, 256>>>(Qh, sq, qp);
    rmsrope_kernel<<<nRowHeads / 8, 256>>>(Kh, sk, kp);

    dim3 gAttn(NQT / 2, B * H);
    attn_kernel<<<gAttn, 128>>>(Qh, Kh, Vh, At);

    // Output projection
    split_kernel<<<nA4 / 256, 256>>>(At, Ahi, Alo, nA4);
    split_kernel<<<nW4 / 256, 256>>>(wo, Whi, Wlo, nW4);
    gemm_mma_kernel<<<gGemm, 256>>>(Ahi, Alo, Whi, Wlo, bo, out);
}

// round 4
// speedup vs baseline: 2.8770x; 2.3694x over previous
#include <cuda_runtime.h>
#include <cuda_bf16.h>
#include <math.h>
#include <cstdint>

// Problem constants (fixed by the dataset)
#define B   4
#define T   2048
#define D   512
#define H   8
#define DH  64
#define M_ROWS (B*T)        // 8192
#define BH  (B*H)           // 32

// ---------------------------------------------------------------------------
// Scratch (device globals; allocation inside kernel_launch is forbidden)
// ---------------------------------------------------------------------------
__device__ float g_Qh[M_ROWS * D];                 // fp32 projections (pre-norm)
__device__ float g_Kh[M_ROWS * D];
__device__ float g_Vh[M_ROWS * D];
__device__ __nv_bfloat16 g_Ahi[M_ROWS * D];        // split activations (GEMM A)
__device__ __nv_bfloat16 g_Alo[M_ROWS * D];
__device__ __nv_bfloat16 g_Whi[D * D];
__device__ __nv_bfloat16 g_Wlo[D * D];
// head-major [b][h][t][64] bf16 hi/lo for attention
__device__ __nv_bfloat16 g_Qhi[BH * T * DH];
__device__ __nv_bfloat16 g_Qlo[BH * T * DH];
__device__ __nv_bfloat16 g_Khi[BH * T * DH];
__device__ __nv_bfloat16 g_Klo[BH * T * DH];
__device__ __nv_bfloat16 g_Vhi[BH * T * DH];
__device__ __nv_bfloat16 g_Vlo[BH * T * DH];

// ---------------------------------------------------------------------------
// Split fp32 -> bf16 hi + bf16 lo (residual), elementwise, vectorized x4.
// ---------------------------------------------------------------------------
__global__ __launch_bounds__(256) void split_kernel(
    const float* __restrict__ X, __nv_bfloat16* __restrict__ hi,
    __nv_bfloat16* __restrict__ lo, int n4)
{
    int i = blockIdx.x * 256 + threadIdx.x;
    if (i >= n4) return;
    float4 v = ((const float4*)X)[i];
    float a[4] = {v.x, v.y, v.z, v.w};
    __nv_bfloat162 h2[2], l2[2];
#pragma unroll
    for (int j = 0; j < 2; j++) {
        __nv_bfloat16 h0 = __float2bfloat16_rn(a[2*j]);
        __nv_bfloat16 h1 = __float2bfloat16_rn(a[2*j+1]);
        __nv_bfloat16 l0 = __float2bfloat16_rn(a[2*j]   - __bfloat162float(h0));
        __nv_bfloat16 l1 = __float2bfloat16_rn(a[2*j+1] - __bfloat162float(h1));
        h2[j] = __nv_bfloat162(h0, h1);
        l2[j] = __nv_bfloat162(l0, l1);
    }
    ((uint2*)hi)[i] = *(uint2*)h2;
    ((uint2*)lo)[i] = *(uint2*)l2;
}

// ---------------------------------------------------------------------------
// m16n8k16 bf16 MMA wrapper
// ---------------------------------------------------------------------------
__device__ __forceinline__ void mma16816(
    float& c0, float& c1, float& c2, float& c3,
    uint32_t a0, uint32_t a1, uint32_t a2, uint32_t a3,
    uint32_t b0, uint32_t b1)
{
    asm volatile(
        "mma.sync.aligned.m16n8k16.row.col.f32.bf16.bf16.f32 "
        "{%0,%1,%2,%3}, {%4,%5,%6,%7}, {%8,%9}, {%0,%1,%2,%3};"
        : "+f"(c0), "+f"(c1), "+f"(c2), "+f"(c3)
        : "r"(a0), "r"(a1), "r"(a2), "r"(a3), "r"(b0), "r"(b1));
}

// ---------------------------------------------------------------------------
// HMMA GEMM with bf16 hi/lo split: C = A@W + bias, fp32-accurate.
// M=8192, N=512, K=512. CTA 128x128, BK=32, 8 warps of 64x32.
// ---------------------------------------------------------------------------
#define GK 512
#define GN 512
#define BK 32

__global__ __launch_bounds__(256, 2) void gemm_mma_kernel(
    const __nv_bfloat16* __restrict__ Ahi, const __nv_bfloat16* __restrict__ Alo,
    const __nv_bfloat16* __restrict__ Whi, const __nv_bfloat16* __restrict__ Wlo,
    const float* __restrict__ bias, float* __restrict__ C)
{
    __shared__ __align__(16) __nv_bfloat16 Ash[128][40];
    __shared__ __align__(16) __nv_bfloat16 Asl[128][40];
    __shared__ __align__(16) __nv_bfloat16 Bsh[BK][136];
    __shared__ __align__(16) __nv_bfloat16 Bsl[BK][136];

    const int tid  = threadIdx.x;
    const int lane = tid & 31;
    const int wid  = tid >> 5;
    const int wm   = wid >> 2;
    const int wn   = wid & 3;
    const int m0   = blockIdx.y * 128;
    const int n0   = blockIdx.x * 128;
    const int gid  = lane >> 2;
    const int tig  = lane & 3;

    float c[4][4][4];
#pragma unroll
    for (int mf = 0; mf < 4; mf++)
#pragma unroll
        for (int nf = 0; nf < 4; nf++)
#pragma unroll
            for (int r = 0; r < 4; r++) c[mf][nf][r] = 0.f;

    for (int kc = 0; kc < GK; kc += BK) {
#pragma unroll
        for (int i = 0; i < 2; i++) {
            int idx = tid + i * 256;
            int row = idx >> 2;
            int c8  = (idx & 3) * 8;
            size_t g = (size_t)(m0 + row) * GK + kc + c8;
            *(uint4*)&Ash[row][c8] = *(const uint4*)&Ahi[g];
            *(uint4*)&Asl[row][c8] = *(const uint4*)&Alo[g];
        }
#pragma unroll
        for (int i = 0; i < 2; i++) {
            int idx = tid + i * 256;
            int k   = idx >> 4;
            int n8  = (idx & 15) * 8;
            size_t g = (size_t)(kc + k) * GN + n0 + n8;
            *(uint4*)&Bsh[k][n8] = *(const uint4*)&Whi[g];
            *(uint4*)&Bsl[k][n8] = *(const uint4*)&Wlo[g];
        }
        __syncthreads();

#pragma unroll
        for (int s = 0; s < 2; s++) {
            const int kb = s * 16 + tig * 2;
            uint32_t ah[4][4], al[4][4];
#pragma unroll
            for (int mf = 0; mf < 4; mf++) {
                int row = wm * 64 + mf * 16 + gid;
                ah[mf][0] = *(const uint32_t*)&Ash[row    ][kb    ];
                ah[mf][1] = *(const uint32_t*)&Ash[row + 8][kb    ];
                ah[mf][2] = *(const uint32_t*)&Ash[row    ][kb + 8];
                ah[mf][3] = *(const uint32_t*)&Ash[row + 8][kb + 8];
                al[mf][0] = *(const uint32_t*)&Asl[row    ][kb    ];
                al[mf][1] = *(const uint32_t*)&Asl[row + 8][kb    ];
                al[mf][2] = *(const uint32_t*)&Asl[row    ][kb + 8];
                al[mf][3] = *(const uint32_t*)&Asl[row + 8][kb + 8];
            }
            uint32_t bh[4][2];
#pragma unroll
            for (int nf = 0; nf < 4; nf++) {
                int n  = wn * 32 + nf * 8 + gid;
                int k0 = s * 16 + tig * 2;
                unsigned short t0 = *(const unsigned short*)&Bsh[k0    ][n];
                unsigned short t1 = *(const unsigned short*)&Bsh[k0 + 1][n];
                unsigned short t2 = *(const unsigned short*)&Bsh[k0 + 8][n];
                unsigned short t3 = *(const unsigned short*)&Bsh[k0 + 9][n];
                bh[nf][0] = (uint32_t)t0 | ((uint32_t)t1 << 16);
                bh[nf][1] = (uint32_t)t2 | ((uint32_t)t3 << 16);
            }
#pragma unroll
            for (int mf = 0; mf < 4; mf++)
#pragma unroll
                for (int nf = 0; nf < 4; nf++) {
                    mma16816(c[mf][nf][0], c[mf][nf][1], c[mf][nf][2], c[mf][nf][3],
                             ah[mf][0], ah[mf][1], ah[mf][2], ah[mf][3],
                             bh[nf][0], bh[nf][1]);
                    mma16816(c[mf][nf][0], c[mf][nf][1], c[mf][nf][2], c[mf][nf][3],
                             al[mf][0], al[mf][1], al[mf][2], al[mf][3],
                             bh[nf][0], bh[nf][1]);
                }
#pragma unroll
            for (int nf = 0; nf < 4; nf++) {
                int n  = wn * 32 + nf * 8 + gid;
                int k0 = s * 16 + tig * 2;
                unsigned short t0 = *(const unsigned short*)&Bsl[k0    ][n];
                unsigned short t1 = *(const unsigned short*)&Bsl[k0 + 1][n];
                unsigned short t2 = *(const unsigned short*)&Bsl[k0 + 8][n];
                unsigned short t3 = *(const unsigned short*)&Bsl[k0 + 9][n];
                uint32_t b0 = (uint32_t)t0 | ((uint32_t)t1 << 16);
                uint32_t b1 = (uint32_t)t2 | ((uint32_t)t3 << 16);
#pragma unroll
                for (int mf = 0; mf < 4; mf++)
                    mma16816(c[mf][nf][0], c[mf][nf][1], c[mf][nf][2], c[mf][nf][3],
                             ah[mf][0], ah[mf][1], ah[mf][2], ah[mf][3], b0, b1);
            }
        }
        __syncthreads();
    }

#pragma unroll
    for (int mf = 0; mf < 4; mf++) {
        int m = m0 + wm * 64 + mf * 16 + gid;
#pragma unroll
        for (int nf = 0; nf < 4; nf++) {
            int n = n0 + wn * 32 + nf * 8 + tig * 2;
            float b0 = __ldg(&bias[n]), b1 = __ldg(&bias[n + 1]);
            float2 v0 = make_float2(c[mf][nf][0] + b0, c[mf][nf][1] + b1);
            float2 v1 = make_float2(c[mf][nf][2] + b0, c[mf][nf][3] + b1);
            *(float2*)&C[(size_t)m * GN + n]       = v0;
            *(float2*)&C[(size_t)(m + 8) * GN + n] = v1;
        }
    }
}

// ---------------------------------------------------------------------------
// RMSNorm + RoPE, fp32 in -> head-major bf16 hi/lo out [b][h][t][64].
// One warp per (row, head); lane owns d=lane and d=lane+32.
// ---------------------------------------------------------------------------
__global__ __launch_bounds__(256) void rmsropeb_kernel(
    const float* __restrict__ X, const float* __restrict__ scale,
    const int* __restrict__ pos,
    __nv_bfloat16* __restrict__ hi, __nv_bfloat16* __restrict__ lo)
{
    const int warp = threadIdx.x >> 5;
    const int lane = threadIdx.x & 31;
    const long long gw = (long long)blockIdx.x * 8 + warp;   // 0..B*T*H-1
    const int h = (int)(gw & (H - 1));
    const long long row = gw >> 3;                           // b*T + t
    const int b = (int)(row >> 11);
    const int t = (int)(row & 2047);

    const float* xp = X + row * D + h * DH;
    float x0 = xp[lane];
    float x1 = xp[lane + 32];

    float ss = x0 * x0 + x1 * x1;
#pragma unroll
    for (int o = 16; o; o >>= 1) ss += __shfl_xor_sync(0xffffffffu, ss, o);

    float r = rsqrtf(ss * (1.0f / 64.0f) + 1e-6f);
    float y0 = x0 * r * (1.0f + scale[lane]);
    float y1 = x1 * r * (1.0f + scale[lane + 32]);

    double ts  = exp2((double)lane * (1.0 / 32.0) * 13.28771237954945);  // log2(10000)
    double ang = (double)pos[row] / ts;
    float sn = (float)sin(ang);
    float cs = (float)cos(ang);

    float v0 = y0 * cs - y1 * sn;
    float v1 = y1 * cs + y0 * sn;

    size_t o0 = ((size_t)(b * H + h) * T + t) * DH + lane;
    __nv_bfloat16 h0 = __float2bfloat16_rn(v0);
    __nv_bfloat16 h1 = __float2bfloat16_rn(v1);
    hi[o0]      = h0;
    hi[o0 + 32] = h1;
    lo[o0]      = __float2bfloat16_rn(v0 - __bfloat162float(h0));
    lo[o0 + 32] = __float2bfloat16_rn(v1 - __bfloat162float(h1));
}

// ---------------------------------------------------------------------------
// V: fp32 [row][h*64+d] -> head-major bf16 hi/lo [b][h][t][64] (pairwise).
// ---------------------------------------------------------------------------
__global__ __launch_bounds__(256) void vconv_kernel(
    const float* __restrict__ V,
    __nv_bfloat16* __restrict__ hi, __nv_bfloat16* __restrict__ lo)
{
    int i = blockIdx.x * 256 + threadIdx.x;          // pair index
    if (i >= M_ROWS * D / 2) return;
    int e0 = i * 2;
    int row = e0 >> 9;
    int c   = e0 & 511;
    int h = c >> 6, d = c & 63;
    int b = row >> 11, t = row & 2047;
    float2 v = *(const float2*)&V[(size_t)row * D + c];
    __nv_bfloat16 h0 = __float2bfloat16_rn(v.x);
    __nv_bfloat16 h1 = __float2bfloat16_rn(v.y);
    __nv_bfloat162 hp(h0, h1);
    __nv_bfloat162 lp(__float2bfloat16_rn(v.x - __bfloat162float(h0)),
                      __float2bfloat16_rn(v.y - __bfloat162float(h1)));
    size_t oi = ((size_t)(b * H + h) * T + t) * DH + d;
    *(__nv_bfloat162*)&hi[oi] = hp;
    *(__nv_bfloat162*)&lo[oi] = lp;
}

// ---------------------------------------------------------------------------
// HMMA causal flash attention.
// grid (8, 32): blockIdx.y = b*8+h; each CTA runs q-tiles bx and 15-bx.
// CTA: 128 queries, 4 warps x 32 queries. 64-key K/V smem tiles, V transposed.
// S = (Qhi+Qlo)(Khi+Klo)^T via 3 MMAs; PV via Phi*Vhi + Phi*Vlo + Plo*Vhi.
// Output split to bf16 hi/lo activation buffers (GEMM-A layout [row][512]).
// ---------------------------------------------------------------------------
#define ATT_SQH 0
#define ATT_SQL 18432
#define ATT_SKH 36864
#define ATT_SKL 46080
#define ATT_SVH 55296
#define ATT_SVL 64512
#define ATT_SMEM 73728

__global__ __launch_bounds__(128) void attn_mma_kernel(
    const __nv_bfloat16* __restrict__ Qhi, const __nv_bfloat16* __restrict__ Qlo,
    const __nv_bfloat16* __restrict__ Khi, const __nv_bfloat16* __restrict__ Klo,
    const __nv_bfloat16* __restrict__ Vhi, const __nv_bfloat16* __restrict__ Vlo,
    __nv_bfloat16* __restrict__ Ohi, __nv_bfloat16* __restrict__ Olo)
{
    extern __shared__ char sm[];
    __nv_bfloat16 (*Qsh)[72] = (__nv_bfloat16(*)[72])(sm + ATT_SQH);
    __nv_bfloat16 (*Qsl)[72] = (__nv_bfloat16(*)[72])(sm + ATT_SQL);
    __nv_bfloat16 (*Ksh)[72] = (__nv_bfloat16(*)[72])(sm + ATT_SKH);  // [key][d]
    __nv_bfloat16 (*Ksl)[72] = (__nv_bfloat16(*)[72])(sm + ATT_SKL);
    __nv_bfloat16 (*Vth)[72] = (__nv_bfloat16(*)[72])(sm + ATT_SVH);  // [d][key]
    __nv_bfloat16 (*Vtl)[72] = (__nv_bfloat16(*)[72])(sm + ATT_SVL);

    const int tid  = threadIdx.x;
    const int lane = tid & 31;
    const int w    = tid >> 5;
    const int gid  = lane >> 2;
    const int tig  = lane & 3;
    const int bh   = blockIdx.y;
    const int b    = bh >> 3;
    const int h    = bh & 7;
    const size_t headbase = (size_t)bh * T * DH;

    for (int pass = 0; pass < 2; pass++) {
        const int qt = pass ? (15 - (int)blockIdx.x) : (int)blockIdx.x;
        const int q0 = qt * 128;

        // ---- load Q tile (128x64 hi/lo), coalesced ----
#pragma unroll
        for (int i = 0; i < 8; i++) {
            int idx = tid + i * 128;
            int row = idx >> 3;
            int c8  = (idx & 7) * 8;
            size_t g = headbase + (size_t)(q0 + row) * DH + c8;
            *(uint4*)&Qsh[row][c8] = *(const uint4*)&Qhi[g];
            *(uint4*)&Qsl[row][c8] = *(const uint4*)&Qlo[g];
        }
        __syncthreads();

        float O[2][8][4];
#pragma unroll
        for (int mf = 0; mf < 2; mf++)
#pragma unroll
            for (int nf = 0; nf < 8; nf++)
#pragma unroll
                for (int r = 0; r < 4; r++) O[mf][nf][r] = 0.f;
        float mrow[4] = {-1e30f, -1e30f, -1e30f, -1e30f};
        float lrow[4] = {0.f, 0.f, 0.f, 0.f};

        const int qwb = q0 + w * 32;       // warp's first query (absolute)
        const int nkt = (qt + 1) * 2;      // 64-key tiles

        for (int kt = 0; kt < nkt; kt++) {
            const int n0 = kt * 64;
            // ---- load K (row layout) and V (transposed) tiles ----
#pragma unroll
            for (int i = 0; i < 4; i++) {
                int idx = tid + i * 128;
                int key = idx >> 3;
                int c8  = (idx & 7) * 8;
                size_t g = headbase + (size_t)(n0 + key) * DH + c8;
                *(uint4*)&Ksh[key][c8] = *(const uint4*)&Khi[g];
                *(uint4*)&Ksl[key][c8] = *(const uint4*)&Klo[g];
                uint4 vh = *(const uint4*)&Vhi[g];
                uint4 vl = *(const uint4*)&Vlo[g];
                __nv_bfloat16 th[8], tl[8];
                *(uint4*)th = vh; *(uint4*)tl = vl;
#pragma unroll
                for (int j = 0; j < 8; j++) {
                    Vth[c8 + j][key] = th[j];
                    Vtl[c8 + j][key] = tl[j];
                }
            }
            __syncthreads();

            const bool active = (n0 <= qwb + 31);
            if (active) {
                // ---- S = Q K^T (3-way split) ----
                float S[2][8][4];
#pragma unroll
                for (int mf = 0; mf < 2; mf++)
#pragma unroll
                    for (int nf = 0; nf < 8; nf++)
#pragma unroll
                        for (int r = 0; r < 4; r++) S[mf][nf][r] = 0.f;

#pragma unroll
                for (int ks = 0; ks < 4; ks++) {
                    const int kb = ks * 16 + tig * 2;
                    uint32_t ah[2][4], al[2][4];
#pragma unroll
                    for (int mf = 0; mf < 2; mf++) {
                        int qr = w * 32 + mf * 16 + gid;
                        ah[mf][0] = *(const uint32_t*)&Qsh[qr    ][kb    ];
                        ah[mf][1] = *(const uint32_t*)&Qsh[qr + 8][kb    ];
                        ah[mf][2] = *(const uint32_t*)&Qsh[qr    ][kb + 8];
                        ah[mf][3] = *(const uint32_t*)&Qsh[qr + 8][kb + 8];
                        al[mf][0] = *(const uint32_t*)&Qsl[qr    ][kb    ];
                        al[mf][1] = *(const uint32_t*)&Qsl[qr + 8][kb    ];
                        al[mf][2] = *(const uint32_t*)&Qsl[qr    ][kb + 8];
                        al[mf][3] = *(const uint32_t*)&Qsl[qr + 8][kb + 8];
                    }
#pragma unroll
                    for (int nf = 0; nf < 8; nf++) {
                        int kr = nf * 8 + gid;
                        uint32_t bh0 = *(const uint32_t*)&Ksh[kr][kb];
                        uint32_t bh1 = *(const uint32_t*)&Ksh[kr][kb + 8];
                        uint32_t bl0 = *(const uint32_t*)&Ksl[kr][kb];
                        uint32_t bl1 = *(const uint32_t*)&Ksl[kr][kb + 8];
#pragma unroll
                        for (int mf = 0; mf < 2; mf++) {
                            mma16816(S[mf][nf][0], S[mf][nf][1], S[mf][nf][2], S[mf][nf][3],
                                     ah[mf][0], ah[mf][1], ah[mf][2], ah[mf][3], bh0, bh1);
                            mma16816(S[mf][nf][0], S[mf][nf][1], S[mf][nf][2], S[mf][nf][3],
                                     ah[mf][0], ah[mf][1], ah[mf][2], ah[mf][3], bl0, bl1);
                            mma16816(S[mf][nf][0], S[mf][nf][1], S[mf][nf][2], S[mf][nf][3],
                                     al[mf][0], al[mf][1], al[mf][2], al[mf][3], bh0, bh1);
                        }
                    }
                }

                // ---- scale + causal mask ----
                const bool needmask = (n0 + 63) > qwb;
#pragma unroll
                for (int mf = 0; mf < 2; mf++)
#pragma unroll
                    for (int nf = 0; nf < 8; nf++)
#pragma unroll
                        for (int r = 0; r < 4; r++) {
                            float s = S[mf][nf][r] * 0.125f;
                            if (needmask) {
                                int key = n0 + nf * 8 + tig * 2 + (r & 1);
                                int qv  = qwb + mf * 16 + gid + ((r >> 1) ? 8 : 0);
                                if (key > qv) s = -1e30f;
                            }
                            S[mf][nf][r] = s;
                        }

                // ---- online softmax ----
                float mt[4] = {-1e30f, -1e30f, -1e30f, -1e30f};
#pragma unroll
                for (int mf = 0; mf < 2; mf++)
#pragma unroll
                    for (int nf = 0; nf < 8; nf++)
#pragma unroll
                        for (int r = 0; r < 4; r++) {
                            int rid = mf * 2 + (r >> 1);
                            mt[rid] = fmaxf(mt[rid], S[mf][nf][r]);
                        }
#pragma unroll
                for (int rid = 0; rid < 4; rid++) {
                    mt[rid] = fmaxf(mt[rid], __shfl_xor_sync(0xffffffffu, mt[rid], 1));
                    mt[rid] = fmaxf(mt[rid], __shfl_xor_sync(0xffffffffu, mt[rid], 2));
                }
                float corr[4];
#pragma unroll
                for (int rid = 0; rid < 4; rid++) {
                    float nm = fmaxf(mrow[rid], mt[rid]);
                    corr[rid] = __expf(mrow[rid] - nm);
                    mrow[rid] = nm;
                }
                float rs[4] = {0.f, 0.f, 0.f, 0.f};
#pragma unroll
                for (int mf = 0; mf < 2; mf++)
#pragma unroll
                    for (int nf = 0; nf < 8; nf++)
#pragma unroll
                        for (int r = 0; r < 4; r++) {
                            int rid = mf * 2 + (r >> 1);
                            float p = __expf(S[mf][nf][r] - mrow[rid]);
                            S[mf][nf][r] = p;
                            rs[rid] += p;
                        }
#pragma unroll
                for (int rid = 0; rid < 4; rid++) {
                    rs[rid] += __shfl_xor_sync(0xffffffffu, rs[rid], 1);
                    rs[rid] += __shfl_xor_sync(0xffffffffu, rs[rid], 2);
                    lrow[rid] = lrow[rid] * corr[rid] + rs[rid];
                }
                // rescale O
#pragma unroll
                for (int mf = 0; mf < 2; mf++)
#pragma unroll
                    for (int nf = 0; nf < 8; nf++)
#pragma unroll
                        for (int r = 0; r < 4; r++)
                            O[mf][nf][r] *= corr[mf * 2 + (r >> 1)];

                // ---- pack P to bf16 hi/lo (in-register repack to A-frags) ----
                uint32_t ph[2][8][2], pl[2][8][2];
#pragma unroll
                for (int mf = 0; mf < 2; mf++)
#pragma unroll
                    for (int nf = 0; nf < 8; nf++)
#pragma unroll
                        for (int half = 0; half < 2; half++) {
                            float p0 = S[mf][nf][half * 2];
                            float p1 = S[mf][nf][half * 2 + 1];
                            __nv_bfloat16 h0 = __float2bfloat16_rn(p0);
                            __nv_bfloat16 h1 = __float2bfloat16_rn(p1);
                            __nv_bfloat162 hp(h0, h1);
                            __nv_bfloat162 lp(__float2bfloat16_rn(p0 - __bfloat162float(h0)),
                                              __float2bfloat16_rn(p1 - __bfloat162float(h1)));
                            ph[mf][nf][half] = *(uint32_t*)&hp;
                            pl[mf][nf][half] = *(uint32_t*)&lp;
                        }

                // ---- O += P V (3-way split) ----
#pragma unroll
                for (int ks = 0; ks < 4; ks++) {
                    const int kb = ks * 16 + tig * 2;
#pragma unroll
                    for (int nf = 0; nf < 8; nf++) {
                        int dr = nf * 8 + gid;
                        uint32_t bh0 = *(const uint32_t*)&Vth[dr][kb];
                        uint32_t bh1 = *(const uint32_t*)&Vth[dr][kb + 8];
                        uint32_t bl0 = *(const uint32_t*)&Vtl[dr][kb];
                        uint32_t bl1 = *(const uint32_t*)&Vtl[dr][kb + 8];
#pragma unroll
                        for (int mf = 0; mf < 2; mf++) {
                            mma16816(O[mf][nf][0], O[mf][nf][1], O[mf][nf][2], O[mf][nf][3],
                                     ph[mf][2*ks][0], ph[mf][2*ks][1],
                                     ph[mf][2*ks+1][0], ph[mf][2*ks+1][1], bh0, bh1);
                            mma16816(O[mf][nf][0], O[mf][nf][1], O[mf][nf][2], O[mf][nf][3],
                                     ph[mf][2*ks][0], ph[mf][2*ks][1],
                                     ph[mf][2*ks+1][0], ph[mf][2*ks+1][1], bl0, bl1);
                            mma16816(O[mf][nf][0], O[mf][nf][1], O[mf][nf][2], O[mf][nf][3],
                                     pl[mf][2*ks][0], pl[mf][2*ks][1],
                                     pl[mf][2*ks+1][0], pl[mf][2*ks+1][1], bh0, bh1);
                        }
                    }
                }
            }
            __syncthreads();
        }

        // ---- epilogue: normalize, split, store to activation buffers ----
        float linv[4];
#pragma unroll
        for (int rid = 0; rid < 4; rid++) linv[rid] = 1.0f / lrow[rid];
#pragma unroll
        for (int mf = 0; mf < 2; mf++) {
            int t0v = q0 + w * 32 + mf * 16 + gid;
#pragma unroll
            for (int nf = 0; nf < 8; nf++) {
                int d = nf * 8 + tig * 2;
#pragma unroll
                for (int half = 0; half < 2; half++) {
                    int tq = t0v + (half ? 8 : 0);
                    float o0 = O[mf][nf][half * 2]     * linv[mf * 2 + half];
                    float o1 = O[mf][nf][half * 2 + 1] * linv[mf * 2 + half];
                    __nv_bfloat16 h0 = __float2bfloat16_rn(o0);
                    __nv_bfloat16 h1 = __float2bfloat16_rn(o1);
                    __nv_bfloat162 hp(h0, h1);
                    __nv_bfloat162 lp(__float2bfloat16_rn(o0 - __bfloat162float(h0)),
                                      __float2bfloat16_rn(o1 - __bfloat162float(h1)));
                    size_t oi = ((size_t)(b * T + tq)) * D + h * DH + d;
                    *(uint32_t*)&Ohi[oi] = *(uint32_t*)&hp;
                    *(uint32_t*)&Olo[oi] = *(uint32_t*)&lp;
                }
            }
        }
        __syncthreads();
    }
}

// ---------------------------------------------------------------------------
// Launcher
// Inputs: 0 q, 1 kv, 2 mask, 3 q_pos, 4 kv_pos, 5 wq, 6 bq, 7 wk, 8 bk,
//         9 wv, 10 bv, 11 scale_q, 12 scale_k, 13 wo, 14 bo
// ---------------------------------------------------------------------------
extern "C" void kernel_launch(void* const* d_in, const int* in_sizes, int n_in,
                              void* d_out, int out_size)
{
    const float* q   = (const float*)d_in[0];
    const float* kv  = (const float*)d_in[1];
    const int*   qp  = (const int*)d_in[3];
    const int*   kp  = (const int*)d_in[4];
    const float* wq  = (const float*)d_in[5];
    const float* bq  = (const float*)d_in[6];
    const float* wk  = (const float*)d_in[7];
    const float* bk  = (const float*)d_in[8];
    const float* wv  = (const float*)d_in[9];
    const float* bv  = (const float*)d_in[10];
    const float* sq  = (const float*)d_in[11];
    const float* sk  = (const float*)d_in[12];
    const float* wo  = (const float*)d_in[13];
    const float* bo  = (const float*)d_in[14];
    float* out = (float*)d_out;

    float *Qh, *Kh, *Vh;
    __nv_bfloat16 *Ahi, *Alo, *Whi, *Wlo;
    __nv_bfloat16 *Qhi, *Qlo, *Khi, *Klo, *Vhi, *Vlo;
    cudaGetSymbolAddress((void**)&Qh, g_Qh);
    cudaGetSymbolAddress((void**)&Kh, g_Kh);
    cudaGetSymbolAddress((void**)&Vh, g_Vh);
    cudaGetSymbolAddress((void**)&Ahi, g_Ahi);
    cudaGetSymbolAddress((void**)&Alo, g_Alo);
    cudaGetSymbolAddress((void**)&Whi, g_Whi);
    cudaGetSymbolAddress((void**)&Wlo, g_Wlo);
    cudaGetSymbolAddress((void**)&Qhi, g_Qhi);
    cudaGetSymbolAddress((void**)&Qlo, g_Qlo);
    cudaGetSymbolAddress((void**)&Khi, g_Khi);
    cudaGetSymbolAddress((void**)&Klo, g_Klo);
    cudaGetSymbolAddress((void**)&Vhi, g_Vhi);
    cudaGetSymbolAddress((void**)&Vlo, g_Vlo);

    cudaFuncSetAttribute(attn_mma_kernel,
                         cudaFuncAttributeMaxDynamicSharedMemorySize, ATT_SMEM);

    const int nA4 = M_ROWS * D / 4;
    const int nW4 = D * D / 4;
    dim3 gGemm(GN / 128, M_ROWS / 128);

    // projections
    split_kernel<<<nA4 / 256, 256>>>(q, Ahi, Alo, nA4);
    split_kernel<<<nW4 / 256, 256>>>(wq, Whi, Wlo, nW4);
    gemm_mma_kernel<<<gGemm, 256>>>(Ahi, Alo, Whi, Wlo, bq, Qh);
    split_kernel<<<nA4 / 256, 256>>>(kv, Ahi, Alo, nA4);
    split_kernel<<<nW4 / 256, 256>>>(wk, Whi, Wlo, nW4);
    gemm_mma_kernel<<<gGemm, 256>>>(Ahi, Alo, Whi, Wlo, bk, Kh);
    split_kernel<<<nW4 / 256, 256>>>(wv, Whi, Wlo, nW4);
    gemm_mma_kernel<<<gGemm, 256>>>(Ahi, Alo, Whi, Wlo, bv, Vh);

    // norm + rope + head-major split
    int nRowHeads = M_ROWS * H;
    rmsropeb_kernel<<<nRowHeads / 8, 256>>>(Qh, sq, qp, Qhi, Qlo);
    rmsropeb_kernel<<<nRowHeads / 8, 256>>>(Kh, sk, kp, Khi, Klo);
    vconv_kernel<<<M_ROWS * D / 2 / 256, 256>>>(Vh, Vhi, Vlo);

    // attention (writes split activation buffers directly)
    dim3 gAttn(8, BH);
    attn_mma_kernel<<<gAttn, 128, ATT_SMEM>>>(Qhi, Qlo, Khi, Klo, Vhi, Vlo, Ahi, Alo);

    // output projection
    split_kernel<<<nW4 / 256, 256>>>(wo, Whi, Wlo, nW4);
    gemm_mma_kernel<<<gGemm, 256>>>(Ahi, Alo, Whi, Wlo, bo, out);
}

// round 6
// speedup vs baseline: 2.9138x; 1.0128x over previous
#include <cuda_runtime.h>
#include <cuda_bf16.h>
#include <math.h>
#include <cstdint>

// Problem constants (fixed by the dataset)
#define B   4
#define T   2048
#define D   512
#define H   8
#define DH  64
#define M_ROWS (B*T)        // 8192
#define BH  (B*H)           // 32

// ---------------------------------------------------------------------------
// Scratch (device globals; allocation inside kernel_launch is forbidden)
// ---------------------------------------------------------------------------
__device__ float g_Qh[M_ROWS * D];                 // fp32 projections (pre-norm)
__device__ float g_Kh[M_ROWS * D];
__device__ __nv_bfloat16 g_Ahi[M_ROWS * D];        // split activations (GEMM A)
__device__ __nv_bfloat16 g_Alo[M_ROWS * D];
__device__ __nv_bfloat16 g_Whi[D * D];             // transposed weight [n][k]
__device__ __nv_bfloat16 g_Wlo[D * D];
// head-major [b][h][t][64] bf16 hi/lo for attention
__device__ __nv_bfloat16 g_Qhi[BH * T * DH];
__device__ __nv_bfloat16 g_Qlo[BH * T * DH];
__device__ __nv_bfloat16 g_Khi[BH * T * DH];
__device__ __nv_bfloat16 g_Klo[BH * T * DH];
__device__ __nv_bfloat16 g_Vhi[BH * T * DH];
__device__ __nv_bfloat16 g_Vlo[BH * T * DH];

// ---------------------------------------------------------------------------
// Small PTX helpers
// ---------------------------------------------------------------------------
__device__ __forceinline__ uint32_t smem_u32(const void* p) {
    uint32_t a;
    asm("{ .reg .u64 t; cvta.to.shared.u64 t, %1; cvt.u32.u64 %0, t; }" : "=r"(a) : "l"(p));
    return a;
}
__device__ __forceinline__ void cp16(uint32_t dst, const void* src) {
    asm volatile("cp.async.cg.shared.global [%0], [%1], 16;" :: "r"(dst), "l"(src));
}
#define CP_COMMIT() asm volatile("cp.async.commit_group;")
#define CP_WAIT0()  asm volatile("cp.async.wait_group 0;")

__device__ __forceinline__ void ldsm4(uint32_t& r0, uint32_t& r1, uint32_t& r2,
                                      uint32_t& r3, uint32_t a) {
    asm volatile("ldmatrix.sync.aligned.m8n8.x4.shared.b16 {%0,%1,%2,%3}, [%4];"
                 : "=r"(r0), "=r"(r1), "=r"(r2), "=r"(r3) : "r"(a));
}

__device__ __forceinline__ void mma16816(
    float& c0, float& c1, float& c2, float& c3,
    uint32_t a0, uint32_t a1, uint32_t a2, uint32_t a3,
    uint32_t b0, uint32_t b1)
{
    asm volatile(
        "mma.sync.aligned.m16n8k16.row.col.f32.bf16.bf16.f32 "
        "{%0,%1,%2,%3}, {%4,%5,%6,%7}, {%8,%9}, {%0,%1,%2,%3};"
        : "+f"(c0), "+f"(c1), "+f"(c2), "+f"(c3)
        : "r"(a0), "r"(a1), "r"(a2), "r"(a3), "r"(b0), "r"(b1));
}

// ---------------------------------------------------------------------------
// Split fp32 -> bf16 hi + bf16 lo (residual), elementwise, vectorized x4.
// ---------------------------------------------------------------------------
__global__ __launch_bounds__(256) void split_kernel(
    const float* __restrict__ X, __nv_bfloat16* __restrict__ hi,
    __nv_bfloat16* __restrict__ lo, int n4)
{
    int i = blockIdx.x * 256 + threadIdx.x;
    if (i >= n4) return;
    float4 v = ((const float4*)X)[i];
    float a[4] = {v.x, v.y, v.z, v.w};
    __nv_bfloat162 h2[2], l2[2];
#pragma unroll
    for (int j = 0; j < 2; j++) {
        __nv_bfloat16 h0 = __float2bfloat16_rn(a[2*j]);
        __nv_bfloat16 h1 = __float2bfloat16_rn(a[2*j+1]);
        __nv_bfloat16 l0 = __float2bfloat16_rn(a[2*j]   - __bfloat162float(h0));
        __nv_bfloat16 l1 = __float2bfloat16_rn(a[2*j+1] - __bfloat162float(h1));
        h2[j] = __nv_bfloat162(h0, h1);
        l2[j] = __nv_bfloat162(l0, l1);
    }
    ((uint2*)hi)[i] = *(uint2*)h2;
    ((uint2*)lo)[i] = *(uint2*)l2;
}

// ---------------------------------------------------------------------------
// Weight transpose + split: W[k][n] fp32 -> Wt[n][k] bf16 hi/lo. 32x32 tiles.
// ---------------------------------------------------------------------------
__global__ __launch_bounds__(256) void wtrans_kernel(
    const float* __restrict__ W,
    __nv_bfloat16* __restrict__ hi, __nv_bfloat16* __restrict__ lo)
{
    __shared__ float tile[32][33];
    const int tx = threadIdx.x, ty = threadIdx.y;    // block (32, 8)
    const int n0 = blockIdx.x * 32, k0 = blockIdx.y * 32;
#pragma unroll
    for (int i = 0; i < 4; i++)
        tile[ty + i * 8][tx] = W[(size_t)(k0 + ty + i * 8) * D + n0 + tx];
    __syncthreads();
#pragma unroll
    for (int i = 0; i < 4; i++) {
        float v = tile[tx][ty + i * 8];
        __nv_bfloat16 h = __float2bfloat16_rn(v);
        size_t oi = (size_t)(n0 + ty + i * 8) * D + k0 + tx;
        hi[oi] = h;
        lo[oi] = __float2bfloat16_rn(v - __bfloat162float(h));
    }
}

// ---------------------------------------------------------------------------
// cp.async double-buffered HMMA GEMM (bf16 hi/lo split, fp32-accurate):
//   C = A@W^T + bias ; A[m][k] hi/lo, Wt[n][k] hi/lo. M=8192, N=K=512.
// CTA 128x128, BK=32, 8 warps of 64x32, ldmatrix fragment loads.
// VOUT=1: write head-major bf16 hi/lo (V path) instead of fp32 C.
// ---------------------------------------------------------------------------
#define GK 512
#define GN 512
// smem: per stage 4 buffers of 128x40 bf16 (10240 B): Ah, Al, Bh, Bl
#define GSTAGE 40960
#define GSMEM  (2 * GSTAGE)

template<int VOUT>
__global__ __launch_bounds__(256, 2) void gemm_cp_kernel(
    const __nv_bfloat16* __restrict__ Ahi, const __nv_bfloat16* __restrict__ Alo,
    const __nv_bfloat16* __restrict__ Bhi, const __nv_bfloat16* __restrict__ Blo,
    const float* __restrict__ bias, float* __restrict__ C,
    __nv_bfloat16* __restrict__ Vhi, __nv_bfloat16* __restrict__ Vlo)
{
    extern __shared__ char sm[];
    const uint32_t smb = smem_u32(sm);
    const int tid  = threadIdx.x;
    const int lane = tid & 31;
    const int wid  = tid >> 5;
    const int wm   = wid >> 2;
    const int wn   = wid & 3;
    const int m0   = blockIdx.y * 128;
    const int n0   = blockIdx.x * 128;
    const int gid  = lane >> 2;
    const int tig  = lane & 3;

    // ldmatrix per-lane offsets (pad-40 rows, bytes)
    const int lr = lane & 15;
    const int lc = (lane >> 4) * 8;
    uint32_t aoff[4], boff[2];
#pragma unroll
    for (int mf = 0; mf < 4; mf++)
        aoff[mf] = (uint32_t)(((wm * 64 + mf * 16 + lr) * 40 + lc) * 2);
#pragma unroll
    for (int p = 0; p < 2; p++)
        boff[p] = (uint32_t)(((wn * 32 + p * 16 + lr) * 40 + lc) * 2);

    float c[4][4][4];
#pragma unroll
    for (int mf = 0; mf < 4; mf++)
#pragma unroll
        for (int nf = 0; nf < 4; nf++)
#pragma unroll
            for (int r = 0; r < 4; r++) c[mf][nf][r] = 0.f;

    // row/quad this thread copies (2 iterations of 256)
    const int prow0 = tid >> 2;
    const int pq    = (tid & 3) * 8;

#define PREFETCH(stage, kc) do {                                              \
        uint32_t sbase = smb + (stage) * GSTAGE;                              \
        _Pragma("unroll")                                                     \
        for (int i_ = 0; i_ < 2; i_++) {                                      \
            int row_ = prow0 + i_ * 64;                                       \
            uint32_t so_ = (uint32_t)((row_ * 40 + pq) * 2);                  \
            size_t ga_ = (size_t)(m0 + row_) * GK + (kc) * 32 + pq;           \
            size_t gb_ = (size_t)(n0 + row_) * GK + (kc) * 32 + pq;           \
            cp16(sbase + so_,          Ahi + ga_);                            \
            cp16(sbase + 10240 + so_,  Alo + ga_);                            \
            cp16(sbase + 20480 + so_,  Bhi + gb_);                            \
            cp16(sbase + 30720 + so_,  Blo + gb_);                            \
        }                                                                     \
    } while (0)

    PREFETCH(0, 0);
    CP_COMMIT();

    for (int kc = 0; kc < 16; kc++) {
        const int st = kc & 1;
        CP_WAIT0();
        __syncthreads();
        if (kc + 1 < 16) { PREFETCH(st ^ 1, kc + 1); CP_COMMIT(); }

        const uint32_t bAh = smb + st * GSTAGE;
        const uint32_t bAl = bAh + 10240;
        const uint32_t bBh = bAh + 20480;
        const uint32_t bBl = bAh + 30720;

#pragma unroll
        for (int s = 0; s < 2; s++) {
            uint32_t ah[4][4], al[4][4];
#pragma unroll
            for (int mf = 0; mf < 4; mf++) {
                ldsm4(ah[mf][0], ah[mf][1], ah[mf][2], ah[mf][3], bAh + aoff[mf] + s * 32);
                ldsm4(al[mf][0], al[mf][1], al[mf][2], al[mf][3], bAl + aoff[mf] + s * 32);
            }
#pragma unroll
            for (int p = 0; p < 2; p++) {
                uint32_t h0, h1, h2, h3, l0, l1, l2, l3;
                ldsm4(h0, h1, h2, h3, bBh + boff[p] + s * 32);
                ldsm4(l0, l1, l2, l3, bBl + boff[p] + s * 32);
                const int nfa = p * 2, nfb = p * 2 + 1;
#pragma unroll
                for (int mf = 0; mf < 4; mf++) {
                    mma16816(c[mf][nfa][0], c[mf][nfa][1], c[mf][nfa][2], c[mf][nfa][3],
                             ah[mf][0], ah[mf][1], ah[mf][2], ah[mf][3], h0, h2);
                    mma16816(c[mf][nfa][0], c[mf][nfa][1], c[mf][nfa][2], c[mf][nfa][3],
                             al[mf][0], al[mf][1], al[mf][2], al[mf][3], h0, h2);
                    mma16816(c[mf][nfa][0], c[mf][nfa][1], c[mf][nfa][2], c[mf][nfa][3],
                             ah[mf][0], ah[mf][1], ah[mf][2], ah[mf][3], l0, l2);
                    mma16816(c[mf][nfb][0], c[mf][nfb][1], c[mf][nfb][2], c[mf][nfb][3],
                             ah[mf][0], ah[mf][1], ah[mf][2], ah[mf][3], h1, h3);
                    mma16816(c[mf][nfb][0], c[mf][nfb][1], c[mf][nfb][2], c[mf][nfb][3],
                             al[mf][0], al[mf][1], al[mf][2], al[mf][3], h1, h3);
                    mma16816(c[mf][nfb][0], c[mf][nfb][1], c[mf][nfb][2], c[mf][nfb][3],
                             ah[mf][0], ah[mf][1], ah[mf][2], ah[mf][3], l1, l3);
                }
            }
        }
        __syncthreads();
    }
#undef PREFETCH

    // ---- epilogue ----
#pragma unroll
    for (int mf = 0; mf < 4; mf++) {
        int m = m0 + wm * 64 + mf * 16 + gid;
#pragma unroll
        for (int nf = 0; nf < 4; nf++) {
            int n = n0 + wn * 32 + nf * 8 + tig * 2;
            float b0 = __ldg(&bias[n]), b1 = __ldg(&bias[n + 1]);
            float x0 = c[mf][nf][0] + b0, x1 = c[mf][nf][1] + b1;
            float x2 = c[mf][nf][2] + b0, x3 = c[mf][nf][3] + b1;
            if (VOUT) {
                // head-major bf16 hi/lo: m -> (b, t); n -> (h, d)
                int bb = m >> 11, tt = m & 2047;
                int hh = n >> 6,  dd = n & 63;
                size_t o0 = ((size_t)(bb * H + hh) * T + tt) * DH + dd;
                size_t o1 = o0 + 8 * DH;   // row m+8
                __nv_bfloat16 h0 = __float2bfloat16_rn(x0);
                __nv_bfloat16 h1 = __float2bfloat16_rn(x1);
                __nv_bfloat162 hp0(h0, h1);
                __nv_bfloat162 lp0(__float2bfloat16_rn(x0 - __bfloat162float(h0)),
                                   __float2bfloat16_rn(x1 - __bfloat162float(h1)));
                __nv_bfloat16 h2 = __float2bfloat16_rn(x2);
                __nv_bfloat16 h3 = __float2bfloat16_rn(x3);
                __nv_bfloat162 hp1(h2, h3);
                __nv_bfloat162 lp1(__float2bfloat16_rn(x2 - __bfloat162float(h2)),
                                   __float2bfloat16_rn(x3 - __bfloat162float(h3)));
                *(uint32_t*)&Vhi[o0] = *(uint32_t*)&hp0;
                *(uint32_t*)&Vlo[o0] = *(uint32_t*)&lp0;
                *(uint32_t*)&Vhi[o1] = *(uint32_t*)&hp1;
                *(uint32_t*)&Vlo[o1] = *(uint32_t*)&lp1;
            } else {
                *(float2*)&C[(size_t)m * GN + n]       = make_float2(x0, x1);
                *(float2*)&C[(size_t)(m + 8) * GN + n] = make_float2(x2, x3);
            }
        }
    }
}

// ---------------------------------------------------------------------------
// RMSNorm + RoPE, fp32 in -> head-major bf16 hi/lo out [b][h][t][64].
// ---------------------------------------------------------------------------
__global__ __launch_bounds__(256) void rmsropeb_kernel(
    const float* __restrict__ X, const float* __restrict__ scale,
    const int* __restrict__ pos,
    __nv_bfloat16* __restrict__ hi, __nv_bfloat16* __restrict__ lo)
{
    const int warp = threadIdx.x >> 5;
    const int lane = threadIdx.x & 31;
    const long long gw = (long long)blockIdx.x * 8 + warp;   // 0..B*T*H-1
    const int h = (int)(gw & (H - 1));
    const long long row = gw >> 3;                           // b*T + t
    const int b = (int)(row >> 11);
    const int t = (int)(row & 2047);

    const float* xp = X + row * D + h * DH;
    float x0 = xp[lane];
    float x1 = xp[lane + 32];

    float ss = x0 * x0 + x1 * x1;
#pragma unroll
    for (int o = 16; o; o >>= 1) ss += __shfl_xor_sync(0xffffffffu, ss, o);

    float r = rsqrtf(ss * (1.0f / 64.0f) + 1e-6f);
    float y0 = x0 * r * (1.0f + scale[lane]);
    float y1 = x1 * r * (1.0f + scale[lane + 32]);

    double ts  = exp2((double)lane * (1.0 / 32.0) * 13.28771237954945);  // log2(10000)
    double ang = (double)pos[row] / ts;
    float sn = (float)sin(ang);
    float cs = (float)cos(ang);

    float v0 = y0 * cs - y1 * sn;
    float v1 = y1 * cs + y0 * sn;

    size_t o0 = ((size_t)(b * H + h) * T + t) * DH + lane;
    __nv_bfloat16 h0 = __float2bfloat16_rn(v0);
    __nv_bfloat16 h1 = __float2bfloat16_rn(v1);
    hi[o0]      = h0;
    hi[o0 + 32] = h1;
    lo[o0]      = __float2bfloat16_rn(v0 - __bfloat162float(h0));
    lo[o0 + 32] = __float2bfloat16_rn(v1 - __bfloat162float(h1));
}

// ---------------------------------------------------------------------------
// HMMA causal flash attention (as round 4).
// ---------------------------------------------------------------------------
#define ATT_SQH 0
#define ATT_SQL 18432
#define ATT_SKH 36864
#define ATT_SKL 46080
#define ATT_SVH 55296
#define ATT_SVL 64512
#define ATT_SMEM 73728

__global__ __launch_bounds__(128) void attn_mma_kernel(
    const __nv_bfloat16* __restrict__ Qhi, const __nv_bfloat16* __restrict__ Qlo,
    const __nv_bfloat16* __restrict__ Khi, const __nv_bfloat16* __restrict__ Klo,
    const __nv_bfloat16* __restrict__ Vhi, const __nv_bfloat16* __restrict__ Vlo,
    __nv_bfloat16* __restrict__ Ohi, __nv_bfloat16* __restrict__ Olo)
{
    extern __shared__ char sm[];
    __nv_bfloat16 (*Qsh)[72] = (__nv_bfloat16(*)[72])(sm + ATT_SQH);
    __nv_bfloat16 (*Qsl)[72] = (__nv_bfloat16(*)[72])(sm + ATT_SQL);
    __nv_bfloat16 (*Ksh)[72] = (__nv_bfloat16(*)[72])(sm + ATT_SKH);  // [key][d]
    __nv_bfloat16 (*Ksl)[72] = (__nv_bfloat16(*)[72])(sm + ATT_SKL);
    __nv_bfloat16 (*Vth)[72] = (__nv_bfloat16(*)[72])(sm + ATT_SVH);  // [d][key]
    __nv_bfloat16 (*Vtl)[72] = (__nv_bfloat16(*)[72])(sm + ATT_SVL);

    const int tid  = threadIdx.x;
    const int lane = tid & 31;
    const int w    = tid >> 5;
    const int gid  = lane >> 2;
    const int tig  = lane & 3;
    const int bh   = blockIdx.y;
    const int b    = bh >> 3;
    const int h    = bh & 7;
    const size_t headbase = (size_t)bh * T * DH;

    for (int pass = 0; pass < 2; pass++) {
        const int qt = pass ? (15 - (int)blockIdx.x) : (int)blockIdx.x;
        const int q0 = qt * 128;

#pragma unroll
        for (int i = 0; i < 8; i++) {
            int idx = tid + i * 128;
            int row = idx >> 3;
            int c8  = (idx & 7) * 8;
            size_t g = headbase + (size_t)(q0 + row) * DH + c8;
            *(uint4*)&Qsh[row][c8] = *(const uint4*)&Qhi[g];
            *(uint4*)&Qsl[row][c8] = *(const uint4*)&Qlo[g];
        }
        __syncthreads();

        float O[2][8][4];
#pragma unroll
        for (int mf = 0; mf < 2; mf++)
#pragma unroll
            for (int nf = 0; nf < 8; nf++)
#pragma unroll
                for (int r = 0; r < 4; r++) O[mf][nf][r] = 0.f;
        float mrow[4] = {-1e30f, -1e30f, -1e30f, -1e30f};
        float lrow[4] = {0.f, 0.f, 0.f, 0.f};

        const int qwb = q0 + w * 32;
        const int nkt = (qt + 1) * 2;

        for (int kt = 0; kt < nkt; kt++) {
            const int n0 = kt * 64;
#pragma unroll
            for (int i = 0; i < 4; i++) {
                int idx = tid + i * 128;
                int key = idx >> 3;
                int c8  = (idx & 7) * 8;
                size_t g = headbase + (size_t)(n0 + key) * DH + c8;
                *(uint4*)&Ksh[key][c8] = *(const uint4*)&Khi[g];
                *(uint4*)&Ksl[key][c8] = *(const uint4*)&Klo[g];
                uint4 vh = *(const uint4*)&Vhi[g];
                uint4 vl = *(const uint4*)&Vlo[g];
                __nv_bfloat16 th[8], tl[8];
                *(uint4*)th = vh; *(uint4*)tl = vl;
#pragma unroll
                for (int j = 0; j < 8; j++) {
                    Vth[c8 + j][key] = th[j];
                    Vtl[c8 + j][key] = tl[j];
                }
            }
            __syncthreads();

            const bool active = (n0 <= qwb + 31);
            if (active) {
                float S[2][8][4];
#pragma unroll
                for (int mf = 0; mf < 2; mf++)
#pragma unroll
                    for (int nf = 0; nf < 8; nf++)
#pragma unroll
                        for (int r = 0; r < 4; r++) S[mf][nf][r] = 0.f;

#pragma unroll
                for (int ks = 0; ks < 4; ks++) {
                    const int kb = ks * 16 + tig * 2;
                    uint32_t ah[2][4], al[2][4];
#pragma unroll
                    for (int mf = 0; mf < 2; mf++) {
                        int qr = w * 32 + mf * 16 + gid;
                        ah[mf][0] = *(const uint32_t*)&Qsh[qr    ][kb    ];
                        ah[mf][1] = *(const uint32_t*)&Qsh[qr + 8][kb    ];
                        ah[mf][2] = *(const uint32_t*)&Qsh[qr    ][kb + 8];
                        ah[mf][3] = *(const uint32_t*)&Qsh[qr + 8][kb + 8];
                        al[mf][0] = *(const uint32_t*)&Qsl[qr    ][kb    ];
                        al[mf][1] = *(const uint32_t*)&Qsl[qr + 8][kb    ];
                        al[mf][2] = *(const uint32_t*)&Qsl[qr    ][kb + 8];
                        al[mf][3] = *(const uint32_t*)&Qsl[qr + 8][kb + 8];
                    }
#pragma unroll
                    for (int nf = 0; nf < 8; nf++) {
                        int kr = nf * 8 + gid;
                        uint32_t bh0 = *(const uint32_t*)&Ksh[kr][kb];
                        uint32_t bh1 = *(const uint32_t*)&Ksh[kr][kb + 8];
                        uint32_t bl0 = *(const uint32_t*)&Ksl[kr][kb];
                        uint32_t bl1 = *(const uint32_t*)&Ksl[kr][kb + 8];
#pragma unroll
                        for (int mf = 0; mf < 2; mf++) {
                            mma16816(S[mf][nf][0], S[mf][nf][1], S[mf][nf][2], S[mf][nf][3],
                                     ah[mf][0], ah[mf][1], ah[mf][2], ah[mf][3], bh0, bh1);
                            mma16816(S[mf][nf][0], S[mf][nf][1], S[mf][nf][2], S[mf][nf][3],
                                     ah[mf][0], ah[mf][1], ah[mf][2], ah[mf][3], bl0, bl1);
                            mma16816(S[mf][nf][0], S[mf][nf][1], S[mf][nf][2], S[mf][nf][3],
                                     al[mf][0], al[mf][1], al[mf][2], al[mf][3], bh0, bh1);
                        }
                    }
                }

                const bool needmask = (n0 + 63) > qwb;
#pragma unroll
                for (int mf = 0; mf < 2; mf++)
#pragma unroll
                    for (int nf = 0; nf < 8; nf++)
#pragma unroll
                        for (int r = 0; r < 4; r++) {
                            float s = S[mf][nf][r] * 0.125f;
                            if (needmask) {
                                int key = n0 + nf * 8 + tig * 2 + (r & 1);
                                int qv  = qwb + mf * 16 + gid + ((r >> 1) ? 8 : 0);
                                if (key > qv) s = -1e30f;
                            }
                            S[mf][nf][r] = s;
                        }

                float mt[4] = {-1e30f, -1e30f, -1e30f, -1e30f};
#pragma unroll
                for (int mf = 0; mf < 2; mf++)
#pragma unroll
                    for (int nf = 0; nf < 8; nf++)
#pragma unroll
                        for (int r = 0; r < 4; r++) {
                            int rid = mf * 2 + (r >> 1);
                            mt[rid] = fmaxf(mt[rid], S[mf][nf][r]);
                        }
#pragma unroll
                for (int rid = 0; rid < 4; rid++) {
                    mt[rid] = fmaxf(mt[rid], __shfl_xor_sync(0xffffffffu, mt[rid], 1));
                    mt[rid] = fmaxf(mt[rid], __shfl_xor_sync(0xffffffffu, mt[rid], 2));
                }
                float corr[4];
#pragma unroll
                for (int rid = 0; rid < 4; rid++) {
                    float nm = fmaxf(mrow[rid], mt[rid]);
                    corr[rid] = __expf(mrow[rid] - nm);
                    mrow[rid] = nm;
                }
                float rs[4] = {0.f, 0.f, 0.f, 0.f};
#pragma unroll
                for (int mf = 0; mf < 2; mf++)
#pragma unroll
                    for (int nf = 0; nf < 8; nf++)
#pragma unroll
                        for (int r = 0; r < 4; r++) {
                            int rid = mf * 2 + (r >> 1);
                            float p = __expf(S[mf][nf][r] - mrow[rid]);
                            S[mf][nf][r] = p;
                            rs[rid] += p;
                        }
#pragma unroll
                for (int rid = 0; rid < 4; rid++) {
                    rs[rid] += __shfl_xor_sync(0xffffffffu, rs[rid], 1);
                    rs[rid] += __shfl_xor_sync(0xffffffffu, rs[rid], 2);
                    lrow[rid] = lrow[rid] * corr[rid] + rs[rid];
                }
#pragma unroll
                for (int mf = 0; mf < 2; mf++)
#pragma unroll
                    for (int nf = 0; nf < 8; nf++)
#pragma unroll
                        for (int r = 0; r < 4; r++)
                            O[mf][nf][r] *= corr[mf * 2 + (r >> 1)];

                uint32_t ph[2][8][2], pl[2][8][2];
#pragma unroll
                for (int mf = 0; mf < 2; mf++)
#pragma unroll
                    for (int nf = 0; nf < 8; nf++)
#pragma unroll
                        for (int half = 0; half < 2; half++) {
                            float p0 = S[mf][nf][half * 2];
                            float p1 = S[mf][nf][half * 2 + 1];
                            __nv_bfloat16 h0 = __float2bfloat16_rn(p0);
                            __nv_bfloat16 h1 = __float2bfloat16_rn(p1);
                            __nv_bfloat162 hp(h0, h1);
                            __nv_bfloat162 lp(__float2bfloat16_rn(p0 - __bfloat162float(h0)),
                                              __float2bfloat16_rn(p1 - __bfloat162float(h1)));
                            ph[mf][nf][half] = *(uint32_t*)&hp;
                            pl[mf][nf][half] = *(uint32_t*)&lp;
                        }

#pragma unroll
                for (int ks = 0; ks < 4; ks++) {
                    const int kb = ks * 16 + tig * 2;
#pragma unroll
                    for (int nf = 0; nf < 8; nf++) {
                        int dr = nf * 8 + gid;
                        uint32_t bh0 = *(const uint32_t*)&Vth[dr][kb];
                        uint32_t bh1 = *(const uint32_t*)&Vth[dr][kb + 8];
                        uint32_t bl0 = *(const uint32_t*)&Vtl[dr][kb];
                        uint32_t bl1 = *(const uint32_t*)&Vtl[dr][kb + 8];
#pragma unroll
                        for (int mf = 0; mf < 2; mf++) {
                            mma16816(O[mf][nf][0], O[mf][nf][1], O[mf][nf][2], O[mf][nf][3],
                                     ph[mf][2*ks][0], ph[mf][2*ks][1],
                                     ph[mf][2*ks+1][0], ph[mf][2*ks+1][1], bh0, bh1);
                            mma16816(O[mf][nf][0], O[mf][nf][1], O[mf][nf][2], O[mf][nf][3],
                                     ph[mf][2*ks][0], ph[mf][2*ks][1],
                                     ph[mf][2*ks+1][0], ph[mf][2*ks+1][1], bl0, bl1);
                            mma16816(O[mf][nf][0], O[mf][nf][1], O[mf][nf][2], O[mf][nf][3],
                                     pl[mf][2*ks][0], pl[mf][2*ks][1],
                                     pl[mf][2*ks+1][0], pl[mf][2*ks+1][1], bh0, bh1);
                        }
                    }
                }
            }
            __syncthreads();
        }

        float linv[4];
#pragma unroll
        for (int rid = 0; rid < 4; rid++) linv[rid] = 1.0f / lrow[rid];
#pragma unroll
        for (int mf = 0; mf < 2; mf++) {
            int t0v = q0 + w * 32 + mf * 16 + gid;
#pragma unroll
            for (int nf = 0; nf < 8; nf++) {
                int d = nf * 8 + tig * 2;
#pragma unroll
                for (int half = 0; half < 2; half++) {
                    int tq = t0v + (half ? 8 : 0);
                    float o0 = O[mf][nf][half * 2]     * linv[mf * 2 + half];
                    float o1 = O[mf][nf][half * 2 + 1] * linv[mf * 2 + half];
                    __nv_bfloat16 h0 = __float2bfloat16_rn(o0);
                    __nv_bfloat16 h1 = __float2bfloat16_rn(o1);
                    __nv_bfloat162 hp(h0, h1);
                    __nv_bfloat162 lp(__float2bfloat16_rn(o0 - __bfloat162float(h0)),
                                      __float2bfloat16_rn(o1 - __bfloat162float(h1)));
                    size_t oi = ((size_t)(b * T + tq)) * D + h * DH + d;
                    *(uint32_t*)&Ohi[oi] = *(uint32_t*)&hp;
                    *(uint32_t*)&Olo[oi] = *(uint32_t*)&lp;
                }
            }
        }
        __syncthreads();
    }
}

// ---------------------------------------------------------------------------
// Launcher
// Inputs: 0 q, 1 kv, 2 mask, 3 q_pos, 4 kv_pos, 5 wq, 6 bq, 7 wk, 8 bk,
//         9 wv, 10 bv, 11 scale_q, 12 scale_k, 13 wo, 14 bo
// ---------------------------------------------------------------------------
extern "C" void kernel_launch(void* const* d_in, const int* in_sizes, int n_in,
                              void* d_out, int out_size)
{
    const float* q   = (const float*)d_in[0];
    const float* kv  = (const float*)d_in[1];
    const int*   qp  = (const int*)d_in[3];
    const int*   kp  = (const int*)d_in[4];
    const float* wq  = (const float*)d_in[5];
    const float* bq  = (const float*)d_in[6];
    const float* wk  = (const float*)d_in[7];
    const float* bk  = (const float*)d_in[8];
    const float* wv  = (const float*)d_in[9];
    const float* bv  = (const float*)d_in[10];
    const float* sq  = (const float*)d_in[11];
    const float* sk  = (const float*)d_in[12];
    const float* wo  = (const float*)d_in[13];
    const float* bo  = (const float*)d_in[14];
    float* out = (float*)d_out;

    float *Qh, *Kh;
    __nv_bfloat16 *Ahi, *Alo, *Whi, *Wlo;
    __nv_bfloat16 *Qhi, *Qlo, *Khi, *Klo, *Vhi, *Vlo;
    cudaGetSymbolAddress((void**)&Qh, g_Qh);
    cudaGetSymbolAddress((void**)&Kh, g_Kh);
    cudaGetSymbolAddress((void**)&Ahi, g_Ahi);
    cudaGetSymbolAddress((void**)&Alo, g_Alo);
    cudaGetSymbolAddress((void**)&Whi, g_Whi);
    cudaGetSymbolAddress((void**)&Wlo, g_Wlo);
    cudaGetSymbolAddress((void**)&Qhi, g_Qhi);
    cudaGetSymbolAddress((void**)&Qlo, g_Qlo);
    cudaGetSymbolAddress((void**)&Khi, g_Khi);
    cudaGetSymbolAddress((void**)&Klo, g_Klo);
    cudaGetSymbolAddress((void**)&Vhi, g_Vhi);
    cudaGetSymbolAddress((void**)&Vlo, g_Vlo);

    cudaFuncSetAttribute(attn_mma_kernel,
                         cudaFuncAttributeMaxDynamicSharedMemorySize, ATT_SMEM);
    cudaFuncSetAttribute(gemm_cp_kernel<0>,
                         cudaFuncAttributeMaxDynamicSharedMemorySize, GSMEM);
    cudaFuncSetAttribute(gemm_cp_kernel<1>,
                         cudaFuncAttributeMaxDynamicSharedMemorySize, GSMEM);

    const int nA4 = M_ROWS * D / 4;
    dim3 gGemm(GN / 128, M_ROWS / 128);     // (4, 64)
    dim3 gTr(D / 32, D / 32);               // (16, 16)
    dim3 bTr(32, 8);

    // Q projection
    split_kernel<<<nA4 / 256, 256>>>(q, Ahi, Alo, nA4);
    wtrans_kernel<<<gTr, bTr>>>(wq, Whi, Wlo);
    gemm_cp_kernel<0><<<gGemm, 256, GSMEM>>>(Ahi, Alo, Whi, Wlo, bq, Qh, nullptr, nullptr);
    // K projection
    split_kernel<<<nA4 / 256, 256>>>(kv, Ahi, Alo, nA4);
    wtrans_kernel<<<gTr, bTr>>>(wk, Whi, Wlo);
    gemm_cp_kernel<0><<<gGemm, 256, GSMEM>>>(Ahi, Alo, Whi, Wlo, bk, Kh, nullptr, nullptr);
    // V projection -> head-major bf16 hi/lo directly
    wtrans_kernel<<<gTr, bTr>>>(wv, Whi, Wlo);
    gemm_cp_kernel<1><<<gGemm, 256, GSMEM>>>(Ahi, Alo, Whi, Wlo, bv, nullptr, Vhi, Vlo);

    // norm + rope + head-major split
    int nRowHeads = M_ROWS * H;
    rmsropeb_kernel<<<nRowHeads / 8, 256>>>(Qh, sq, qp, Qhi, Qlo);
    rmsropeb_kernel<<<nRowHeads / 8, 256>>>(Kh, sk, kp, Khi, Klo);

    // attention (writes split activation buffers directly)
    dim3 gAttn(8, BH);
    attn_mma_kernel<<<gAttn, 128, ATT_SMEM>>>(Qhi, Qlo, Khi, Klo, Vhi, Vlo, Ahi, Alo);

    // output projection
    wtrans_kernel<<<gTr, bTr>>>(wo, Whi, Wlo);
    gemm_cp_kernel<0><<<gGemm, 256, GSMEM>>>(Ahi, Alo, Whi, Wlo, bo, out, nullptr, nullptr);
}

// round 7
// speedup vs baseline: 4.1787x; 1.4341x over previous
#include <cuda_runtime.h>
#include <cuda_fp16.h>
#include <math.h>
#include <cstdint>

// Problem constants (fixed by the dataset)
#define B   4
#define T   2048
#define D   512
#define H   8
#define DH  64
#define M_ROWS (B*T)        // 8192
#define BH  (B*H)           // 32

// ---------------------------------------------------------------------------
// Scratch (device globals; allocation inside kernel_launch is forbidden)
// ---------------------------------------------------------------------------
__device__ float g_Qh[M_ROWS * D];        // fp32 projections (pre-norm)
__device__ float g_Kh[M_ROWS * D];
__device__ __half g_Ahi[M_ROWS * D];      // activation hi (GEMM A, fp16)
__device__ __half g_Whi[D * D];           // transposed weight [n][k] hi/lo
__device__ __half g_Wlo[D * D];
// head-major [b][h][t][64] fp16 for attention
__device__ __half g_Qhi[BH * T * DH];
__device__ __half g_Khi[BH * T * DH];
__device__ __half g_Klo[BH * T * DH];
__device__ __half g_Vhi[BH * T * DH];

// ---------------------------------------------------------------------------
// Small PTX helpers
// ---------------------------------------------------------------------------
__device__ __forceinline__ uint32_t smem_u32(const void* p) {
    uint32_t a;
    asm("{ .reg .u64 t; cvta.to.shared.u64 t, %1; cvt.u32.u64 %0, t; }" : "=r"(a) : "l"(p));
    return a;
}
__device__ __forceinline__ void cp16(uint32_t dst, const void* src) {
    asm volatile("cp.async.cg.shared.global [%0], [%1], 16;" :: "r"(dst), "l"(src));
}
#define CP_COMMIT() asm volatile("cp.async.commit_group;")
#define CP_WAIT0()  asm volatile("cp.async.wait_group 0;")

__device__ __forceinline__ void ldsm4(uint32_t& r0, uint32_t& r1, uint32_t& r2,
                                      uint32_t& r3, uint32_t a) {
    asm volatile("ldmatrix.sync.aligned.m8n8.x4.shared.b16 {%0,%1,%2,%3}, [%4];"
                 : "=r"(r0), "=r"(r1), "=r"(r2), "=r"(r3) : "r"(a));
}

// m16n8k16 fp16 MMA, fp32 accumulate
__device__ __forceinline__ void mma16816(
    float& c0, float& c1, float& c2, float& c3,
    uint32_t a0, uint32_t a1, uint32_t a2, uint32_t a3,
    uint32_t b0, uint32_t b1)
{
    asm volatile(
        "mma.sync.aligned.m16n8k16.row.col.f32.f16.f16.f32 "
        "{%0,%1,%2,%3}, {%4,%5,%6,%7}, {%8,%9}, {%0,%1,%2,%3};"
        : "+f"(c0), "+f"(c1), "+f"(c2), "+f"(c3)
        : "r"(a0), "r"(a1), "r"(a2), "r"(a3), "r"(b0), "r"(b1));
}

// ---------------------------------------------------------------------------
// fp32 -> fp16 (round-to-nearest), hi only, vectorized x4.
// ---------------------------------------------------------------------------
__global__ __launch_bounds__(256) void splith_kernel(
    const float* __restrict__ X, __half* __restrict__ hi, int n4)
{
    int i = blockIdx.x * 256 + threadIdx.x;
    if (i >= n4) return;
    float4 v = ((const float4*)X)[i];
    __half2 h2[2];
    h2[0] = __floats2half2_rn(v.x, v.y);
    h2[1] = __floats2half2_rn(v.z, v.w);
    ((uint2*)hi)[i] = *(uint2*)h2;
}

// ---------------------------------------------------------------------------
// Weight transpose + split: W[k][n] fp32 -> Wt[n][k] fp16 hi/lo. 32x32 tiles.
// ---------------------------------------------------------------------------
__global__ __launch_bounds__(256) void wtrans_kernel(
    const float* __restrict__ W,
    __half* __restrict__ hi, __half* __restrict__ lo)
{
    __shared__ float tile[32][33];
    const int tx = threadIdx.x, ty = threadIdx.y;    // block (32, 8)
    const int n0 = blockIdx.x * 32, k0 = blockIdx.y * 32;
#pragma unroll
    for (int i = 0; i < 4; i++)
        tile[ty + i * 8][tx] = W[(size_t)(k0 + ty + i * 8) * D + n0 + tx];
    __syncthreads();
#pragma unroll
    for (int i = 0; i < 4; i++) {
        float v = tile[tx][ty + i * 8];
        __half h = __float2half_rn(v);
        size_t oi = (size_t)(n0 + ty + i * 8) * D + k0 + tx;
        hi[oi] = h;
        lo[oi] = __float2half_rn(v - __half2float(h));
    }
}

// ---------------------------------------------------------------------------
// cp.async double-buffered HMMA GEMM (fp16, W split hi/lo):
//   C = Ahi@(Whi+Wlo)^T + bias ; A[m][k] hi, Wt[n][k] hi/lo. M=8192, N=K=512.
// CTA 128x128, BK=32, 8 warps of 64x32, ldmatrix fragment loads.
// VOUT=1: write head-major fp16 (V path) instead of fp32 C.
// ---------------------------------------------------------------------------
#define GK 512
#define GN 512
// per stage 3 buffers of 128x40 half (10240 B): Ah, Bh, Bl
#define GSTAGE 30720
#define GSMEM  (2 * GSTAGE)

template<int VOUT>
__global__ __launch_bounds__(256, 2) void gemm_cp_kernel(
    const __half* __restrict__ Ahi,
    const __half* __restrict__ Bhi, const __half* __restrict__ Blo,
    const float* __restrict__ bias, float* __restrict__ C,
    __half* __restrict__ Vhi)
{
    extern __shared__ char sm[];
    const uint32_t smb = smem_u32(sm);
    const int tid  = threadIdx.x;
    const int lane = tid & 31;
    const int wid  = tid >> 5;
    const int wm   = wid >> 2;
    const int wn   = wid & 3;
    const int m0   = blockIdx.y * 128;
    const int n0   = blockIdx.x * 128;
    const int gid  = lane >> 2;
    const int tig  = lane & 3;

    // ldmatrix per-lane offsets (pad-40 rows, bytes)
    const int lr = lane & 15;
    const int lc = (lane >> 4) * 8;
    uint32_t aoff[4], boff[2];
#pragma unroll
    for (int mf = 0; mf < 4; mf++)
        aoff[mf] = (uint32_t)(((wm * 64 + mf * 16 + lr) * 40 + lc) * 2);
#pragma unroll
    for (int p = 0; p < 2; p++)
        boff[p] = (uint32_t)(((wn * 32 + p * 16 + lr) * 40 + lc) * 2);

    float c[4][4][4];
#pragma unroll
    for (int mf = 0; mf < 4; mf++)
#pragma unroll
        for (int nf = 0; nf < 4; nf++)
#pragma unroll
            for (int r = 0; r < 4; r++) c[mf][nf][r] = 0.f;

    const int prow0 = tid >> 2;
    const int pq    = (tid & 3) * 8;

#define PREFETCH(stage, kc) do {                                              \
        uint32_t sbase = smb + (stage) * GSTAGE;                              \
        _Pragma("unroll")                                                     \
        for (int i_ = 0; i_ < 2; i_++) {                                      \
            int row_ = prow0 + i_ * 64;                                       \
            uint32_t so_ = (uint32_t)((row_ * 40 + pq) * 2);                  \
            size_t ga_ = (size_t)(m0 + row_) * GK + (kc) * 32 + pq;           \
            size_t gb_ = (size_t)(n0 + row_) * GK + (kc) * 32 + pq;           \
            cp16(sbase + so_,          Ahi + ga_);                            \
            cp16(sbase + 10240 + so_,  Bhi + gb_);                            \
            cp16(sbase + 20480 + so_,  Blo + gb_);                            \
        }                                                                     \
    } while (0)

    PREFETCH(0, 0);
    CP_COMMIT();

    for (int kc = 0; kc < 16; kc++) {
        const int st = kc & 1;
        CP_WAIT0();
        __syncthreads();
        if (kc + 1 < 16) { PREFETCH(st ^ 1, kc + 1); CP_COMMIT(); }

        const uint32_t bAh = smb + st * GSTAGE;
        const uint32_t bBh = bAh + 10240;
        const uint32_t bBl = bAh + 20480;

#pragma unroll
        for (int s = 0; s < 2; s++) {
            uint32_t a[4][4];
#pragma unroll
            for (int mf = 0; mf < 4; mf++)
                ldsm4(a[mf][0], a[mf][1], a[mf][2], a[mf][3], bAh + aoff[mf] + s * 32);
#pragma unroll
            for (int p = 0; p < 2; p++) {
                uint32_t h0, h1, h2, h3, l0, l1, l2, l3;
                ldsm4(h0, h1, h2, h3, bBh + boff[p] + s * 32);
                ldsm4(l0, l1, l2, l3, bBl + boff[p] + s * 32);
                const int nfa = p * 2, nfb = p * 2 + 1;
#pragma unroll
                for (int mf = 0; mf < 4; mf++) {
                    mma16816(c[mf][nfa][0], c[mf][nfa][1], c[mf][nfa][2], c[mf][nfa][3],
                             a[mf][0], a[mf][1], a[mf][2], a[mf][3], h0, h2);
                    mma16816(c[mf][nfa][0], c[mf][nfa][1], c[mf][nfa][2], c[mf][nfa][3],
                             a[mf][0], a[mf][1], a[mf][2], a[mf][3], l0, l2);
                    mma16816(c[mf][nfb][0], c[mf][nfb][1], c[mf][nfb][2], c[mf][nfb][3],
                             a[mf][0], a[mf][1], a[mf][2], a[mf][3], h1, h3);
                    mma16816(c[mf][nfb][0], c[mf][nfb][1], c[mf][nfb][2], c[mf][nfb][3],
                             a[mf][0], a[mf][1], a[mf][2], a[mf][3], l1, l3);
                }
            }
        }
        __syncthreads();
    }
#undef PREFETCH

    // ---- epilogue ----
#pragma unroll
    for (int mf = 0; mf < 4; mf++) {
        int m = m0 + wm * 64 + mf * 16 + gid;
#pragma unroll
        for (int nf = 0; nf < 4; nf++) {
            int n = n0 + wn * 32 + nf * 8 + tig * 2;
            float b0 = __ldg(&bias[n]), b1 = __ldg(&bias[n + 1]);
            float x0 = c[mf][nf][0] + b0, x1 = c[mf][nf][1] + b1;
            float x2 = c[mf][nf][2] + b0, x3 = c[mf][nf][3] + b1;
            if (VOUT) {
                // head-major fp16: m -> (b, t); n -> (h, d)
                int bb = m >> 11, tt = m & 2047;
                int hh = n >> 6,  dd = n & 63;
                size_t o0 = ((size_t)(bb * H + hh) * T + tt) * DH + dd;
                size_t o1 = o0 + 8 * DH;   // row m+8
                __half2 hp0 = __floats2half2_rn(x0, x1);
                __half2 hp1 = __floats2half2_rn(x2, x3);
                *(uint32_t*)&Vhi[o0] = *(uint32_t*)&hp0;
                *(uint32_t*)&Vhi[o1] = *(uint32_t*)&hp1;
            } else {
                *(float2*)&C[(size_t)m * GN + n]       = make_float2(x0, x1);
                *(float2*)&C[(size_t)(m + 8) * GN + n] = make_float2(x2, x3);
            }
        }
    }
}

// ---------------------------------------------------------------------------
// RMSNorm + RoPE, fp32 in -> head-major fp16 out [b][h][t][64].
// WLO=1 also writes the fp16 residual (K path needs exact K = hi+lo).
// ---------------------------------------------------------------------------
template<int WLO>
__global__ __launch_bounds__(256) void rmsropeb_kernel(
    const float* __restrict__ X, const float* __restrict__ scale,
    const int* __restrict__ pos,
    __half* __restrict__ hi, __half* __restrict__ lo)
{
    const int warp = threadIdx.x >> 5;
    const int lane = threadIdx.x & 31;
    const long long gw = (long long)blockIdx.x * 8 + warp;   // 0..B*T*H-1
    const int h = (int)(gw & (H - 1));
    const long long row = gw >> 3;                           // b*T + t
    const int b = (int)(row >> 11);
    const int t = (int)(row & 2047);

    const float* xp = X + row * D + h * DH;
    float x0 = xp[lane];
    float x1 = xp[lane + 32];

    float ss = x0 * x0 + x1 * x1;
#pragma unroll
    for (int o = 16; o; o >>= 1) ss += __shfl_xor_sync(0xffffffffu, ss, o);

    float r = rsqrtf(ss * (1.0f / 64.0f) + 1e-6f);
    float y0 = x0 * r * (1.0f + scale[lane]);
    float y1 = x1 * r * (1.0f + scale[lane + 32]);

    double ts  = exp2((double)lane * (1.0 / 32.0) * 13.28771237954945);  // log2(10000)
    double ang = (double)pos[row] / ts;
    float sn = (float)sin(ang);
    float cs = (float)cos(ang);

    float v0 = y0 * cs - y1 * sn;
    float v1 = y1 * cs + y0 * sn;

    size_t o0 = ((size_t)(b * H + h) * T + t) * DH + lane;
    __half h0 = __float2half_rn(v0);
    __half h1 = __float2half_rn(v1);
    hi[o0]      = h0;
    hi[o0 + 32] = h1;
    if (WLO) {
        lo[o0]      = __float2half_rn(v0 - __half2float(h0));
        lo[o0 + 32] = __float2half_rn(v1 - __half2float(h1));
    }
}

// ---------------------------------------------------------------------------
// HMMA causal flash attention, fp16 2-term split:
//   S = Qhi (Khi + Klo)^T ; O = (Phi + Plo) Vhi
// grid (8, 32); CTA 128 queries, 4 warps; 64-key K/V smem tiles, V transposed.
// Output written as fp16 hi activations (GEMM-A layout [row][512]).
// ---------------------------------------------------------------------------
#define ATT_SQH 0
#define ATT_SKH 18432
#define ATT_SKL 27648
#define ATT_SVH 36864
#define ATT_SMEM 46080

__global__ __launch_bounds__(128) void attn_mma_kernel(
    const __half* __restrict__ Qhi,
    const __half* __restrict__ Khi, const __half* __restrict__ Klo,
    const __half* __restrict__ Vhi,
    __half* __restrict__ Ohi)
{
    extern __shared__ char sm[];
    __half (*Qsh)[72] = (__half(*)[72])(sm + ATT_SQH);
    __half (*Ksh)[72] = (__half(*)[72])(sm + ATT_SKH);  // [key][d]
    __half (*Ksl)[72] = (__half(*)[72])(sm + ATT_SKL);
    __half (*Vth)[72] = (__half(*)[72])(sm + ATT_SVH);  // [d][key]

    const int tid  = threadIdx.x;
    const int lane = tid & 31;
    const int w    = tid >> 5;
    const int gid  = lane >> 2;
    const int tig  = lane & 3;
    const int bh   = blockIdx.y;
    const int b    = bh >> 3;
    const int h    = bh & 7;
    const size_t headbase = (size_t)bh * T * DH;

    for (int pass = 0; pass < 2; pass++) {
        const int qt = pass ? (15 - (int)blockIdx.x) : (int)blockIdx.x;
        const int q0 = qt * 128;

        // ---- load Q tile (128x64 hi) ----
#pragma unroll
        for (int i = 0; i < 8; i++) {
            int idx = tid + i * 128;
            int row = idx >> 3;
            int c8  = (idx & 7) * 8;
            size_t g = headbase + (size_t)(q0 + row) * DH + c8;
            *(uint4*)&Qsh[row][c8] = *(const uint4*)&Qhi[g];
        }
        __syncthreads();

        float O[2][8][4];
#pragma unroll
        for (int mf = 0; mf < 2; mf++)
#pragma unroll
            for (int nf = 0; nf < 8; nf++)
#pragma unroll
                for (int r = 0; r < 4; r++) O[mf][nf][r] = 0.f;
        float mrow[4] = {-1e30f, -1e30f, -1e30f, -1e30f};
        float lrow[4] = {0.f, 0.f, 0.f, 0.f};

        const int qwb = q0 + w * 32;
        const int nkt = (qt + 1) * 2;

        for (int kt = 0; kt < nkt; kt++) {
            const int n0 = kt * 64;
            // ---- load K hi/lo (row layout) and V hi (transposed) ----
#pragma unroll
            for (int i = 0; i < 4; i++) {
                int idx = tid + i * 128;
                int key = idx >> 3;
                int c8  = (idx & 7) * 8;
                size_t g = headbase + (size_t)(n0 + key) * DH + c8;
                *(uint4*)&Ksh[key][c8] = *(const uint4*)&Khi[g];
                *(uint4*)&Ksl[key][c8] = *(const uint4*)&Klo[g];
                uint4 vh = *(const uint4*)&Vhi[g];
                __half th[8];
                *(uint4*)th = vh;
#pragma unroll
                for (int j = 0; j < 8; j++)
                    Vth[c8 + j][key] = th[j];
            }
            __syncthreads();

            const bool active = (n0 <= qwb + 31);
            if (active) {
                // ---- S = Qhi (Khi+Klo)^T : 2 MMAs per fragment ----
                float S[2][8][4];
#pragma unroll
                for (int mf = 0; mf < 2; mf++)
#pragma unroll
                    for (int nf = 0; nf < 8; nf++)
#pragma unroll
                        for (int r = 0; r < 4; r++) S[mf][nf][r] = 0.f;

#pragma unroll
                for (int ks = 0; ks < 4; ks++) {
                    const int kb = ks * 16 + tig * 2;
                    uint32_t ah[2][4];
#pragma unroll
                    for (int mf = 0; mf < 2; mf++) {
                        int qr = w * 32 + mf * 16 + gid;
                        ah[mf][0] = *(const uint32_t*)&Qsh[qr    ][kb    ];
                        ah[mf][1] = *(const uint32_t*)&Qsh[qr + 8][kb    ];
                        ah[mf][2] = *(const uint32_t*)&Qsh[qr    ][kb + 8];
                        ah[mf][3] = *(const uint32_t*)&Qsh[qr + 8][kb + 8];
                    }
#pragma unroll
                    for (int nf = 0; nf < 8; nf++) {
                        int kr = nf * 8 + gid;
                        uint32_t bh0 = *(const uint32_t*)&Ksh[kr][kb];
                        uint32_t bh1 = *(const uint32_t*)&Ksh[kr][kb + 8];
                        uint32_t bl0 = *(const uint32_t*)&Ksl[kr][kb];
                        uint32_t bl1 = *(const uint32_t*)&Ksl[kr][kb + 8];
#pragma unroll
                        for (int mf = 0; mf < 2; mf++) {
                            mma16816(S[mf][nf][0], S[mf][nf][1], S[mf][nf][2], S[mf][nf][3],
                                     ah[mf][0], ah[mf][1], ah[mf][2], ah[mf][3], bh0, bh1);
                            mma16816(S[mf][nf][0], S[mf][nf][1], S[mf][nf][2], S[mf][nf][3],
                                     ah[mf][0], ah[mf][1], ah[mf][2], ah[mf][3], bl0, bl1);
                        }
                    }
                }

                const bool needmask = (n0 + 63) > qwb;
#pragma unroll
                for (int mf = 0; mf < 2; mf++)
#pragma unroll
                    for (int nf = 0; nf < 8; nf++)
#pragma unroll
                        for (int r = 0; r < 4; r++) {
                            float s = S[mf][nf][r] * 0.125f;
                            if (needmask) {
                                int key = n0 + nf * 8 + tig * 2 + (r & 1);
                                int qv  = qwb + mf * 16 + gid + ((r >> 1) ? 8 : 0);
                                if (key > qv) s = -1e30f;
                            }
                            S[mf][nf][r] = s;
                        }

                // ---- online softmax ----
                float mt[4] = {-1e30f, -1e30f, -1e30f, -1e30f};
#pragma unroll
                for (int mf = 0; mf < 2; mf++)
#pragma unroll
                    for (int nf = 0; nf < 8; nf++)
#pragma unroll
                        for (int r = 0; r < 4; r++) {
                            int rid = mf * 2 + (r >> 1);
                            mt[rid] = fmaxf(mt[rid], S[mf][nf][r]);
                        }
#pragma unroll
                for (int rid = 0; rid < 4; rid++) {
                    mt[rid] = fmaxf(mt[rid], __shfl_xor_sync(0xffffffffu, mt[rid], 1));
                    mt[rid] = fmaxf(mt[rid], __shfl_xor_sync(0xffffffffu, mt[rid], 2));
                }
                float corr[4];
#pragma unroll
                for (int rid = 0; rid < 4; rid++) {
                    float nm = fmaxf(mrow[rid], mt[rid]);
                    corr[rid] = __expf(mrow[rid] - nm);
                    mrow[rid] = nm;
                }
                float rs[4] = {0.f, 0.f, 0.f, 0.f};
#pragma unroll
                for (int mf = 0; mf < 2; mf++)
#pragma unroll
                    for (int nf = 0; nf < 8; nf++)
#pragma unroll
                        for (int r = 0; r < 4; r++) {
                            int rid = mf * 2 + (r >> 1);
                            float p = __expf(S[mf][nf][r] - mrow[rid]);
                            S[mf][nf][r] = p;
                            rs[rid] += p;
                        }
#pragma unroll
                for (int rid = 0; rid < 4; rid++) {
                    rs[rid] += __shfl_xor_sync(0xffffffffu, rs[rid], 1);
                    rs[rid] += __shfl_xor_sync(0xffffffffu, rs[rid], 2);
                    lrow[rid] = lrow[rid] * corr[rid] + rs[rid];
                }
#pragma unroll
                for (int mf = 0; mf < 2; mf++)
#pragma unroll
                    for (int nf = 0; nf < 8; nf++)
#pragma unroll
                        for (int r = 0; r < 4; r++)
                            O[mf][nf][r] *= corr[mf * 2 + (r >> 1)];

                // ---- pack P to fp16 hi/lo (in-register A-fragments) ----
                uint32_t ph[2][8][2], pl[2][8][2];
#pragma unroll
                for (int mf = 0; mf < 2; mf++)
#pragma unroll
                    for (int nf = 0; nf < 8; nf++)
#pragma unroll
                        for (int half = 0; half < 2; half++) {
                            float p0 = S[mf][nf][half * 2];
                            float p1 = S[mf][nf][half * 2 + 1];
                            __half h0 = __float2half_rn(p0);
                            __half h1 = __float2half_rn(p1);
                            __half2 hp = __halves2half2(h0, h1);
                            __half2 lp = __halves2half2(
                                __float2half_rn(p0 - __half2float(h0)),
                                __float2half_rn(p1 - __half2float(h1)));
                            ph[mf][nf][half] = *(uint32_t*)&hp;
                            pl[mf][nf][half] = *(uint32_t*)&lp;
                        }

                // ---- O += (Phi+Plo) Vhi : 2 MMAs per fragment ----
#pragma unroll
                for (int ks = 0; ks < 4; ks++) {
                    const int kb = ks * 16 + tig * 2;
#pragma unroll
                    for (int nf = 0; nf < 8; nf++) {
                        int dr = nf * 8 + gid;
                        uint32_t bh0 = *(const uint32_t*)&Vth[dr][kb];
                        uint32_t bh1 = *(const uint32_t*)&Vth[dr][kb + 8];
#pragma unroll
                        for (int mf = 0; mf < 2; mf++) {
                            mma16816(O[mf][nf][0], O[mf][nf][1], O[mf][nf][2], O[mf][nf][3],
                                     ph[mf][2*ks][0], ph[mf][2*ks][1],
                                     ph[mf][2*ks+1][0], ph[mf][2*ks+1][1], bh0, bh1);
                            mma16816(O[mf][nf][0], O[mf][nf][1], O[mf][nf][2], O[mf][nf][3],
                                     pl[mf][2*ks][0], pl[mf][2*ks][1],
                                     pl[mf][2*ks+1][0], pl[mf][2*ks+1][1], bh0, bh1);
                        }
                    }
                }
            }
            __syncthreads();
        }

        // ---- epilogue: normalize, store fp16 hi activations ----
        float linv[4];
#pragma unroll
        for (int rid = 0; rid < 4; rid++) linv[rid] = 1.0f / lrow[rid];
#pragma unroll
        for (int mf = 0; mf < 2; mf++) {
            int t0v = q0 + w * 32 + mf * 16 + gid;
#pragma unroll
            for (int nf = 0; nf < 8; nf++) {
                int d = nf * 8 + tig * 2;
#pragma unroll
                for (int half = 0; half < 2; half++) {
                    int tq = t0v + (half ? 8 : 0);
                    float o0 = O[mf][nf][half * 2]     * linv[mf * 2 + half];
                    float o1 = O[mf][nf][half * 2 + 1] * linv[mf * 2 + half];
                    __half2 hp = __floats2half2_rn(o0, o1);
                    size_t oi = ((size_t)(b * T + tq)) * D + h * DH + d;
                    *(uint32_t*)&Ohi[oi] = *(uint32_t*)&hp;
                }
            }
        }
        __syncthreads();
    }
}

// ---------------------------------------------------------------------------
// Launcher
// Inputs: 0 q, 1 kv, 2 mask, 3 q_pos, 4 kv_pos, 5 wq, 6 bq, 7 wk, 8 bk,
//         9 wv, 10 bv, 11 scale_q, 12 scale_k, 13 wo, 14 bo
// ---------------------------------------------------------------------------
extern "C" void kernel_launch(void* const* d_in, const int* in_sizes, int n_in,
                              void* d_out, int out_size)
{
    const float* q   = (const float*)d_in[0];
    const float* kv  = (const float*)d_in[1];
    const int*   qp  = (const int*)d_in[3];
    const int*   kp  = (const int*)d_in[4];
    const float* wq  = (const float*)d_in[5];
    const float* bq  = (const float*)d_in[6];
    const float* wk  = (const float*)d_in[7];
    const float* bk  = (const float*)d_in[8];
    const float* wv  = (const float*)d_in[9];
    const float* bv  = (const float*)d_in[10];
    const float* sq  = (const float*)d_in[11];
    const float* sk  = (const float*)d_in[12];
    const float* wo  = (const float*)d_in[13];
    const float* bo  = (const float*)d_in[14];
    float* out = (float*)d_out;

    float *Qh, *Kh;
    __half *Ahi, *Whi, *Wlo, *Qhi, *Khi, *Klo, *Vhi;
    cudaGetSymbolAddress((void**)&Qh, g_Qh);
    cudaGetSymbolAddress((void**)&Kh, g_Kh);
    cudaGetSymbolAddress((void**)&Ahi, g_Ahi);
    cudaGetSymbolAddress((void**)&Whi, g_Whi);
    cudaGetSymbolAddress((void**)&Wlo, g_Wlo);
    cudaGetSymbolAddress((void**)&Qhi, g_Qhi);
    cudaGetSymbolAddress((void**)&Khi, g_Khi);
    cudaGetSymbolAddress((void**)&Klo, g_Klo);
    cudaGetSymbolAddress((void**)&Vhi, g_Vhi);

    cudaFuncSetAttribute(attn_mma_kernel,
                         cudaFuncAttributeMaxDynamicSharedMemorySize, ATT_SMEM);
    cudaFuncSetAttribute(gemm_cp_kernel<0>,
                         cudaFuncAttributeMaxDynamicSharedMemorySize, GSMEM);
    cudaFuncSetAttribute(gemm_cp_kernel<1>,
                         cudaFuncAttributeMaxDynamicSharedMemorySize, GSMEM);

    const int nA4 = M_ROWS * D / 4;
    dim3 gGemm(GN / 128, M_ROWS / 128);     // (4, 64)
    dim3 gTr(D / 32, D / 32);               // (16, 16)
    dim3 bTr(32, 8);

    // Q projection
    splith_kernel<<<nA4 / 256, 256>>>(q, Ahi, nA4);
    wtrans_kernel<<<gTr, bTr>>>(wq, Whi, Wlo);
    gemm_cp_kernel<0><<<gGemm, 256, GSMEM>>>(Ahi, Whi, Wlo, bq, Qh, nullptr);
    // K projection
    splith_kernel<<<nA4 / 256, 256>>>(kv, Ahi, nA4);
    wtrans_kernel<<<gTr, bTr>>>(wk, Whi, Wlo);
    gemm_cp_kernel<0><<<gGemm, 256, GSMEM>>>(Ahi, Whi, Wlo, bk, Kh, nullptr);
    // V projection -> head-major fp16 directly
    wtrans_kernel<<<gTr, bTr>>>(wv, Whi, Wlo);
    gemm_cp_kernel<1><<<gGemm, 256, GSMEM>>>(Ahi, Whi, Wlo, bv, nullptr, Vhi);

    // norm + rope + head-major fp16
    int nRowHeads = M_ROWS * H;
    rmsropeb_kernel<0><<<nRowHeads / 8, 256>>>(Qh, sq, qp, Qhi, nullptr);
    rmsropeb_kernel<1><<<nRowHeads / 8, 256>>>(Kh, sk, kp, Khi, Klo);

    // attention (writes fp16 activation buffer directly)
    dim3 gAttn(8, BH);
    attn_mma_kernel<<<gAttn, 128, ATT_SMEM>>>(Qhi, Khi, Klo, Vhi, Ahi);

    // output projection
    wtrans_kernel<<<gTr, bTr>>>(wo, Whi, Wlo);
    gemm_cp_kernel<0><<<gGemm, 256, GSMEM>>>(Ahi, Whi, Wlo, bo, out, nullptr);
}

// round 8
// speedup vs baseline: 5.4591x; 1.3064x over previous
#include <cuda_runtime.h>
#include <cuda_fp16.h>
#include <math.h>
#include <cstdint>

// Problem constants (fixed by the dataset)
#define B   4
#define T   2048
#define D   512
#define H   8
#define DH  64
#define M_ROWS (B*T)        // 8192
#define BH  (B*H)           // 32

// ---------------------------------------------------------------------------
// Scratch (device globals; allocation inside kernel_launch is forbidden)
// ---------------------------------------------------------------------------
__device__ float g_Qh[M_ROWS * D];        // fp32 projections (pre-norm)
__device__ float g_Kh[M_ROWS * D];
__device__ __half g_Ahi[M_ROWS * D];      // activation hi (GEMM A, fp16)
__device__ __half g_Whi[D * D];           // transposed weight [n][k] hi
__device__ float2 g_TabQ[M_ROWS * 32];    // per-(row,lane) sin/cos
__device__ float2 g_TabK[M_ROWS * 32];
// head-major [b][h][t][64] fp16 for attention
__device__ __half g_Qhi[BH * T * DH];
__device__ __half g_Khi[BH * T * DH];
__device__ __half g_Klo[BH * T * DH];
__device__ __half g_Vhi[BH * T * DH];

// ---------------------------------------------------------------------------
// Small PTX helpers
// ---------------------------------------------------------------------------
__device__ __forceinline__ uint32_t smem_u32(const void* p) {
    uint32_t a;
    asm("{ .reg .u64 t; cvta.to.shared.u64 t, %1; cvt.u32.u64 %0, t; }" : "=r"(a) : "l"(p));
    return a;
}
__device__ __forceinline__ void cp16(uint32_t dst, const void* src) {
    asm volatile("cp.async.cg.shared.global [%0], [%1], 16;" :: "r"(dst), "l"(src));
}
#define CP_COMMIT() asm volatile("cp.async.commit_group;")
#define CP_WAIT0()  asm volatile("cp.async.wait_group 0;")

__device__ __forceinline__ void ldsm4(uint32_t& r0, uint32_t& r1, uint32_t& r2,
                                      uint32_t& r3, uint32_t a) {
    asm volatile("ldmatrix.sync.aligned.m8n8.x4.shared.b16 {%0,%1,%2,%3}, [%4];"
                 : "=r"(r0), "=r"(r1), "=r"(r2), "=r"(r3) : "r"(a));
}

// m16n8k16 fp16 MMA, fp32 accumulate
__device__ __forceinline__ void mma16816(
    float& c0, float& c1, float& c2, float& c3,
    uint32_t a0, uint32_t a1, uint32_t a2, uint32_t a3,
    uint32_t b0, uint32_t b1)
{
    asm volatile(
        "mma.sync.aligned.m16n8k16.row.col.f32.f16.f16.f32 "
        "{%0,%1,%2,%3}, {%4,%5,%6,%7}, {%8,%9}, {%0,%1,%2,%3};"
        : "+f"(c0), "+f"(c1), "+f"(c2), "+f"(c3)
        : "r"(a0), "r"(a1), "r"(a2), "r"(a3), "r"(b0), "r"(b1));
}

// ---------------------------------------------------------------------------
// fp32 -> fp16 (round-to-nearest), vectorized x4.
// ---------------------------------------------------------------------------
__global__ __launch_bounds__(256) void splith_kernel(
    const float* __restrict__ X, __half* __restrict__ hi, int n4)
{
    int i = blockIdx.x * 256 + threadIdx.x;
    if (i >= n4) return;
    float4 v = ((const float4*)X)[i];
    __half2 h2[2];
    h2[0] = __floats2half2_rn(v.x, v.y);
    h2[1] = __floats2half2_rn(v.z, v.w);
    ((uint2*)hi)[i] = *(uint2*)h2;
}

// ---------------------------------------------------------------------------
// Weight transpose: W[k][n] fp32 -> Wt[n][k] fp16. 32x32 tiles.
// ---------------------------------------------------------------------------
__global__ __launch_bounds__(256) void wtrans_kernel(
    const float* __restrict__ W, __half* __restrict__ hi)
{
    __shared__ float tile[32][33];
    const int tx = threadIdx.x, ty = threadIdx.y;    // block (32, 8)
    const int n0 = blockIdx.x * 32, k0 = blockIdx.y * 32;
#pragma unroll
    for (int i = 0; i < 4; i++)
        tile[ty + i * 8][tx] = W[(size_t)(k0 + ty + i * 8) * D + n0 + tx];
    __syncthreads();
#pragma unroll
    for (int i = 0; i < 4; i++) {
        float v = tile[tx][ty + i * 8];
        hi[(size_t)(n0 + ty + i * 8) * D + k0 + tx] = __float2half_rn(v);
    }
}

// ---------------------------------------------------------------------------
// RoPE sin/cos table: per (row, lane): angle = pos[row] * 10000^(-lane/32).
// Timescale inverse via exact bit-power double constants; double range
// reduction then sincosf (accuracy ~2e-7, matches previous double path).
// ---------------------------------------------------------------------------
__global__ __launch_bounds__(256) void ropetab_kernel(
    const int* __restrict__ pos, float2* __restrict__ tab)
{
    int idx = blockIdx.x * 256 + threadIdx.x;        // < M_ROWS*32
    int row = idx >> 5, lane = idx & 31;
    double w = 1.0;
    if (lane & 1)  w *= 0.7498942093324559;    // 10^(-1/8)
    if (lane & 2)  w *= 0.5623413251903491;    // 10^(-1/4)
    if (lane & 4)  w *= 0.31622776601683794;   // 10^(-1/2)
    if (lane & 8)  w *= 0.1;
    if (lane & 16) w *= 0.01;
    double ang = (double)pos[row] * w;
    double k = rint(ang * 0.15915494309189535);
    float r = (float)fma(-k, 6.283185307179586, ang);
    float s, c;
    sincosf(r, &s, &c);
    tab[idx] = make_float2(s, c);
}

// ---------------------------------------------------------------------------
// cp.async double-buffered HMMA GEMM (fp16, 1-term):
//   C = Ahi@Whi^T + bias ; A[m][k], Wt[n][k]. M=8192, N=K=512.
// CTA 128x128, BK=32, 8 warps of 64x32, ldmatrix fragment loads.
// VOUT=1: write head-major fp16 (V path) instead of fp32 C.
// ---------------------------------------------------------------------------
#define GK 512
#define GN 512
// per stage 2 buffers of 128x40 half (10240 B): Ah, Bh
#define GSTAGE 20480
#define GSMEM  (2 * GSTAGE)

template<int VOUT>
__global__ __launch_bounds__(256, 2) void gemm_cp_kernel(
    const __half* __restrict__ Ahi, const __half* __restrict__ Bhi,
    const float* __restrict__ bias, float* __restrict__ C,
    __half* __restrict__ Vhi)
{
    extern __shared__ char sm[];
    const uint32_t smb = smem_u32(sm);
    const int tid  = threadIdx.x;
    const int lane = tid & 31;
    const int wid  = tid >> 5;
    const int wm   = wid >> 2;
    const int wn   = wid & 3;
    const int m0   = blockIdx.y * 128;
    const int n0   = blockIdx.x * 128;
    const int gid  = lane >> 2;
    const int tig  = lane & 3;

    // ldmatrix per-lane offsets (pad-40 rows, bytes)
    const int lr = lane & 15;
    const int lc = (lane >> 4) * 8;
    uint32_t aoff[4], boff[2];
#pragma unroll
    for (int mf = 0; mf < 4; mf++)
        aoff[mf] = (uint32_t)(((wm * 64 + mf * 16 + lr) * 40 + lc) * 2);
#pragma unroll
    for (int p = 0; p < 2; p++)
        boff[p] = (uint32_t)(((wn * 32 + p * 16 + lr) * 40 + lc) * 2);

    float c[4][4][4];
#pragma unroll
    for (int mf = 0; mf < 4; mf++)
#pragma unroll
        for (int nf = 0; nf < 4; nf++)
#pragma unroll
            for (int r = 0; r < 4; r++) c[mf][nf][r] = 0.f;

    const int prow0 = tid >> 2;
    const int pq    = (tid & 3) * 8;

#define PREFETCH(stage, kc) do {                                              \
        uint32_t sbase = smb + (stage) * GSTAGE;                              \
        _Pragma("unroll")                                                     \
        for (int i_ = 0; i_ < 2; i_++) {                                      \
            int row_ = prow0 + i_ * 64;                                       \
            uint32_t so_ = (uint32_t)((row_ * 40 + pq) * 2);                  \
            size_t ga_ = (size_t)(m0 + row_) * GK + (kc) * 32 + pq;           \
            size_t gb_ = (size_t)(n0 + row_) * GK + (kc) * 32 + pq;           \
            cp16(sbase + so_,          Ahi + ga_);                            \
            cp16(sbase + 10240 + so_,  Bhi + gb_);                            \
        }                                                                     \
    } while (0)

    PREFETCH(0, 0);
    CP_COMMIT();

    for (int kc = 0; kc < 16; kc++) {
        const int st = kc & 1;
        CP_WAIT0();
        __syncthreads();
        if (kc + 1 < 16) { PREFETCH(st ^ 1, kc + 1); CP_COMMIT(); }

        const uint32_t bAh = smb + st * GSTAGE;
        const uint32_t bBh = bAh + 10240;

#pragma unroll
        for (int s = 0; s < 2; s++) {
            uint32_t a[4][4];
#pragma unroll
            for (int mf = 0; mf < 4; mf++)
                ldsm4(a[mf][0], a[mf][1], a[mf][2], a[mf][3], bAh + aoff[mf] + s * 32);
#pragma unroll
            for (int p = 0; p < 2; p++) {
                uint32_t h0, h1, h2, h3;
                ldsm4(h0, h1, h2, h3, bBh + boff[p] + s * 32);
                const int nfa = p * 2, nfb = p * 2 + 1;
#pragma unroll
                for (int mf = 0; mf < 4; mf++) {
                    mma16816(c[mf][nfa][0], c[mf][nfa][1], c[mf][nfa][2], c[mf][nfa][3],
                             a[mf][0], a[mf][1], a[mf][2], a[mf][3], h0, h2);
                    mma16816(c[mf][nfb][0], c[mf][nfb][1], c[mf][nfb][2], c[mf][nfb][3],
                             a[mf][0], a[mf][1], a[mf][2], a[mf][3], h1, h3);
                }
            }
        }
        __syncthreads();
    }
#undef PREFETCH

    // ---- epilogue ----
#pragma unroll
    for (int mf = 0; mf < 4; mf++) {
        int m = m0 + wm * 64 + mf * 16 + gid;
#pragma unroll
        for (int nf = 0; nf < 4; nf++) {
            int n = n0 + wn * 32 + nf * 8 + tig * 2;
            float b0 = __ldg(&bias[n]), b1 = __ldg(&bias[n + 1]);
            float x0 = c[mf][nf][0] + b0, x1 = c[mf][nf][1] + b1;
            float x2 = c[mf][nf][2] + b0, x3 = c[mf][nf][3] + b1;
            if (VOUT) {
                // head-major fp16: m -> (b, t); n -> (h, d)
                int bb = m >> 11, tt = m & 2047;
                int hh = n >> 6,  dd = n & 63;
                size_t o0 = ((size_t)(bb * H + hh) * T + tt) * DH + dd;
                size_t o1 = o0 + 8 * DH;   // row m+8
                __half2 hp0 = __floats2half2_rn(x0, x1);
                __half2 hp1 = __floats2half2_rn(x2, x3);
                *(uint32_t*)&Vhi[o0] = *(uint32_t*)&hp0;
                *(uint32_t*)&Vhi[o1] = *(uint32_t*)&hp1;
            } else {
                *(float2*)&C[(size_t)m * GN + n]       = make_float2(x0, x1);
                *(float2*)&C[(size_t)(m + 8) * GN + n] = make_float2(x2, x3);
            }
        }
    }
}

// ---------------------------------------------------------------------------
// RMSNorm + RoPE (table-driven), fp32 in -> head-major fp16 out [b][h][t][64].
// WLO=1 also writes the fp16 residual (K path: QK stays 2-term).
// ---------------------------------------------------------------------------
template<int WLO>
__global__ __launch_bounds__(256) void rmsropeb_kernel(
    const float* __restrict__ X, const float* __restrict__ scale,
    const float2* __restrict__ tab,
    __half* __restrict__ hi, __half* __restrict__ lo)
{
    const int warp = threadIdx.x >> 5;
    const int lane = threadIdx.x & 31;
    const long long gw = (long long)blockIdx.x * 8 + warp;   // 0..B*T*H-1
    const int h = (int)(gw & (H - 1));
    const long long row = gw >> 3;                           // b*T + t
    const int b = (int)(row >> 11);
    const int t = (int)(row & 2047);

    const float* xp = X + row * D + h * DH;
    float x0 = xp[lane];
    float x1 = xp[lane + 32];

    float ss = x0 * x0 + x1 * x1;
#pragma unroll
    for (int o = 16; o; o >>= 1) ss += __shfl_xor_sync(0xffffffffu, ss, o);

    float r = rsqrtf(ss * (1.0f / 64.0f) + 1e-6f);
    float y0 = x0 * r * (1.0f + scale[lane]);
    float y1 = x1 * r * (1.0f + scale[lane + 32]);

    float2 sc = tab[(size_t)row * 32 + lane];
    float v0 = y0 * sc.y - y1 * sc.x;
    float v1 = y1 * sc.y + y0 * sc.x;

    size_t o0 = ((size_t)(b * H + h) * T + t) * DH + lane;
    __half h0 = __float2half_rn(v0);
    __half h1 = __float2half_rn(v1);
    hi[o0]      = h0;
    hi[o0 + 32] = h1;
    if (WLO) {
        lo[o0]      = __float2half_rn(v0 - __half2float(h0));
        lo[o0 + 32] = __float2half_rn(v1 - __half2float(h1));
    }
}

// ---------------------------------------------------------------------------
// HMMA causal flash attention:
//   S = Qhi (Khi + Klo)^T (2 MMAs) ; O = Phi Vhi (1 MMA)
// grid (8, 32); CTA 128 queries, 4 warps; 64-key K/V smem tiles, V transposed.
// Output written as fp16 activations (GEMM-A layout [row][512]).
// ---------------------------------------------------------------------------
#define ATT_SQH 0
#define ATT_SKH 18432
#define ATT_SKL 27648
#define ATT_SVH 36864
#define ATT_SMEM 46080

__global__ __launch_bounds__(128) void attn_mma_kernel(
    const __half* __restrict__ Qhi,
    const __half* __restrict__ Khi, const __half* __restrict__ Klo,
    const __half* __restrict__ Vhi,
    __half* __restrict__ Ohi)
{
    extern __shared__ char sm[];
    __half (*Qsh)[72] = (__half(*)[72])(sm + ATT_SQH);
    __half (*Ksh)[72] = (__half(*)[72])(sm + ATT_SKH);  // [key][d]
    __half (*Ksl)[72] = (__half(*)[72])(sm + ATT_SKL);
    __half (*Vth)[72] = (__half(*)[72])(sm + ATT_SVH);  // [d][key]

    const int tid  = threadIdx.x;
    const int lane = tid & 31;
    const int w    = tid >> 5;
    const int gid  = lane >> 2;
    const int tig  = lane & 3;
    const int bh   = blockIdx.y;
    const int b    = bh >> 3;
    const int h    = bh & 7;
    const size_t headbase = (size_t)bh * T * DH;

    for (int pass = 0; pass < 2; pass++) {
        const int qt = pass ? (15 - (int)blockIdx.x) : (int)blockIdx.x;
        const int q0 = qt * 128;

        // ---- load Q tile (128x64) ----
#pragma unroll
        for (int i = 0; i < 8; i++) {
            int idx = tid + i * 128;
            int row = idx >> 3;
            int c8  = (idx & 7) * 8;
            size_t g = headbase + (size_t)(q0 + row) * DH + c8;
            *(uint4*)&Qsh[row][c8] = *(const uint4*)&Qhi[g];
        }
        __syncthreads();

        float O[2][8][4];
#pragma unroll
        for (int mf = 0; mf < 2; mf++)
#pragma unroll
            for (int nf = 0; nf < 8; nf++)
#pragma unroll
                for (int r = 0; r < 4; r++) O[mf][nf][r] = 0.f;
        float mrow[4] = {-1e30f, -1e30f, -1e30f, -1e30f};
        float lrow[4] = {0.f, 0.f, 0.f, 0.f};

        const int qwb = q0 + w * 32;
        const int nkt = (qt + 1) * 2;

        for (int kt = 0; kt < nkt; kt++) {
            const int n0 = kt * 64;
            // ---- load K hi/lo (row layout) and V (transposed) ----
#pragma unroll
            for (int i = 0; i < 4; i++) {
                int idx = tid + i * 128;
                int key = idx >> 3;
                int c8  = (idx & 7) * 8;
                size_t g = headbase + (size_t)(n0 + key) * DH + c8;
                *(uint4*)&Ksh[key][c8] = *(const uint4*)&Khi[g];
                *(uint4*)&Ksl[key][c8] = *(const uint4*)&Klo[g];
                uint4 vh = *(const uint4*)&Vhi[g];
                __half th[8];
                *(uint4*)th = vh;
#pragma unroll
                for (int j = 0; j < 8; j++)
                    Vth[c8 + j][key] = th[j];
            }
            __syncthreads();

            const bool active = (n0 <= qwb + 31);
            if (active) {
                // ---- S = Qhi (Khi+Klo)^T ----
                float S[2][8][4];
#pragma unroll
                for (int mf = 0; mf < 2; mf++)
#pragma unroll
                    for (int nf = 0; nf < 8; nf++)
#pragma unroll
                        for (int r = 0; r < 4; r++) S[mf][nf][r] = 0.f;

#pragma unroll
                for (int ks = 0; ks < 4; ks++) {
                    const int kb = ks * 16 + tig * 2;
                    uint32_t ah[2][4];
#pragma unroll
                    for (int mf = 0; mf < 2; mf++) {
                        int qr = w * 32 + mf * 16 + gid;
                        ah[mf][0] = *(const uint32_t*)&Qsh[qr    ][kb    ];
                        ah[mf][1] = *(const uint32_t*)&Qsh[qr + 8][kb    ];
                        ah[mf][2] = *(const uint32_t*)&Qsh[qr    ][kb + 8];
                        ah[mf][3] = *(const uint32_t*)&Qsh[qr + 8][kb + 8];
                    }
#pragma unroll
                    for (int nf = 0; nf < 8; nf++) {
                        int kr = nf * 8 + gid;
                        uint32_t bh0 = *(const uint32_t*)&Ksh[kr][kb];
                        uint32_t bh1 = *(const uint32_t*)&Ksh[kr][kb + 8];
                        uint32_t bl0 = *(const uint32_t*)&Ksl[kr][kb];
                        uint32_t bl1 = *(const uint32_t*)&Ksl[kr][kb + 8];
#pragma unroll
                        for (int mf = 0; mf < 2; mf++) {
                            mma16816(S[mf][nf][0], S[mf][nf][1], S[mf][nf][2], S[mf][nf][3],
                                     ah[mf][0], ah[mf][1], ah[mf][2], ah[mf][3], bh0, bh1);
                            mma16816(S[mf][nf][0], S[mf][nf][1], S[mf][nf][2], S[mf][nf][3],
                                     ah[mf][0], ah[mf][1], ah[mf][2], ah[mf][3], bl0, bl1);
                        }
                    }
                }

                const bool needmask = (n0 + 63) > qwb;
#pragma unroll
                for (int mf = 0; mf < 2; mf++)
#pragma unroll
                    for (int nf = 0; nf < 8; nf++)
#pragma unroll
                        for (int r = 0; r < 4; r++) {
                            float s = S[mf][nf][r] * 0.125f;
                            if (needmask) {
                                int key = n0 + nf * 8 + tig * 2 + (r & 1);
                                int qv  = qwb + mf * 16 + gid + ((r >> 1) ? 8 : 0);
                                if (key > qv) s = -1e30f;
                            }
                            S[mf][nf][r] = s;
                        }

                // ---- online softmax ----
                float mt[4] = {-1e30f, -1e30f, -1e30f, -1e30f};
#pragma unroll
                for (int mf = 0; mf < 2; mf++)
#pragma unroll
                    for (int nf = 0; nf < 8; nf++)
#pragma unroll
                        for (int r = 0; r < 4; r++) {
                            int rid = mf * 2 + (r >> 1);
                            mt[rid] = fmaxf(mt[rid], S[mf][nf][r]);
                        }
#pragma unroll
                for (int rid = 0; rid < 4; rid++) {
                    mt[rid] = fmaxf(mt[rid], __shfl_xor_sync(0xffffffffu, mt[rid], 1));
                    mt[rid] = fmaxf(mt[rid], __shfl_xor_sync(0xffffffffu, mt[rid], 2));
                }
                float corr[4];
#pragma unroll
                for (int rid = 0; rid < 4; rid++) {
                    float nm = fmaxf(mrow[rid], mt[rid]);
                    corr[rid] = __expf(mrow[rid] - nm);
                    mrow[rid] = nm;
                }
                float rs[4] = {0.f, 0.f, 0.f, 0.f};
#pragma unroll
                for (int mf = 0; mf < 2; mf++)
#pragma unroll
                    for (int nf = 0; nf < 8; nf++)
#pragma unroll
                        for (int r = 0; r < 4; r++) {
                            int rid = mf * 2 + (r >> 1);
                            float p = __expf(S[mf][nf][r] - mrow[rid]);
                            S[mf][nf][r] = p;
                            rs[rid] += p;
                        }
#pragma unroll
                for (int rid = 0; rid < 4; rid++) {
                    rs[rid] += __shfl_xor_sync(0xffffffffu, rs[rid], 1);
                    rs[rid] += __shfl_xor_sync(0xffffffffu, rs[rid], 2);
                    lrow[rid] = lrow[rid] * corr[rid] + rs[rid];
                }
#pragma unroll
                for (int mf = 0; mf < 2; mf++)
#pragma unroll
                    for (int nf = 0; nf < 8; nf++)
#pragma unroll
                        for (int r = 0; r < 4; r++)
                            O[mf][nf][r] *= corr[mf * 2 + (r >> 1)];

                // ---- pack P to fp16 (A-fragments) ----
                uint32_t ph[2][8][2];
#pragma unroll
                for (int mf = 0; mf < 2; mf++)
#pragma unroll
                    for (int nf = 0; nf < 8; nf++)
#pragma unroll
                        for (int half = 0; half < 2; half++) {
                            __half2 hp = __floats2half2_rn(S[mf][nf][half * 2],
                                                           S[mf][nf][half * 2 + 1]);
                            ph[mf][nf][half] = *(uint32_t*)&hp;
                        }

                // ---- O += Phi Vhi ----
#pragma unroll
                for (int ks = 0; ks < 4; ks++) {
                    const int kb = ks * 16 + tig * 2;
#pragma unroll
                    for (int nf = 0; nf < 8; nf++) {
                        int dr = nf * 8 + gid;
                        uint32_t bh0 = *(const uint32_t*)&Vth[dr][kb];
                        uint32_t bh1 = *(const uint32_t*)&Vth[dr][kb + 8];
#pragma unroll
                        for (int mf = 0; mf < 2; mf++)
                            mma16816(O[mf][nf][0], O[mf][nf][1], O[mf][nf][2], O[mf][nf][3],
                                     ph[mf][2*ks][0], ph[mf][2*ks][1],
                                     ph[mf][2*ks+1][0], ph[mf][2*ks+1][1], bh0, bh1);
                    }
                }
            }
            __syncthreads();
        }

        // ---- epilogue: normalize, store fp16 activations ----
        float linv[4];
#pragma unroll
        for (int rid = 0; rid < 4; rid++) linv[rid] = 1.0f / lrow[rid];
#pragma unroll
        for (int mf = 0; mf < 2; mf++) {
            int t0v = q0 + w * 32 + mf * 16 + gid;
#pragma unroll
            for (int nf = 0; nf < 8; nf++) {
                int d = nf * 8 + tig * 2;
#pragma unroll
                for (int half = 0; half < 2; half++) {
                    int tq = t0v + (half ? 8 : 0);
                    float o0 = O[mf][nf][half * 2]     * linv[mf * 2 + half];
                    float o1 = O[mf][nf][half * 2 + 1] * linv[mf * 2 + half];
                    __half2 hp = __floats2half2_rn(o0, o1);
                    size_t oi = ((size_t)(b * T + tq)) * D + h * DH + d;
                    *(uint32_t*)&Ohi[oi] = *(uint32_t*)&hp;
                }
            }
        }
        __syncthreads();
    }
}

// ---------------------------------------------------------------------------
// Launcher
// Inputs: 0 q, 1 kv, 2 mask, 3 q_pos, 4 kv_pos, 5 wq, 6 bq, 7 wk, 8 bk,
//         9 wv, 10 bv, 11 scale_q, 12 scale_k, 13 wo, 14 bo
// ---------------------------------------------------------------------------
extern "C" void kernel_launch(void* const* d_in, const int* in_sizes, int n_in,
                              void* d_out, int out_size)
{
    const float* q   = (const float*)d_in[0];
    const float* kv  = (const float*)d_in[1];
    const int*   qp  = (const int*)d_in[3];
    const int*   kp  = (const int*)d_in[4];
    const float* wq  = (const float*)d_in[5];
    const float* bq  = (const float*)d_in[6];
    const float* wk  = (const float*)d_in[7];
    const float* bk  = (const float*)d_in[8];
    const float* wv  = (const float*)d_in[9];
    const float* bv  = (const float*)d_in[10];
    const float* sq  = (const float*)d_in[11];
    const float* sk  = (const float*)d_in[12];
    const float* wo  = (const float*)d_in[13];
    const float* bo  = (const float*)d_in[14];
    float* out = (float*)d_out;

    float *Qh, *Kh;
    float2 *TabQ, *TabK;
    __half *Ahi, *Whi, *Qhi, *Khi, *Klo, *Vhi;
    cudaGetSymbolAddress((void**)&Qh, g_Qh);
    cudaGetSymbolAddress((void**)&Kh, g_Kh);
    cudaGetSymbolAddress((void**)&Ahi, g_Ahi);
    cudaGetSymbolAddress((void**)&Whi, g_Whi);
    cudaGetSymbolAddress((void**)&TabQ, g_TabQ);
    cudaGetSymbolAddress((void**)&TabK, g_TabK);
    cudaGetSymbolAddress((void**)&Qhi, g_Qhi);
    cudaGetSymbolAddress((void**)&Khi, g_Khi);
    cudaGetSymbolAddress((void**)&Klo, g_Klo);
    cudaGetSymbolAddress((void**)&Vhi, g_Vhi);

    cudaFuncSetAttribute(attn_mma_kernel,
                         cudaFuncAttributeMaxDynamicSharedMemorySize, ATT_SMEM);
    cudaFuncSetAttribute(gemm_cp_kernel<0>,
                         cudaFuncAttributeMaxDynamicSharedMemorySize, GSMEM);
    cudaFuncSetAttribute(gemm_cp_kernel<1>,
                         cudaFuncAttributeMaxDynamicSharedMemorySize, GSMEM);

    const int nA4 = M_ROWS * D / 4;
    dim3 gGemm(GN / 128, M_ROWS / 128);     // (4, 64)
    dim3 gTr(D / 32, D / 32);               // (16, 16)
    dim3 bTr(32, 8);

    // RoPE tables (only depend on position inputs)
    ropetab_kernel<<<M_ROWS * 32 / 256, 256>>>(qp, TabQ);
    ropetab_kernel<<<M_ROWS * 32 / 256, 256>>>(kp, TabK);

    // Q projection
    splith_kernel<<<nA4 / 256, 256>>>(q, Ahi, nA4);
    wtrans_kernel<<<gTr, bTr>>>(wq, Whi);
    gemm_cp_kernel<0><<<gGemm, 256, GSMEM>>>(Ahi, Whi, bq, Qh, nullptr);
    // K projection
    splith_kernel<<<nA4 / 256, 256>>>(kv, Ahi, nA4);
    wtrans_kernel<<<gTr, bTr>>>(wk, Whi);
    gemm_cp_kernel<0><<<gGemm, 256, GSMEM>>>(Ahi, Whi, bk, Kh, nullptr);
    // V projection -> head-major fp16 directly
    wtrans_kernel<<<gTr, bTr>>>(wv, Whi);
    gemm_cp_kernel<1><<<gGemm, 256, GSMEM>>>(Ahi, Whi, bv, nullptr, Vhi);

    // norm + rope (table) + head-major fp16
    int nRowHeads = M_ROWS * H;
    rmsropeb_kernel<0><<<nRowHeads / 8, 256>>>(Qh, sq, TabQ, Qhi, nullptr);
    rmsropeb_kernel<1><<<nRowHeads / 8, 256>>>(Kh, sk, TabK, Khi, Klo);

    // attention (writes fp16 activation buffer directly)
    dim3 gAttn(8, BH);
    attn_mma_kernel<<<gAttn, 128, ATT_SMEM>>>(Qhi, Khi, Klo, Vhi, Ahi);

    // output projection
    wtrans_kernel<<<gTr, bTr>>>(wo, Whi);
    gemm_cp_kernel<0><<<gGemm, 256, GSMEM>>>(Ahi, Whi, bo, out, nullptr);
}

// round 9
// speedup vs baseline: 6.2856x; 1.1514x over previous
#include <cuda_runtime.h>
#include <cuda_fp16.h>
#include <math.h>
#include <cstdint>

// Problem constants (fixed by the dataset)
#define B   4
#define T   2048
#define D   512
#define H   8
#define DH  64
#define M_ROWS (B*T)        // 8192
#define BH  (B*H)           // 32

// ---------------------------------------------------------------------------
// Scratch (device globals; allocation inside kernel_launch is forbidden)
// ---------------------------------------------------------------------------
__device__ float g_Qh[M_ROWS * D];        // fp32 projections (pre-norm)
__device__ float g_Kh[M_ROWS * D];
__device__ __half g_Aq[M_ROWS * D];       // fp16 split of q (also attn output)
__device__ __half g_Akv[M_ROWS * D];      // fp16 split of kv
__device__ __half g_W4[4 * D * D];        // transposed weights [n][k]: wq,wk,wv,wo
__device__ float2 g_TabQ[M_ROWS * 32];    // per-(row,lane) sin/cos
__device__ float2 g_TabK[M_ROWS * 32];
// head-major [b][h][t][64] fp16 for attention
__device__ __half g_Qhi[BH * T * DH];
__device__ __half g_Khi[BH * T * DH];
__device__ __half g_Klo[BH * T * DH];
__device__ __half g_Vhi[BH * T * DH];

// ---------------------------------------------------------------------------
// Small PTX helpers
// ---------------------------------------------------------------------------
__device__ __forceinline__ uint32_t smem_u32(const void* p) {
    uint32_t a;
    asm("{ .reg .u64 t; cvta.to.shared.u64 t, %1; cvt.u32.u64 %0, t; }" : "=r"(a) : "l"(p));
    return a;
}
__device__ __forceinline__ void cp16(uint32_t dst, const void* src) {
    asm volatile("cp.async.cg.shared.global [%0], [%1], 16;" :: "r"(dst), "l"(src));
}
#define CP_COMMIT() asm volatile("cp.async.commit_group;")
#define CP_WAIT0()  asm volatile("cp.async.wait_group 0;")

__device__ __forceinline__ void ldsm4(uint32_t& r0, uint32_t& r1, uint32_t& r2,
                                      uint32_t& r3, uint32_t a) {
    asm volatile("ldmatrix.sync.aligned.m8n8.x4.shared.b16 {%0,%1,%2,%3}, [%4];"
                 : "=r"(r0), "=r"(r1), "=r"(r2), "=r"(r3) : "r"(a));
}
__device__ __forceinline__ void ldsm4t(uint32_t& r0, uint32_t& r1, uint32_t& r2,
                                       uint32_t& r3, uint32_t a) {
    asm volatile("ldmatrix.sync.aligned.m8n8.x4.trans.shared.b16 {%0,%1,%2,%3}, [%4];"
                 : "=r"(r0), "=r"(r1), "=r"(r2), "=r"(r3) : "r"(a));
}

// m16n8k16 fp16 MMA, fp32 accumulate
__device__ __forceinline__ void mma16816(
    float& c0, float& c1, float& c2, float& c3,
    uint32_t a0, uint32_t a1, uint32_t a2, uint32_t a3,
    uint32_t b0, uint32_t b1)
{
    asm volatile(
        "mma.sync.aligned.m16n8k16.row.col.f32.f16.f16.f32 "
        "{%0,%1,%2,%3}, {%4,%5,%6,%7}, {%8,%9}, {%0,%1,%2,%3};"
        : "+f"(c0), "+f"(c1), "+f"(c2), "+f"(c3)
        : "r"(a0), "r"(a1), "r"(a2), "r"(a3), "r"(b0), "r"(b1));
}

// ---------------------------------------------------------------------------
// fp32 -> fp16, vectorized x4; y=0: q->Aq, y=1: kv->Akv (fused).
// ---------------------------------------------------------------------------
__global__ __launch_bounds__(256) void splith_kernel(
    const float* __restrict__ q, const float* __restrict__ kv,
    __half* __restrict__ Aq, __half* __restrict__ Akv, int n4)
{
    int i = blockIdx.x * 256 + threadIdx.x;
    if (i >= n4) return;
    const float* X = blockIdx.y ? kv : q;
    __half* hi = blockIdx.y ? Akv : Aq;
    float4 v = ((const float4*)X)[i];
    __half2 h2[2];
    h2[0] = __floats2half2_rn(v.x, v.y);
    h2[1] = __floats2half2_rn(v.z, v.w);
    ((uint2*)hi)[i] = *(uint2*)h2;
}

// ---------------------------------------------------------------------------
// Weight transpose: W[k][n] fp32 -> Wt[n][k] fp16. 32x32 tiles, z picks weight.
// ---------------------------------------------------------------------------
__global__ __launch_bounds__(256) void wtrans_kernel(
    const float* __restrict__ w0, const float* __restrict__ w1,
    const float* __restrict__ w2, const float* __restrict__ w3,
    __half* __restrict__ W4)
{
    __shared__ float tile[32][33];
    const int z = blockIdx.z;
    const float* W = (z == 0) ? w0 : (z == 1) ? w1 : (z == 2) ? w2 : w3;
    __half* dst = W4 + (size_t)z * D * D;
    const int tx = threadIdx.x, ty = threadIdx.y;    // block (32, 8)
    const int n0 = blockIdx.x * 32, k0 = blockIdx.y * 32;
#pragma unroll
    for (int i = 0; i < 4; i++)
        tile[ty + i * 8][tx] = W[(size_t)(k0 + ty + i * 8) * D + n0 + tx];
    __syncthreads();
#pragma unroll
    for (int i = 0; i < 4; i++) {
        float v = tile[tx][ty + i * 8];
        dst[(size_t)(n0 + ty + i * 8) * D + k0 + tx] = __float2half_rn(v);
    }
}

// ---------------------------------------------------------------------------
// RoPE sin/cos tables for both pos arrays (y picks).
// ---------------------------------------------------------------------------
__global__ __launch_bounds__(256) void ropetab_kernel(
    const int* __restrict__ qp, const int* __restrict__ kp,
    float2* __restrict__ TabQ, float2* __restrict__ TabK)
{
    int idx = blockIdx.x * 256 + threadIdx.x;        // < M_ROWS*32
    const int* pos = blockIdx.y ? kp : qp;
    float2* tab = blockIdx.y ? TabK : TabQ;
    int row = idx >> 5, lane = idx & 31;
    double w = 1.0;
    if (lane & 1)  w *= 0.7498942093324559;    // 10^(-1/8)
    if (lane & 2)  w *= 0.5623413251903491;    // 10^(-1/4)
    if (lane & 4)  w *= 0.31622776601683794;   // 10^(-1/2)
    if (lane & 8)  w *= 0.1;
    if (lane & 16) w *= 0.01;
    double ang = (double)pos[row] * w;
    double k = rint(ang * 0.15915494309189535);
    float r = (float)fma(-k, 6.283185307179586, ang);
    float s, c;
    sincosf(r, &s, &c);
    tab[idx] = make_float2(s, c);
}

// ---------------------------------------------------------------------------
// cp.async double-buffered HMMA GEMM, all 4 projections in one kernel.
// z (= blockIdx.z + zbase): 0:Q 1:K 2:V(->head-major fp16) 3:out.
// C = A@Wt^T + bias ; A[m][k] fp16, Wt[n][k] fp16. M=8192, N=K=512.
// CTA 128x128, BK=32, 8 warps of 64x32, ldmatrix fragment loads.
// ---------------------------------------------------------------------------
#define GK 512
#define GN 512
#define GSTAGE 20480
#define GSMEM  (2 * GSTAGE)

__global__ __launch_bounds__(256, 2) void gemm_all_kernel(
    int zbase,
    const __half* __restrict__ Aq, const __half* __restrict__ Akv,
    const __half* __restrict__ W4,
    const float* __restrict__ bq, const float* __restrict__ bk,
    const float* __restrict__ bv, const float* __restrict__ bo,
    float* __restrict__ Qh, float* __restrict__ Kh,
    __half* __restrict__ Vhi, float* __restrict__ out)
{
    const int z = blockIdx.z + zbase;
    const __half* Ahi = (z == 0 || z == 3) ? Aq : Akv;
    const __half* Bhi = W4 + (size_t)z * D * D;
    const float* bias = (z == 0) ? bq : (z == 1) ? bk : (z == 2) ? bv : bo;

    extern __shared__ char sm[];
    const uint32_t smb = smem_u32(sm);
    const int tid  = threadIdx.x;
    const int lane = tid & 31;
    const int wid  = tid >> 5;
    const int wm   = wid >> 2;
    const int wn   = wid & 3;
    const int m0   = blockIdx.y * 128;
    const int n0   = blockIdx.x * 128;
    const int gid  = lane >> 2;
    const int tig  = lane & 3;

    const int lr = lane & 15;
    const int lc = (lane >> 4) * 8;
    uint32_t aoff[4], boff[2];
#pragma unroll
    for (int mf = 0; mf < 4; mf++)
        aoff[mf] = (uint32_t)(((wm * 64 + mf * 16 + lr) * 40 + lc) * 2);
#pragma unroll
    for (int p = 0; p < 2; p++)
        boff[p] = (uint32_t)(((wn * 32 + p * 16 + lr) * 40 + lc) * 2);

    float c[4][4][4];
#pragma unroll
    for (int mf = 0; mf < 4; mf++)
#pragma unroll
        for (int nf = 0; nf < 4; nf++)
#pragma unroll
            for (int r = 0; r < 4; r++) c[mf][nf][r] = 0.f;

    const int prow0 = tid >> 2;
    const int pq    = (tid & 3) * 8;

#define PREFETCH(stage, kc) do {                                              \
        uint32_t sbase = smb + (stage) * GSTAGE;                              \
        _Pragma("unroll")                                                     \
        for (int i_ = 0; i_ < 2; i_++) {                                      \
            int row_ = prow0 + i_ * 64;                                       \
            uint32_t so_ = (uint32_t)((row_ * 40 + pq) * 2);                  \
            size_t ga_ = (size_t)(m0 + row_) * GK + (kc) * 32 + pq;           \
            size_t gb_ = (size_t)(n0 + row_) * GK + (kc) * 32 + pq;           \
            cp16(sbase + so_,          Ahi + ga_);                            \
            cp16(sbase + 10240 + so_,  Bhi + gb_);                            \
        }                                                                     \
    } while (0)

    PREFETCH(0, 0);
    CP_COMMIT();

    for (int kc = 0; kc < 16; kc++) {
        const int st = kc & 1;
        CP_WAIT0();
        __syncthreads();
        if (kc + 1 < 16) { PREFETCH(st ^ 1, kc + 1); CP_COMMIT(); }

        const uint32_t bAh = smb + st * GSTAGE;
        const uint32_t bBh = bAh + 10240;

#pragma unroll
        for (int s = 0; s < 2; s++) {
            uint32_t a[4][4];
#pragma unroll
            for (int mf = 0; mf < 4; mf++)
                ldsm4(a[mf][0], a[mf][1], a[mf][2], a[mf][3], bAh + aoff[mf] + s * 32);
#pragma unroll
            for (int p = 0; p < 2; p++) {
                uint32_t h0, h1, h2, h3;
                ldsm4(h0, h1, h2, h3, bBh + boff[p] + s * 32);
                const int nfa = p * 2, nfb = p * 2 + 1;
#pragma unroll
                for (int mf = 0; mf < 4; mf++) {
                    mma16816(c[mf][nfa][0], c[mf][nfa][1], c[mf][nfa][2], c[mf][nfa][3],
                             a[mf][0], a[mf][1], a[mf][2], a[mf][3], h0, h2);
                    mma16816(c[mf][nfb][0], c[mf][nfb][1], c[mf][nfb][2], c[mf][nfb][3],
                             a[mf][0], a[mf][1], a[mf][2], a[mf][3], h1, h3);
                }
            }
        }
        __syncthreads();
    }
#undef PREFETCH

    // ---- epilogue ----
    float* C = (z == 0) ? Qh : (z == 1) ? Kh : out;
#pragma unroll
    for (int mf = 0; mf < 4; mf++) {
        int m = m0 + wm * 64 + mf * 16 + gid;
#pragma unroll
        for (int nf = 0; nf < 4; nf++) {
            int n = n0 + wn * 32 + nf * 8 + tig * 2;
            float b0 = __ldg(&bias[n]), b1 = __ldg(&bias[n + 1]);
            float x0 = c[mf][nf][0] + b0, x1 = c[mf][nf][1] + b1;
            float x2 = c[mf][nf][2] + b0, x3 = c[mf][nf][3] + b1;
            if (z == 2) {
                // V path: head-major fp16: m -> (b, t); n -> (h, d)
                int bb = m >> 11, tt = m & 2047;
                int hh = n >> 6,  dd = n & 63;
                size_t o0 = ((size_t)(bb * H + hh) * T + tt) * DH + dd;
                size_t o1 = o0 + 8 * DH;   // row m+8
                __half2 hp0 = __floats2half2_rn(x0, x1);
                __half2 hp1 = __floats2half2_rn(x2, x3);
                *(uint32_t*)&Vhi[o0] = *(uint32_t*)&hp0;
                *(uint32_t*)&Vhi[o1] = *(uint32_t*)&hp1;
            } else {
                *(float2*)&C[(size_t)m * GN + n]       = make_float2(x0, x1);
                *(float2*)&C[(size_t)(m + 8) * GN + n] = make_float2(x2, x3);
            }
        }
    }
}

// ---------------------------------------------------------------------------
// RMSNorm + RoPE (table), fused Q/K by blockIdx.y.
// y=0: Qh -> Qhi ; y=1: Kh -> Khi + Klo (K residual kept for 2-term QK).
// ---------------------------------------------------------------------------
__global__ __launch_bounds__(256) void rmsropeb_kernel(
    const float* __restrict__ Qh, const float* __restrict__ Kh,
    const float* __restrict__ sq, const float* __restrict__ sk,
    const float2* __restrict__ TabQ, const float2* __restrict__ TabK,
    __half* __restrict__ Qhi, __half* __restrict__ Khi, __half* __restrict__ Klo)
{
    const int yk = blockIdx.y;
    const float* X = yk ? Kh : Qh;
    const float* scale = yk ? sk : sq;
    const float2* tab = yk ? TabK : TabQ;
    __half* hi = yk ? Khi : Qhi;

    const int warp = threadIdx.x >> 5;
    const int lane = threadIdx.x & 31;
    const long long gw = (long long)blockIdx.x * 8 + warp;   // 0..B*T*H-1
    const int h = (int)(gw & (H - 1));
    const long long row = gw >> 3;                           // b*T + t
    const int b = (int)(row >> 11);
    const int t = (int)(row & 2047);

    const float* xp = X + row * D + h * DH;
    float x0 = xp[lane];
    float x1 = xp[lane + 32];

    float ss = x0 * x0 + x1 * x1;
#pragma unroll
    for (int o = 16; o; o >>= 1) ss += __shfl_xor_sync(0xffffffffu, ss, o);

    float r = rsqrtf(ss * (1.0f / 64.0f) + 1e-6f);
    float y0 = x0 * r * (1.0f + scale[lane]);
    float y1 = x1 * r * (1.0f + scale[lane + 32]);

    float2 sc = tab[(size_t)row * 32 + lane];
    float v0 = y0 * sc.y - y1 * sc.x;
    float v1 = y1 * sc.y + y0 * sc.x;

    size_t o0 = ((size_t)(b * H + h) * T + t) * DH + lane;
    __half h0 = __float2half_rn(v0);
    __half h1 = __float2half_rn(v1);
    hi[o0]      = h0;
    hi[o0 + 32] = h1;
    if (yk) {
        Klo[o0]      = __float2half_rn(v0 - __half2float(h0));
        Klo[o0 + 32] = __float2half_rn(v1 - __half2float(h1));
    }
}

// ---------------------------------------------------------------------------
// HMMA causal flash attention, 8 warps x 16 queries (128-query CTA):
//   S = Qhi (Khi + Klo)^T (2 MMAs) ; O = Phi Vhi (1 MMA)
// grid (8, 32), pass pairing (qt, 15-qt). All fragments via ldmatrix;
// V row-major + ldmatrix.trans. Output: fp16 activations [row][512].
// ---------------------------------------------------------------------------
#define ATT_SMEM 46080   // Qsh 128x72 | Ksh 64x72 | Ksl 64x72 | Vs 64x72

__global__ __launch_bounds__(256, 2) void attn_mma_kernel(
    const __half* __restrict__ Qhi,
    const __half* __restrict__ Khi, const __half* __restrict__ Klo,
    const __half* __restrict__ Vhi,
    __half* __restrict__ Ohi)
{
    extern __shared__ char sm[];
    __half (*Qsh)[72] = (__half(*)[72])(sm);
    __half (*Ksh)[72] = (__half(*)[72])(sm + 18432);
    __half (*Ksl)[72] = (__half(*)[72])(sm + 27648);
    __half (*Vs)[72]  = (__half(*)[72])(sm + 36864);

    const uint32_t smb = smem_u32(sm);
    const int tid  = threadIdx.x;
    const int lane = tid & 31;
    const int w    = tid >> 5;          // 0..7
    const int gid  = lane >> 2;
    const int tig  = lane & 3;
    const int lr   = lane & 15;
    const int lc   = (lane >> 4) * 8;
    const int bh   = blockIdx.y;
    const int b    = bh >> 3;
    const int h    = bh & 7;
    const size_t headbase = (size_t)bh * T * DH;

    const uint32_t smQ  = smb;
    const uint32_t smKh = smb + 18432;
    const uint32_t smKl = smb + 27648;
    const uint32_t smV  = smb + 36864;
    const uint32_t qoff = smQ + (uint32_t)((w * 16 + lr) * 144 + lc * 2);
    const uint32_t kro  = (uint32_t)(lr * 144 + lc * 2);   // + p*2304 + ks*32

    for (int pass = 0; pass < 2; pass++) {
        const int qt = pass ? (15 - (int)blockIdx.x) : (int)blockIdx.x;
        const int q0 = qt * 128;

        // ---- load Q tile (128x64) ----
#pragma unroll
        for (int i = 0; i < 4; i++) {
            int idx = tid + i * 256;
            int row = idx >> 3;
            int c8  = (idx & 7) * 8;
            size_t g = headbase + (size_t)(q0 + row) * DH + c8;
            *(uint4*)&Qsh[row][c8] = *(const uint4*)&Qhi[g];
        }
        __syncthreads();

        float O[8][4];
#pragma unroll
        for (int nf = 0; nf < 8; nf++)
#pragma unroll
            for (int r = 0; r < 4; r++) O[nf][r] = 0.f;
        float mrow[2] = {-1e30f, -1e30f};
        float lrow[2] = {0.f, 0.f};

        const int qwb = q0 + w * 16;
        const int nkt = (qt + 1) * 2;

        for (int kt = 0; kt < nkt; kt++) {
            const int n0 = kt * 64;
            // ---- load K hi/lo + V (all row-major [key][d]) ----
#pragma unroll
            for (int i = 0; i < 2; i++) {
                int idx = tid + i * 256;
                int key = idx >> 3;
                int c8  = (idx & 7) * 8;
                size_t g = headbase + (size_t)(n0 + key) * DH + c8;
                *(uint4*)&Ksh[key][c8] = *(const uint4*)&Khi[g];
                *(uint4*)&Ksl[key][c8] = *(const uint4*)&Klo[g];
                *(uint4*)&Vs[key][c8]  = *(const uint4*)&Vhi[g];
            }
            __syncthreads();

            const bool active = (n0 <= qwb + 15);
            if (active) {
                // ---- S = Qhi (Khi+Klo)^T ----
                float S[8][4];
#pragma unroll
                for (int nf = 0; nf < 8; nf++)
#pragma unroll
                    for (int r = 0; r < 4; r++) S[nf][r] = 0.f;

#pragma unroll
                for (int ks = 0; ks < 4; ks++) {
                    uint32_t a0, a1, a2, a3;
                    ldsm4(a0, a1, a2, a3, qoff + ks * 32);
#pragma unroll
                    for (int p = 0; p < 4; p++) {
                        uint32_t h0, h1, h2, h3, l0, l1, l2, l3;
                        ldsm4(h0, h1, h2, h3, smKh + kro + p * 2304 + ks * 32);
                        ldsm4(l0, l1, l2, l3, smKl + kro + p * 2304 + ks * 32);
                        mma16816(S[2*p][0], S[2*p][1], S[2*p][2], S[2*p][3],
                                 a0, a1, a2, a3, h0, h2);
                        mma16816(S[2*p][0], S[2*p][1], S[2*p][2], S[2*p][3],
                                 a0, a1, a2, a3, l0, l2);
                        mma16816(S[2*p+1][0], S[2*p+1][1], S[2*p+1][2], S[2*p+1][3],
                                 a0, a1, a2, a3, h1, h3);
                        mma16816(S[2*p+1][0], S[2*p+1][1], S[2*p+1][2], S[2*p+1][3],
                                 a0, a1, a2, a3, l1, l3);
                    }
                }

                // ---- scale + causal mask ----
                const bool needmask = (n0 + 63) > qwb;
#pragma unroll
                for (int nf = 0; nf < 8; nf++)
#pragma unroll
                    for (int r = 0; r < 4; r++) {
                        float s = S[nf][r] * 0.125f;
                        if (needmask) {
                            int key = n0 + nf * 8 + tig * 2 + (r & 1);
                            int qv  = qwb + gid + ((r >> 1) ? 8 : 0);
                            if (key > qv) s = -1e30f;
                        }
                        S[nf][r] = s;
                    }

                // ---- online softmax (rid = r>>1: rows gid, gid+8) ----
                float mt[2] = {-1e30f, -1e30f};
#pragma unroll
                for (int nf = 0; nf < 8; nf++)
#pragma unroll
                    for (int r = 0; r < 4; r++)
                        mt[r >> 1] = fmaxf(mt[r >> 1], S[nf][r]);
#pragma unroll
                for (int rid = 0; rid < 2; rid++) {
                    mt[rid] = fmaxf(mt[rid], __shfl_xor_sync(0xffffffffu, mt[rid], 1));
                    mt[rid] = fmaxf(mt[rid], __shfl_xor_sync(0xffffffffu, mt[rid], 2));
                }
                float corr[2];
#pragma unroll
                for (int rid = 0; rid < 2; rid++) {
                    float nm = fmaxf(mrow[rid], mt[rid]);
                    corr[rid] = __expf(mrow[rid] - nm);
                    mrow[rid] = nm;
                }
                float rs[2] = {0.f, 0.f};
#pragma unroll
                for (int nf = 0; nf < 8; nf++)
#pragma unroll
                    for (int r = 0; r < 4; r++) {
                        float p = __expf(S[nf][r] - mrow[r >> 1]);
                        S[nf][r] = p;
                        rs[r >> 1] += p;
                    }
#pragma unroll
                for (int rid = 0; rid < 2; rid++) {
                    rs[rid] += __shfl_xor_sync(0xffffffffu, rs[rid], 1);
                    rs[rid] += __shfl_xor_sync(0xffffffffu, rs[rid], 2);
                    lrow[rid] = lrow[rid] * corr[rid] + rs[rid];
                }
#pragma unroll
                for (int nf = 0; nf < 8; nf++)
#pragma unroll
                    for (int r = 0; r < 4; r++)
                        O[nf][r] *= corr[r >> 1];

                // ---- pack P to fp16 A-fragments ----
                uint32_t ph[8][2];
#pragma unroll
                for (int nf = 0; nf < 8; nf++) {
                    __half2 hp0 = __floats2half2_rn(S[nf][0], S[nf][1]);
                    __half2 hp1 = __floats2half2_rn(S[nf][2], S[nf][3]);
                    ph[nf][0] = *(uint32_t*)&hp0;
                    ph[nf][1] = *(uint32_t*)&hp1;
                }

                // ---- O += Phi Vhi (V via ldmatrix.trans) ----
#pragma unroll
                for (int ks = 0; ks < 4; ks++) {
                    uint32_t a0 = ph[2*ks][0], a1 = ph[2*ks][1];
                    uint32_t a2 = ph[2*ks+1][0], a3 = ph[2*ks+1][1];
#pragma unroll
                    for (int p = 0; p < 4; p++) {
                        uint32_t v0, v1, v2, v3;
                        ldsm4t(v0, v1, v2, v3, smV + kro + ks * 2304 + p * 32);
                        mma16816(O[2*p][0], O[2*p][1], O[2*p][2], O[2*p][3],
                                 a0, a1, a2, a3, v0, v1);
                        mma16816(O[2*p+1][0], O[2*p+1][1], O[2*p+1][2], O[2*p+1][3],
                                 a0, a1, a2, a3, v2, v3);
                    }
                }
            }
            __syncthreads();
        }

        // ---- epilogue: normalize, store fp16 activations [row][512] ----
        float linv[2] = {1.0f / lrow[0], 1.0f / lrow[1]};
        const int tq0 = q0 + w * 16 + gid;
#pragma unroll
        for (int nf = 0; nf < 8; nf++) {
            int d = nf * 8 + tig * 2;
#pragma unroll
            for (int half = 0; half < 2; half++) {
                int tq = tq0 + (half ? 8 : 0);
                float o0 = O[nf][half * 2]     * linv[half];
                float o1 = O[nf][half * 2 + 1] * linv[half];
                __half2 hp = __floats2half2_rn(o0, o1);
                size_t oi = ((size_t)(b * T + tq)) * D + h * DH + d;
                *(uint32_t*)&Ohi[oi] = *(uint32_t*)&hp;
            }
        }
        __syncthreads();
    }
}

// ---------------------------------------------------------------------------
// Launcher
// Inputs: 0 q, 1 kv, 2 mask, 3 q_pos, 4 kv_pos, 5 wq, 6 bq, 7 wk, 8 bk,
//         9 wv, 10 bv, 11 scale_q, 12 scale_k, 13 wo, 14 bo
// ---------------------------------------------------------------------------
extern "C" void kernel_launch(void* const* d_in, const int* in_sizes, int n_in,
                              void* d_out, int out_size)
{
    const float* q   = (const float*)d_in[0];
    const float* kv  = (const float*)d_in[1];
    const int*   qp  = (const int*)d_in[3];
    const int*   kp  = (const int*)d_in[4];
    const float* wq  = (const float*)d_in[5];
    const float* bq  = (const float*)d_in[6];
    const float* wk  = (const float*)d_in[7];
    const float* bk  = (const float*)d_in[8];
    const float* wv  = (const float*)d_in[9];
    const float* bv  = (const float*)d_in[10];
    const float* sq  = (const float*)d_in[11];
    const float* sk  = (const float*)d_in[12];
    const float* wo  = (const float*)d_in[13];
    const float* bo  = (const float*)d_in[14];
    float* out = (float*)d_out;

    float *Qh, *Kh;
    float2 *TabQ, *TabK;
    __half *Aq, *Akv, *W4, *Qhi, *Khi, *Klo, *Vhi;
    cudaGetSymbolAddress((void**)&Qh, g_Qh);
    cudaGetSymbolAddress((void**)&Kh, g_Kh);
    cudaGetSymbolAddress((void**)&Aq, g_Aq);
    cudaGetSymbolAddress((void**)&Akv, g_Akv);
    cudaGetSymbolAddress((void**)&W4, g_W4);
    cudaGetSymbolAddress((void**)&TabQ, g_TabQ);
    cudaGetSymbolAddress((void**)&TabK, g_TabK);
    cudaGetSymbolAddress((void**)&Qhi, g_Qhi);
    cudaGetSymbolAddress((void**)&Khi, g_Khi);
    cudaGetSymbolAddress((void**)&Klo, g_Klo);
    cudaGetSymbolAddress((void**)&Vhi, g_Vhi);

    cudaFuncSetAttribute(attn_mma_kernel,
                         cudaFuncAttributeMaxDynamicSharedMemorySize, ATT_SMEM);
    cudaFuncSetAttribute(gemm_all_kernel,
                         cudaFuncAttributeMaxDynamicSharedMemorySize, GSMEM);

    const int nA4 = M_ROWS * D / 4;     // 1048576
    dim3 bTr(32, 8);

    // 1. RoPE tables (both)
    ropetab_kernel<<<dim3(M_ROWS * 32 / 256, 2), 256>>>(qp, kp, TabQ, TabK);
    // 2. fp16 splits of q and kv
    splith_kernel<<<dim3(nA4 / 256, 2), 256>>>(q, kv, Aq, Akv, nA4);
    // 3. all 4 weight transposes
    wtrans_kernel<<<dim3(16, 16, 4), bTr>>>(wq, wk, wv, wo, W4);
    // 4. Q/K/V projections in one launch (z = 0,1,2)
    gemm_all_kernel<<<dim3(4, 64, 3), 256, GSMEM>>>(
        0, Aq, Akv, W4, bq, bk, bv, bo, Qh, Kh, Vhi, nullptr);
    // 5. norm + rope for Q and K
    rmsropeb_kernel<<<dim3(M_ROWS, 2), 256>>>(
        Qh, Kh, sq, sk, TabQ, TabK, Qhi, Khi, Klo);
    // 6. attention (writes fp16 activations into Aq)
    attn_mma_kernel<<<dim3(8, BH), 256, ATT_SMEM>>>(Qhi, Khi, Klo, Vhi, Aq);
    // 7. output projection (z = 3)
    gemm_all_kernel<<<dim3(4, 64, 1), 256, GSMEM>>>(
        3, Aq, Akv, W4, bq, bk, bv, bo, Qh, Kh, Vhi, out);
}

// round 10
// speedup vs baseline: 7.1965x; 1.1449x over previous
#include <cuda_runtime.h>
#include <cuda_fp16.h>
#include <math.h>
#include <cstdint>

// Problem constants (fixed by the dataset)
#define B   4
#define T   2048
#define D   512
#define H   8
#define DH  64
#define M_ROWS (B*T)        // 8192
#define BH  (B*H)           // 32

// ---------------------------------------------------------------------------
// Scratch (device globals; allocation inside kernel_launch is forbidden)
// ---------------------------------------------------------------------------
__device__ float g_Qh[M_ROWS * D];        // fp32 projections (pre-norm)
__device__ float g_Kh[M_ROWS * D];
__device__ __half g_Aq[M_ROWS * D];       // fp16 split of q (also attn output)
__device__ __half g_Akv[M_ROWS * D];      // fp16 split of kv
__device__ __half g_W4[4 * D * D];        // transposed weights [n][k]: wq,wk,wv,wo
__device__ float2 g_TabQ[M_ROWS * 32];    // per-(row,lane) sin/cos
__device__ float2 g_TabK[M_ROWS * 32];
// head-major [b][h][t][64] fp16 for attention
__device__ __half g_Qhi[BH * T * DH];
__device__ __half g_Khi[BH * T * DH];
__device__ __half g_Vhi[BH * T * DH];

// ---------------------------------------------------------------------------
// Small PTX helpers
// ---------------------------------------------------------------------------
__device__ __forceinline__ uint32_t smem_u32(const void* p) {
    uint32_t a;
    asm("{ .reg .u64 t; cvta.to.shared.u64 t, %1; cvt.u32.u64 %0, t; }" : "=r"(a) : "l"(p));
    return a;
}
__device__ __forceinline__ void cp16(uint32_t dst, const void* src) {
    asm volatile("cp.async.cg.shared.global [%0], [%1], 16;" :: "r"(dst), "l"(src));
}
#define CP_COMMIT() asm volatile("cp.async.commit_group;")
#define CP_WAIT0()  asm volatile("cp.async.wait_group 0;")

__device__ __forceinline__ void ldsm4(uint32_t& r0, uint32_t& r1, uint32_t& r2,
                                      uint32_t& r3, uint32_t a) {
    asm volatile("ldmatrix.sync.aligned.m8n8.x4.shared.b16 {%0,%1,%2,%3}, [%4];"
                 : "=r"(r0), "=r"(r1), "=r"(r2), "=r"(r3) : "r"(a));
}
__device__ __forceinline__ void ldsm4t(uint32_t& r0, uint32_t& r1, uint32_t& r2,
                                       uint32_t& r3, uint32_t a) {
    asm volatile("ldmatrix.sync.aligned.m8n8.x4.trans.shared.b16 {%0,%1,%2,%3}, [%4];"
                 : "=r"(r0), "=r"(r1), "=r"(r2), "=r"(r3) : "r"(a));
}

// m16n8k16 fp16 MMA, fp32 accumulate
__device__ __forceinline__ void mma16816(
    float& c0, float& c1, float& c2, float& c3,
    uint32_t a0, uint32_t a1, uint32_t a2, uint32_t a3,
    uint32_t b0, uint32_t b1)
{
    asm volatile(
        "mma.sync.aligned.m16n8k16.row.col.f32.f16.f16.f32 "
        "{%0,%1,%2,%3}, {%4,%5,%6,%7}, {%8,%9}, {%0,%1,%2,%3};"
        : "+f"(c0), "+f"(c1), "+f"(c2), "+f"(c3)
        : "r"(a0), "r"(a1), "r"(a2), "r"(a3), "r"(b0), "r"(b1));
}

// ---------------------------------------------------------------------------
// fp32 -> fp16, vectorized x4; y=0: q->Aq, y=1: kv->Akv (fused).
// ---------------------------------------------------------------------------
__global__ __launch_bounds__(256) void splith_kernel(
    const float* __restrict__ q, const float* __restrict__ kv,
    __half* __restrict__ Aq, __half* __restrict__ Akv, int n4)
{
    int i = blockIdx.x * 256 + threadIdx.x;
    if (i >= n4) return;
    const float* X = blockIdx.y ? kv : q;
    __half* hi = blockIdx.y ? Akv : Aq;
    float4 v = ((const float4*)X)[i];
    __half2 h2[2];
    h2[0] = __floats2half2_rn(v.x, v.y);
    h2[1] = __floats2half2_rn(v.z, v.w);
    ((uint2*)hi)[i] = *(uint2*)h2;
}

// ---------------------------------------------------------------------------
// Weight transpose: W[k][n] fp32 -> Wt[n][k] fp16. 32x32 tiles, z picks weight.
// ---------------------------------------------------------------------------
__global__ __launch_bounds__(256) void wtrans_kernel(
    const float* __restrict__ w0, const float* __restrict__ w1,
    const float* __restrict__ w2, const float* __restrict__ w3,
    __half* __restrict__ W4)
{
    __shared__ float tile[32][33];
    const int z = blockIdx.z;
    const float* W = (z == 0) ? w0 : (z == 1) ? w1 : (z == 2) ? w2 : w3;
    __half* dst = W4 + (size_t)z * D * D;
    const int tx = threadIdx.x, ty = threadIdx.y;    // block (32, 8)
    const int n0 = blockIdx.x * 32, k0 = blockIdx.y * 32;
#pragma unroll
    for (int i = 0; i < 4; i++)
        tile[ty + i * 8][tx] = W[(size_t)(k0 + ty + i * 8) * D + n0 + tx];
    __syncthreads();
#pragma unroll
    for (int i = 0; i < 4; i++) {
        float v = tile[tx][ty + i * 8];
        dst[(size_t)(n0 + ty + i * 8) * D + k0 + tx] = __float2half_rn(v);
    }
}

// ---------------------------------------------------------------------------
// RoPE sin/cos tables for both pos arrays (y picks).
// ---------------------------------------------------------------------------
__global__ __launch_bounds__(256) void ropetab_kernel(
    const int* __restrict__ qp, const int* __restrict__ kp,
    float2* __restrict__ TabQ, float2* __restrict__ TabK)
{
    int idx = blockIdx.x * 256 + threadIdx.x;        // < M_ROWS*32
    const int* pos = blockIdx.y ? kp : qp;
    float2* tab = blockIdx.y ? TabK : TabQ;
    int row = idx >> 5, lane = idx & 31;
    double w = 1.0;
    if (lane & 1)  w *= 0.7498942093324559;    // 10^(-1/8)
    if (lane & 2)  w *= 0.5623413251903491;    // 10^(-1/4)
    if (lane & 4)  w *= 0.31622776601683794;   // 10^(-1/2)
    if (lane & 8)  w *= 0.1;
    if (lane & 16) w *= 0.01;
    double ang = (double)pos[row] * w;
    double k = rint(ang * 0.15915494309189535);
    float r = (float)fma(-k, 6.283185307179586, ang);
    float s, c;
    sincosf(r, &s, &c);
    tab[idx] = make_float2(s, c);
}

// ---------------------------------------------------------------------------
// cp.async double-buffered HMMA GEMM, all 4 projections in one kernel.
// z (= blockIdx.z + zbase): 0:Q 1:K 2:V(->head-major fp16) 3:out.
// C = A@Wt^T + bias ; A[m][k] fp16, Wt[n][k] fp16. M=8192, N=K=512.
// CTA 128x128, BK=32, 8 warps of 64x32, ldmatrix fragment loads.
// ---------------------------------------------------------------------------
#define GK 512
#define GN 512
#define GSTAGE 20480
#define GSMEM  (2 * GSTAGE)

__global__ __launch_bounds__(256, 2) void gemm_all_kernel(
    int zbase,
    const __half* __restrict__ Aq, const __half* __restrict__ Akv,
    const __half* __restrict__ W4,
    const float* __restrict__ bq, const float* __restrict__ bk,
    const float* __restrict__ bv, const float* __restrict__ bo,
    float* __restrict__ Qh, float* __restrict__ Kh,
    __half* __restrict__ Vhi, float* __restrict__ out)
{
    const int z = blockIdx.z + zbase;
    const __half* Ahi = (z == 0 || z == 3) ? Aq : Akv;
    const __half* Bhi = W4 + (size_t)z * D * D;
    const float* bias = (z == 0) ? bq : (z == 1) ? bk : (z == 2) ? bv : bo;

    extern __shared__ char sm[];
    const uint32_t smb = smem_u32(sm);
    const int tid  = threadIdx.x;
    const int lane = tid & 31;
    const int wid  = tid >> 5;
    const int wm   = wid >> 2;
    const int wn   = wid & 3;
    const int m0   = blockIdx.y * 128;
    const int n0   = blockIdx.x * 128;
    const int gid  = lane >> 2;
    const int tig  = lane & 3;

    const int lr = lane & 15;
    const int lc = (lane >> 4) * 8;
    uint32_t aoff[4], boff[2];
#pragma unroll
    for (int mf = 0; mf < 4; mf++)
        aoff[mf] = (uint32_t)(((wm * 64 + mf * 16 + lr) * 40 + lc) * 2);
#pragma unroll
    for (int p = 0; p < 2; p++)
        boff[p] = (uint32_t)(((wn * 32 + p * 16 + lr) * 40 + lc) * 2);

    float c[4][4][4];
#pragma unroll
    for (int mf = 0; mf < 4; mf++)
#pragma unroll
        for (int nf = 0; nf < 4; nf++)
#pragma unroll
            for (int r = 0; r < 4; r++) c[mf][nf][r] = 0.f;

    const int prow0 = tid >> 2;
    const int pq    = (tid & 3) * 8;

#define PREFETCH(stage, kc) do {                                              \
        uint32_t sbase = smb + (stage) * GSTAGE;                              \
        _Pragma("unroll")                                                     \
        for (int i_ = 0; i_ < 2; i_++) {                                      \
            int row_ = prow0 + i_ * 64;                                       \
            uint32_t so_ = (uint32_t)((row_ * 40 + pq) * 2);                  \
            size_t ga_ = (size_t)(m0 + row_) * GK + (kc) * 32 + pq;           \
            size_t gb_ = (size_t)(n0 + row_) * GK + (kc) * 32 + pq;           \
            cp16(sbase + so_,          Ahi + ga_);                            \
            cp16(sbase + 10240 + so_,  Bhi + gb_);                            \
        }                                                                     \
    } while (0)

    PREFETCH(0, 0);
    CP_COMMIT();

    for (int kc = 0; kc < 16; kc++) {
        const int st = kc & 1;
        CP_WAIT0();
        __syncthreads();
        if (kc + 1 < 16) { PREFETCH(st ^ 1, kc + 1); CP_COMMIT(); }

        const uint32_t bAh = smb + st * GSTAGE;
        const uint32_t bBh = bAh + 10240;

#pragma unroll
        for (int s = 0; s < 2; s++) {
            uint32_t a[4][4];
#pragma unroll
            for (int mf = 0; mf < 4; mf++)
                ldsm4(a[mf][0], a[mf][1], a[mf][2], a[mf][3], bAh + aoff[mf] + s * 32);
#pragma unroll
            for (int p = 0; p < 2; p++) {
                uint32_t h0, h1, h2, h3;
                ldsm4(h0, h1, h2, h3, bBh + boff[p] + s * 32);
                const int nfa = p * 2, nfb = p * 2 + 1;
#pragma unroll
                for (int mf = 0; mf < 4; mf++) {
                    mma16816(c[mf][nfa][0], c[mf][nfa][1], c[mf][nfa][2], c[mf][nfa][3],
                             a[mf][0], a[mf][1], a[mf][2], a[mf][3], h0, h2);
                    mma16816(c[mf][nfb][0], c[mf][nfb][1], c[mf][nfb][2], c[mf][nfb][3],
                             a[mf][0], a[mf][1], a[mf][2], a[mf][3], h1, h3);
                }
            }
        }
        __syncthreads();
    }
#undef PREFETCH

    // ---- epilogue ----
    float* C = (z == 0) ? Qh : (z == 1) ? Kh : out;
#pragma unroll
    for (int mf = 0; mf < 4; mf++) {
        int m = m0 + wm * 64 + mf * 16 + gid;
#pragma unroll
        for (int nf = 0; nf < 4; nf++) {
            int n = n0 + wn * 32 + nf * 8 + tig * 2;
            float b0 = __ldg(&bias[n]), b1 = __ldg(&bias[n + 1]);
            float x0 = c[mf][nf][0] + b0, x1 = c[mf][nf][1] + b1;
            float x2 = c[mf][nf][2] + b0, x3 = c[mf][nf][3] + b1;
            if (z == 2) {
                // V path: head-major fp16: m -> (b, t); n -> (h, d)
                int bb = m >> 11, tt = m & 2047;
                int hh = n >> 6,  dd = n & 63;
                size_t o0 = ((size_t)(bb * H + hh) * T + tt) * DH + dd;
                size_t o1 = o0 + 8 * DH;   // row m+8
                __half2 hp0 = __floats2half2_rn(x0, x1);
                __half2 hp1 = __floats2half2_rn(x2, x3);
                *(uint32_t*)&Vhi[o0] = *(uint32_t*)&hp0;
                *(uint32_t*)&Vhi[o1] = *(uint32_t*)&hp1;
            } else {
                *(float2*)&C[(size_t)m * GN + n]       = make_float2(x0, x1);
                *(float2*)&C[(size_t)(m + 8) * GN + n] = make_float2(x2, x3);
            }
        }
    }
}

// ---------------------------------------------------------------------------
// RMSNorm + RoPE (table), fused Q/K by blockIdx.y -> head-major fp16.
// ---------------------------------------------------------------------------
__global__ __launch_bounds__(256) void rmsropeb_kernel(
    const float* __restrict__ Qh, const float* __restrict__ Kh,
    const float* __restrict__ sq, const float* __restrict__ sk,
    const float2* __restrict__ TabQ, const float2* __restrict__ TabK,
    __half* __restrict__ Qhi, __half* __restrict__ Khi)
{
    const int yk = blockIdx.y;
    const float* X = yk ? Kh : Qh;
    const float* scale = yk ? sk : sq;
    const float2* tab = yk ? TabK : TabQ;
    __half* hi = yk ? Khi : Qhi;

    const int warp = threadIdx.x >> 5;
    const int lane = threadIdx.x & 31;
    const long long gw = (long long)blockIdx.x * 8 + warp;   // 0..B*T*H-1
    const int h = (int)(gw & (H - 1));
    const long long row = gw >> 3;                           // b*T + t
    const int b = (int)(row >> 11);
    const int t = (int)(row & 2047);

    const float* xp = X + row * D + h * DH;
    float x0 = xp[lane];
    float x1 = xp[lane + 32];

    float ss = x0 * x0 + x1 * x1;
#pragma unroll
    for (int o = 16; o; o >>= 1) ss += __shfl_xor_sync(0xffffffffu, ss, o);

    float r = rsqrtf(ss * (1.0f / 64.0f) + 1e-6f);
    float y0 = x0 * r * (1.0f + scale[lane]);
    float y1 = x1 * r * (1.0f + scale[lane + 32]);

    float2 sc = tab[(size_t)row * 32 + lane];
    float v0 = y0 * sc.y - y1 * sc.x;
    float v1 = y1 * sc.y + y0 * sc.x;

    size_t o0 = ((size_t)(b * H + h) * T + t) * DH + lane;
    hi[o0]      = __float2half_rn(v0);
    hi[o0 + 32] = __float2half_rn(v1);
}

// ---------------------------------------------------------------------------
// HMMA causal flash attention, 8 warps x 16 queries (128-query CTA):
//   S = Qhi Khi^T (1 MMA) ; O = Phi Vhi (1 MMA)
// grid (8, 32), pass pairing (qt, 15-qt). All fragments via ldmatrix;
// V row-major + ldmatrix.trans. Output: fp16 activations [row][512].
// ---------------------------------------------------------------------------
#define ATT_SMEM 36864   // Qsh 128x72 | Ksh 64x72 | Vs 64x72

__global__ __launch_bounds__(256, 2) void attn_mma_kernel(
    const __half* __restrict__ Qhi, const __half* __restrict__ Khi,
    const __half* __restrict__ Vhi,
    __half* __restrict__ Ohi)
{
    extern __shared__ char sm[];
    __half (*Qsh)[72] = (__half(*)[72])(sm);
    __half (*Ksh)[72] = (__half(*)[72])(sm + 18432);
    __half (*Vs)[72]  = (__half(*)[72])(sm + 27648);

    const uint32_t smb = smem_u32(sm);
    const int tid  = threadIdx.x;
    const int lane = tid & 31;
    const int w    = tid >> 5;          // 0..7
    const int gid  = lane >> 2;
    const int tig  = lane & 3;
    const int lr   = lane & 15;
    const int lc   = (lane >> 4) * 8;
    const int bh   = blockIdx.y;
    const int b    = bh >> 3;
    const int h    = bh & 7;
    const size_t headbase = (size_t)bh * T * DH;

    const uint32_t smQ  = smb;
    const uint32_t smKh = smb + 18432;
    const uint32_t smV  = smb + 27648;
    const uint32_t qoff = smQ + (uint32_t)((w * 16 + lr) * 144 + lc * 2);
    const uint32_t kro  = (uint32_t)(lr * 144 + lc * 2);   // + p*2304 + ks*32

    for (int pass = 0; pass < 2; pass++) {
        const int qt = pass ? (15 - (int)blockIdx.x) : (int)blockIdx.x;
        const int q0 = qt * 128;

        // ---- load Q tile (128x64) ----
#pragma unroll
        for (int i = 0; i < 4; i++) {
            int idx = tid + i * 256;
            int row = idx >> 3;
            int c8  = (idx & 7) * 8;
            size_t g = headbase + (size_t)(q0 + row) * DH + c8;
            *(uint4*)&Qsh[row][c8] = *(const uint4*)&Qhi[g];
        }
        __syncthreads();

        float O[8][4];
#pragma unroll
        for (int nf = 0; nf < 8; nf++)
#pragma unroll
            for (int r = 0; r < 4; r++) O[nf][r] = 0.f;
        float mrow[2] = {-1e30f, -1e30f};
        float lrow[2] = {0.f, 0.f};

        const int qwb = q0 + w * 16;
        const int nkt = (qt + 1) * 2;

        for (int kt = 0; kt < nkt; kt++) {
            const int n0 = kt * 64;
            // ---- load K + V (row-major [key][d]) ----
            {
                int key = tid >> 2;
                int c8  = (tid & 3) * 16;
                size_t g = headbase + (size_t)(n0 + key) * DH + c8;
                *(uint4*)&Ksh[key][c8]     = *(const uint4*)&Khi[g];
                *(uint4*)&Ksh[key][c8 + 8] = *(const uint4*)&Khi[g + 8];
                *(uint4*)&Vs[key][c8]      = *(const uint4*)&Vhi[g];
                *(uint4*)&Vs[key][c8 + 8]  = *(const uint4*)&Vhi[g + 8];
            }
            __syncthreads();

            const bool active = (n0 <= qwb + 15);
            if (active) {
                // ---- S = Qhi Khi^T ----
                float S[8][4];
#pragma unroll
                for (int nf = 0; nf < 8; nf++)
#pragma unroll
                    for (int r = 0; r < 4; r++) S[nf][r] = 0.f;

#pragma unroll
                for (int ks = 0; ks < 4; ks++) {
                    uint32_t a0, a1, a2, a3;
                    ldsm4(a0, a1, a2, a3, qoff + ks * 32);
#pragma unroll
                    for (int p = 0; p < 4; p++) {
                        uint32_t h0, h1, h2, h3;
                        ldsm4(h0, h1, h2, h3, smKh + kro + p * 2304 + ks * 32);
                        mma16816(S[2*p][0], S[2*p][1], S[2*p][2], S[2*p][3],
                                 a0, a1, a2, a3, h0, h2);
                        mma16816(S[2*p+1][0], S[2*p+1][1], S[2*p+1][2], S[2*p+1][3],
                                 a0, a1, a2, a3, h1, h3);
                    }
                }

                // ---- scale + causal mask ----
                const bool needmask = (n0 + 63) > qwb;
#pragma unroll
                for (int nf = 0; nf < 8; nf++)
#pragma unroll
                    for (int r = 0; r < 4; r++) {
                        float s = S[nf][r] * 0.125f;
                        if (needmask) {
                            int key = n0 + nf * 8 + tig * 2 + (r & 1);
                            int qv  = qwb + gid + ((r >> 1) ? 8 : 0);
                            if (key > qv) s = -1e30f;
                        }
                        S[nf][r] = s;
                    }

                // ---- online softmax (rid = r>>1: rows gid, gid+8) ----
                float mt[2] = {-1e30f, -1e30f};
#pragma unroll
                for (int nf = 0; nf < 8; nf++)
#pragma unroll
                    for (int r = 0; r < 4; r++)
                        mt[r >> 1] = fmaxf(mt[r >> 1], S[nf][r]);
#pragma unroll
                for (int rid = 0; rid < 2; rid++) {
                    mt[rid] = fmaxf(mt[rid], __shfl_xor_sync(0xffffffffu, mt[rid], 1));
                    mt[rid] = fmaxf(mt[rid], __shfl_xor_sync(0xffffffffu, mt[rid], 2));
                }
                float corr[2];
#pragma unroll
                for (int rid = 0; rid < 2; rid++) {
                    float nm = fmaxf(mrow[rid], mt[rid]);
                    corr[rid] = __expf(mrow[rid] - nm);
                    mrow[rid] = nm;
                }
                float rs[2] = {0.f, 0.f};
#pragma unroll
                for (int nf = 0; nf < 8; nf++)
#pragma unroll
                    for (int r = 0; r < 4; r++) {
                        float p = __expf(S[nf][r] - mrow[r >> 1]);
                        S[nf][r] = p;
                        rs[r >> 1] += p;
                    }
#pragma unroll
                for (int rid = 0; rid < 2; rid++) {
                    rs[rid] += __shfl_xor_sync(0xffffffffu, rs[rid], 1);
                    rs[rid] += __shfl_xor_sync(0xffffffffu, rs[rid], 2);
                    lrow[rid] = lrow[rid] * corr[rid] + rs[rid];
                }
#pragma unroll
                for (int nf = 0; nf < 8; nf++)
#pragma unroll
                    for (int r = 0; r < 4; r++)
                        O[nf][r] *= corr[r >> 1];

                // ---- pack P to fp16 A-fragments ----
                uint32_t ph[8][2];
#pragma unroll
                for (int nf = 0; nf < 8; nf++) {
                    __half2 hp0 = __floats2half2_rn(S[nf][0], S[nf][1]);
                    __half2 hp1 = __floats2half2_rn(S[nf][2], S[nf][3]);
                    ph[nf][0] = *(uint32_t*)&hp0;
                    ph[nf][1] = *(uint32_t*)&hp1;
                }

                // ---- O += Phi Vhi (V via ldmatrix.trans) ----
#pragma unroll
                for (int ks = 0; ks < 4; ks++) {
                    uint32_t a0 = ph[2*ks][0], a1 = ph[2*ks][1];
                    uint32_t a2 = ph[2*ks+1][0], a3 = ph[2*ks+1][1];
#pragma unroll
                    for (int p = 0; p < 4; p++) {
                        uint32_t v0, v1, v2, v3;
                        ldsm4t(v0, v1, v2, v3, smV + kro + ks * 2304 + p * 32);
                        mma16816(O[2*p][0], O[2*p][1], O[2*p][2], O[2*p][3],
                                 a0, a1, a2, a3, v0, v1);
                        mma16816(O[2*p+1][0], O[2*p+1][1], O[2*p+1][2], O[2*p+1][3],
                                 a0, a1, a2, a3, v2, v3);
                    }
                }
            }
            __syncthreads();
        }

        // ---- epilogue: normalize, store fp16 activations [row][512] ----
        float linv[2] = {1.0f / lrow[0], 1.0f / lrow[1]};
        const int tq0 = q0 + w * 16 + gid;
#pragma unroll
        for (int nf = 0; nf < 8; nf++) {
            int d = nf * 8 + tig * 2;
#pragma unroll
            for (int half = 0; half < 2; half++) {
                int tq = tq0 + (half ? 8 : 0);
                float o0 = O[nf][half * 2]     * linv[half];
                float o1 = O[nf][half * 2 + 1] * linv[half];
                __half2 hp = __floats2half2_rn(o0, o1);
                size_t oi = ((size_t)(b * T + tq)) * D + h * DH + d;
                *(uint32_t*)&Ohi[oi] = *(uint32_t*)&hp;
            }
        }
        __syncthreads();
    }
}

// ---------------------------------------------------------------------------
// Launcher
// Inputs: 0 q, 1 kv, 2 mask, 3 q_pos, 4 kv_pos, 5 wq, 6 bq, 7 wk, 8 bk,
//         9 wv, 10 bv, 11 scale_q, 12 scale_k, 13 wo, 14 bo
// ---------------------------------------------------------------------------
extern "C" void kernel_launch(void* const* d_in, const int* in_sizes, int n_in,
                              void* d_out, int out_size)
{
    const float* q   = (const float*)d_in[0];
    const float* kv  = (const float*)d_in[1];
    const int*   qp  = (const int*)d_in[3];
    const int*   kp  = (const int*)d_in[4];
    const float* wq  = (const float*)d_in[5];
    const float* bq  = (const float*)d_in[6];
    const float* wk  = (const float*)d_in[7];
    const float* bk  = (const float*)d_in[8];
    const float* wv  = (const float*)d_in[9];
    const float* bv  = (const float*)d_in[10];
    const float* sq  = (const float*)d_in[11];
    const float* sk  = (const float*)d_in[12];
    const float* wo  = (const float*)d_in[13];
    const float* bo  = (const float*)d_in[14];
    float* out = (float*)d_out;

    float *Qh, *Kh;
    float2 *TabQ, *TabK;
    __half *Aq, *Akv, *W4, *Qhi, *Khi, *Vhi;
    cudaGetSymbolAddress((void**)&Qh, g_Qh);
    cudaGetSymbolAddress((void**)&Kh, g_Kh);
    cudaGetSymbolAddress((void**)&Aq, g_Aq);
    cudaGetSymbolAddress((void**)&Akv, g_Akv);
    cudaGetSymbolAddress((void**)&W4, g_W4);
    cudaGetSymbolAddress((void**)&TabQ, g_TabQ);
    cudaGetSymbolAddress((void**)&TabK, g_TabK);
    cudaGetSymbolAddress((void**)&Qhi, g_Qhi);
    cudaGetSymbolAddress((void**)&Khi, g_Khi);
    cudaGetSymbolAddress((void**)&Vhi, g_Vhi);

    cudaFuncSetAttribute(attn_mma_kernel,
                         cudaFuncAttributeMaxDynamicSharedMemorySize, ATT_SMEM);
    cudaFuncSetAttribute(gemm_all_kernel,
                         cudaFuncAttributeMaxDynamicSharedMemorySize, GSMEM);

    const int nA4 = M_ROWS * D / 4;     // 1048576
    dim3 bTr(32, 8);

    // 1. RoPE tables (both)
    ropetab_kernel<<<dim3(M_ROWS * 32 / 256, 2), 256>>>(qp, kp, TabQ, TabK);
    // 2. fp16 splits of q and kv
    splith_kernel<<<dim3(nA4 / 256, 2), 256>>>(q, kv, Aq, Akv, nA4);
    // 3. all 4 weight transposes
    wtrans_kernel<<<dim3(16, 16, 4), bTr>>>(wq, wk, wv, wo, W4);
    // 4. Q/K/V projections in one launch (z = 0,1,2)
    gemm_all_kernel<<<dim3(4, 64, 3), 256, GSMEM>>>(
        0, Aq, Akv, W4, bq, bk, bv, bo, Qh, Kh, Vhi, nullptr);
    // 5. norm + rope for Q and K
    rmsropeb_kernel<<<dim3(M_ROWS, 2), 256>>>(
        Qh, Kh, sq, sk, TabQ, TabK, Qhi, Khi);
    // 6. attention (writes fp16 activations into Aq)
    attn_mma_kernel<<<dim3(8, BH), 256, ATT_SMEM>>>(Qhi, Khi, Vhi, Aq);
    // 7. output projection (z = 3)
    gemm_all_kernel<<<dim3(4, 64, 1), 256, GSMEM>>>(
        3, Aq, Akv, W4, bq, bk, bv, bo, Qh, Kh, Vhi, out);
}

// round 11
// speedup vs baseline: 7.5566x; 1.0500x over previous
#include <cuda_runtime.h>
#include <cuda_fp16.h>
#include <math.h>
#include <cstdint>

// Problem constants (fixed by the dataset)
#define B   4
#define T   2048
#define D   512
#define H   8
#define DH  64
#define M_ROWS (B*T)        // 8192
#define BH  (B*H)           // 32

// ---------------------------------------------------------------------------
// Scratch (device globals; allocation inside kernel_launch is forbidden)
// ---------------------------------------------------------------------------
__device__ float g_Qh[M_ROWS * D];        // fp32 projections (pre-norm)
__device__ float g_Kh[M_ROWS * D];
__device__ __half g_Aq[M_ROWS * D];       // fp16 split of q (also attn output)
__device__ __half g_Akv[M_ROWS * D];      // fp16 split of kv
__device__ __half g_W4[4 * D * D];        // transposed weights [n][k]: wq,wk,wv,wo
__device__ float2 g_TabQ[M_ROWS * 32];    // per-(row,lane) sin/cos
__device__ float2 g_TabK[M_ROWS * 32];
// head-major [b][h][t][64] fp16 for attention
__device__ __half g_Qhi[BH * T * DH];
__device__ __half g_Khi[BH * T * DH];
__device__ __half g_Vhi[BH * T * DH];

// ---------------------------------------------------------------------------
// Small PTX helpers
// ---------------------------------------------------------------------------
__device__ __forceinline__ uint32_t smem_u32(const void* p) {
    uint32_t a;
    asm("{ .reg .u64 t; cvta.to.shared.u64 t, %1; cvt.u32.u64 %0, t; }" : "=r"(a) : "l"(p));
    return a;
}
__device__ __forceinline__ void cp16(uint32_t dst, const void* src) {
    asm volatile("cp.async.cg.shared.global [%0], [%1], 16;" :: "r"(dst), "l"(src));
}
#define CP_COMMIT() asm volatile("cp.async.commit_group;")
#define CP_WAIT0()  asm volatile("cp.async.wait_group 0;")
#define CP_WAIT1()  asm volatile("cp.async.wait_group 1;")

__device__ __forceinline__ void ldsm4(uint32_t& r0, uint32_t& r1, uint32_t& r2,
                                      uint32_t& r3, uint32_t a) {
    asm volatile("ldmatrix.sync.aligned.m8n8.x4.shared.b16 {%0,%1,%2,%3}, [%4];"
                 : "=r"(r0), "=r"(r1), "=r"(r2), "=r"(r3) : "r"(a));
}
__device__ __forceinline__ void ldsm4t(uint32_t& r0, uint32_t& r1, uint32_t& r2,
                                       uint32_t& r3, uint32_t a) {
    asm volatile("ldmatrix.sync.aligned.m8n8.x4.trans.shared.b16 {%0,%1,%2,%3}, [%4];"
                 : "=r"(r0), "=r"(r1), "=r"(r2), "=r"(r3) : "r"(a));
}

// m16n8k16 fp16 MMA, fp32 accumulate
__device__ __forceinline__ void mma16816(
    float& c0, float& c1, float& c2, float& c3,
    uint32_t a0, uint32_t a1, uint32_t a2, uint32_t a3,
    uint32_t b0, uint32_t b1)
{
    asm volatile(
        "mma.sync.aligned.m16n8k16.row.col.f32.f16.f16.f32 "
        "{%0,%1,%2,%3}, {%4,%5,%6,%7}, {%8,%9}, {%0,%1,%2,%3};"
        : "+f"(c0), "+f"(c1), "+f"(c2), "+f"(c3)
        : "r"(a0), "r"(a1), "r"(a2), "r"(a3), "r"(b0), "r"(b1));
}

// ---------------------------------------------------------------------------
// Fused prep kernel (1-D grid, range switch):
//  [0, 1024)       : weight transpose+convert (4 weights x 256 tiles)
//  [1024, 9216)    : fp32->fp16 split of q / kv
//  [9216, 11264)   : RoPE sin/cos tables for q_pos / kv_pos
// ---------------------------------------------------------------------------
__global__ __launch_bounds__(256) void prep_kernel(
    const float* __restrict__ q, const float* __restrict__ kv,
    const int* __restrict__ qp, const int* __restrict__ kp,
    const float* __restrict__ wq, const float* __restrict__ wk,
    const float* __restrict__ wv, const float* __restrict__ wo,
    __half* __restrict__ Aq, __half* __restrict__ Akv,
    __half* __restrict__ W4,
    float2* __restrict__ TabQ, float2* __restrict__ TabK)
{
    __shared__ float tile[32][33];
    const int bx = blockIdx.x;
    const int tid = threadIdx.x;

    if (bx < 1024) {
        // ---- weight transpose: W[k][n] fp32 -> Wt[n][k] fp16 ----
        const int z = bx >> 8, rem = bx & 255;
        const int n0 = (rem & 15) * 32, k0 = (rem >> 4) * 32;
        const float* W = (z == 0) ? wq : (z == 1) ? wk : (z == 2) ? wv : wo;
        __half* dst = W4 + (size_t)z * D * D;
        const int tx = tid & 31, ty = tid >> 5;
#pragma unroll
        for (int i = 0; i < 4; i++)
            tile[ty + i * 8][tx] = W[(size_t)(k0 + ty + i * 8) * D + n0 + tx];
        __syncthreads();
#pragma unroll
        for (int i = 0; i < 4; i++) {
            float v = tile[tx][ty + i * 8];
            dst[(size_t)(n0 + ty + i * 8) * D + k0 + tx] = __float2half_rn(v);
        }
    } else if (bx < 9216) {
        // ---- fp32 -> fp16 split ----
        const int idx = bx - 1024;
        const int yk = idx >> 12;
        const int i = (idx & 4095) * 256 + tid;       // < 1048576
        const float* X = yk ? kv : q;
        __half* hi = yk ? Akv : Aq;
        float4 v = ((const float4*)X)[i];
        __half2 h2[2];
        h2[0] = __floats2half2_rn(v.x, v.y);
        h2[1] = __floats2half2_rn(v.z, v.w);
        ((uint2*)hi)[i] = *(uint2*)h2;
    } else {
        // ---- RoPE tables ----
        const int idx = bx - 9216;
        const int yk = idx >> 10;
        const int gi = (idx & 1023) * 256 + tid;      // < 262144
        const int* pos = yk ? kp : qp;
        float2* tab = yk ? TabK : TabQ;
        int row = gi >> 5, lane = gi & 31;
        double w = 1.0;
        if (lane & 1)  w *= 0.7498942093324559;    // 10^(-1/8)
        if (lane & 2)  w *= 0.5623413251903491;    // 10^(-1/4)
        if (lane & 4)  w *= 0.31622776601683794;   // 10^(-1/2)
        if (lane & 8)  w *= 0.1;
        if (lane & 16) w *= 0.01;
        double ang = (double)pos[row] * w;
        double k = rint(ang * 0.15915494309189535);
        float r = (float)fma(-k, 6.283185307179586, ang);
        float s, c;
        sincosf(r, &s, &c);
        tab[gi] = make_float2(s, c);
    }
}

// ---------------------------------------------------------------------------
// 3-stage cp.async HMMA GEMM, all 4 projections in one kernel.
// z (= blockIdx.z + zbase): 0:Q 1:K 2:V(->head-major fp16) 3:out.
// C = A@Wt^T + bias ; A[m][k] fp16, Wt[n][k] fp16. M=8192, N=K=512.
// CTA 128x128, BK=32, 8 warps of 64x32, ldmatrix fragment loads.
// ---------------------------------------------------------------------------
#define GK 512
#define GN 512
#define GSTAGE 20480
#define GSMEM  (3 * GSTAGE)

__global__ __launch_bounds__(256, 2) void gemm_all_kernel(
    int zbase,
    const __half* __restrict__ Aq, const __half* __restrict__ Akv,
    const __half* __restrict__ W4,
    const float* __restrict__ bq, const float* __restrict__ bk,
    const float* __restrict__ bv, const float* __restrict__ bo,
    float* __restrict__ Qh, float* __restrict__ Kh,
    __half* __restrict__ Vhi, float* __restrict__ out)
{
    const int z = blockIdx.z + zbase;
    const __half* Ahi = (z == 0 || z == 3) ? Aq : Akv;
    const __half* Bhi = W4 + (size_t)z * D * D;
    const float* bias = (z == 0) ? bq : (z == 1) ? bk : (z == 2) ? bv : bo;

    extern __shared__ char sm[];
    const uint32_t smb = smem_u32(sm);
    const int tid  = threadIdx.x;
    const int lane = tid & 31;
    const int wid  = tid >> 5;
    const int wm   = wid >> 2;
    const int wn   = wid & 3;
    const int m0   = blockIdx.y * 128;
    const int n0   = blockIdx.x * 128;
    const int gid  = lane >> 2;
    const int tig  = lane & 3;

    const int lr = lane & 15;
    const int lc = (lane >> 4) * 8;
    uint32_t aoff[4], boff[2];
#pragma unroll
    for (int mf = 0; mf < 4; mf++)
        aoff[mf] = (uint32_t)(((wm * 64 + mf * 16 + lr) * 40 + lc) * 2);
#pragma unroll
    for (int p = 0; p < 2; p++)
        boff[p] = (uint32_t)(((wn * 32 + p * 16 + lr) * 40 + lc) * 2);

    float c[4][4][4];
#pragma unroll
    for (int mf = 0; mf < 4; mf++)
#pragma unroll
        for (int nf = 0; nf < 4; nf++)
#pragma unroll
            for (int r = 0; r < 4; r++) c[mf][nf][r] = 0.f;

    const int prow0 = tid >> 2;
    const int pq    = (tid & 3) * 8;

#define PREFETCH(stage, kc) do {                                              \
        uint32_t sbase = smb + (stage) * GSTAGE;                              \
        _Pragma("unroll")                                                     \
        for (int i_ = 0; i_ < 2; i_++) {                                      \
            int row_ = prow0 + i_ * 64;                                       \
            uint32_t so_ = (uint32_t)((row_ * 40 + pq) * 2);                  \
            size_t ga_ = (size_t)(m0 + row_) * GK + (kc) * 32 + pq;           \
            size_t gb_ = (size_t)(n0 + row_) * GK + (kc) * 32 + pq;           \
            cp16(sbase + so_,          Ahi + ga_);                            \
            cp16(sbase + 10240 + so_,  Bhi + gb_);                            \
        }                                                                     \
    } while (0)

    PREFETCH(0, 0); CP_COMMIT();
    PREFETCH(1, 1); CP_COMMIT();
    CP_WAIT1();
    __syncthreads();

    for (int kc = 0; kc < 16; kc++) {
        const int st = kc % 3;
        // prefetch 2 chunks ahead (stage (kc+2)%3 was last read at kc-1;
        // the barrier at end of kc-1 made that safe). Empty commit keeps
        // group counting constant so CP_WAIT1 always means "group kc+1 done".
        if (kc + 2 < 16) PREFETCH((kc + 2) % 3, kc + 2);
        CP_COMMIT();

        const uint32_t bAh = smb + st * GSTAGE;
        const uint32_t bBh = bAh + 10240;
#pragma unroll
        for (int s = 0; s < 2; s++) {
            uint32_t a[4][4];
#pragma unroll
            for (int mf = 0; mf < 4; mf++)
                ldsm4(a[mf][0], a[mf][1], a[mf][2], a[mf][3], bAh + aoff[mf] + s * 32);
#pragma unroll
            for (int p = 0; p < 2; p++) {
                uint32_t h0, h1, h2, h3;
                ldsm4(h0, h1, h2, h3, bBh + boff[p] + s * 32);
                const int nfa = p * 2, nfb = p * 2 + 1;
#pragma unroll
                for (int mf = 0; mf < 4; mf++) {
                    mma16816(c[mf][nfa][0], c[mf][nfa][1], c[mf][nfa][2], c[mf][nfa][3],
                             a[mf][0], a[mf][1], a[mf][2], a[mf][3], h0, h2);
                    mma16816(c[mf][nfb][0], c[mf][nfb][1], c[mf][nfb][2], c[mf][nfb][3],
                             a[mf][0], a[mf][1], a[mf][2], a[mf][3], h1, h3);
                }
            }
        }
        CP_WAIT1();
        __syncthreads();
    }
#undef PREFETCH

    // ---- epilogue ----
    float* C = (z == 0) ? Qh : (z == 1) ? Kh : out;
#pragma unroll
    for (int mf = 0; mf < 4; mf++) {
        int m = m0 + wm * 64 + mf * 16 + gid;
#pragma unroll
        for (int nf = 0; nf < 4; nf++) {
            int n = n0 + wn * 32 + nf * 8 + tig * 2;
            float b0 = __ldg(&bias[n]), b1 = __ldg(&bias[n + 1]);
            float x0 = c[mf][nf][0] + b0, x1 = c[mf][nf][1] + b1;
            float x2 = c[mf][nf][2] + b0, x3 = c[mf][nf][3] + b1;
            if (z == 2) {
                // V path: head-major fp16: m -> (b, t); n -> (h, d)
                int bb = m >> 11, tt = m & 2047;
                int hh = n >> 6,  dd = n & 63;
                size_t o0 = ((size_t)(bb * H + hh) * T + tt) * DH + dd;
                size_t o1 = o0 + 8 * DH;   // row m+8
                __half2 hp0 = __floats2half2_rn(x0, x1);
                __half2 hp1 = __floats2half2_rn(x2, x3);
                *(uint32_t*)&Vhi[o0] = *(uint32_t*)&hp0;
                *(uint32_t*)&Vhi[o1] = *(uint32_t*)&hp1;
            } else {
                *(float2*)&C[(size_t)m * GN + n]       = make_float2(x0, x1);
                *(float2*)&C[(size_t)(m + 8) * GN + n] = make_float2(x2, x3);
            }
        }
    }
}

// ---------------------------------------------------------------------------
// RMSNorm + RoPE (table), fused Q/K by blockIdx.y -> head-major fp16.
// ---------------------------------------------------------------------------
__global__ __launch_bounds__(256) void rmsropeb_kernel(
    const float* __restrict__ Qh, const float* __restrict__ Kh,
    const float* __restrict__ sq, const float* __restrict__ sk,
    const float2* __restrict__ TabQ, const float2* __restrict__ TabK,
    __half* __restrict__ Qhi, __half* __restrict__ Khi)
{
    const int yk = blockIdx.y;
    const float* X = yk ? Kh : Qh;
    const float* scale = yk ? sk : sq;
    const float2* tab = yk ? TabK : TabQ;
    __half* hi = yk ? Khi : Qhi;

    const int warp = threadIdx.x >> 5;
    const int lane = threadIdx.x & 31;
    const long long gw = (long long)blockIdx.x * 8 + warp;   // 0..B*T*H-1
    const int h = (int)(gw & (H - 1));
    const long long row = gw >> 3;                           // b*T + t
    const int b = (int)(row >> 11);
    const int t = (int)(row & 2047);

    const float* xp = X + row * D + h * DH;
    float x0 = xp[lane];
    float x1 = xp[lane + 32];

    float ss = x0 * x0 + x1 * x1;
#pragma unroll
    for (int o = 16; o; o >>= 1) ss += __shfl_xor_sync(0xffffffffu, ss, o);

    float r = rsqrtf(ss * (1.0f / 64.0f) + 1e-6f);
    float y0 = x0 * r * (1.0f + scale[lane]);
    float y1 = x1 * r * (1.0f + scale[lane + 32]);

    float2 sc = tab[(size_t)row * 32 + lane];
    float v0 = y0 * sc.y - y1 * sc.x;
    float v1 = y1 * sc.y + y0 * sc.x;

    size_t o0 = ((size_t)(b * H + h) * T + t) * DH + lane;
    hi[o0]      = __float2half_rn(v0);
    hi[o0 + 32] = __float2half_rn(v1);
}

// ---------------------------------------------------------------------------
// HMMA causal flash attention, 8 warps x 16 queries, cp.async K/V pipeline:
//   S = Qhi Khi^T (1 MMA) ; O = Phi Vhi (1 MMA)
// grid (8, 32), pass pairing (qt, 15-qt). All fragments via ldmatrix;
// V row-major + ldmatrix.trans. Output: fp16 activations [row][512].
// smem: Q 128x72 | K[2] 64x72 | V[2] 64x72 = 55296 B
// ---------------------------------------------------------------------------
#define ATT_SMEM 55296

__global__ __launch_bounds__(256, 2) void attn_mma_kernel(
    const __half* __restrict__ Qhi, const __half* __restrict__ Khi,
    const __half* __restrict__ Vhi,
    __half* __restrict__ Ohi)
{
    extern __shared__ char sm[];
    __half (*Qsh)[72] = (__half(*)[72])(sm);

    const uint32_t smb = smem_u32(sm);
    const int tid  = threadIdx.x;
    const int lane = tid & 31;
    const int w    = tid >> 5;          // 0..7
    const int gid  = lane >> 2;
    const int tig  = lane & 3;
    const int lr   = lane & 15;
    const int lc   = (lane >> 4) * 8;
    const int bh   = blockIdx.y;
    const int b    = bh >> 3;
    const int h    = bh & 7;
    const size_t headbase = (size_t)bh * T * DH;

    const uint32_t smK[2] = {smb + 18432, smb + 27648};
    const uint32_t smV[2] = {smb + 36864, smb + 46080};
    const uint32_t qoff = smb + (uint32_t)((w * 16 + lr) * 144 + lc * 2);
    const uint32_t kro  = (uint32_t)(lr * 144 + lc * 2);

    // per-thread K/V prefetch slice (row stride 144 B)
    const int pkey = tid >> 2;
    const int pc8  = (tid & 3) * 16;

    for (int pass = 0; pass < 2; pass++) {
        const int qt = pass ? (15 - (int)blockIdx.x) : (int)blockIdx.x;
        const int q0 = qt * 128;
        const int qwb = q0 + w * 16;
        const int nkt = (qt + 1) * 2;

        // prefetch first K/V tile (stage 0 safe: previous pass fully drained)
        {
            size_t g = headbase + (size_t)pkey * DH + pc8;
            uint32_t sk = smK[0] + (uint32_t)(pkey * 144 + pc8 * 2);
            uint32_t sv = smV[0] + (uint32_t)(pkey * 144 + pc8 * 2);
            cp16(sk, Khi + g); cp16(sk + 16, Khi + g + 8);
            cp16(sv, Vhi + g); cp16(sv + 16, Vhi + g + 8);
        }
        CP_COMMIT();

        // ---- load Q tile (128x64) ----
#pragma unroll
        for (int i = 0; i < 4; i++) {
            int idx = tid + i * 256;
            int row = idx >> 3;
            int c8  = (idx & 7) * 8;
            size_t g = headbase + (size_t)(q0 + row) * DH + c8;
            *(uint4*)&Qsh[row][c8] = *(const uint4*)&Qhi[g];
        }

        float O[8][4];
#pragma unroll
        for (int nf = 0; nf < 8; nf++)
#pragma unroll
            for (int r = 0; r < 4; r++) O[nf][r] = 0.f;
        float mrow[2] = {-1e30f, -1e30f};
        float lrow[2] = {0.f, 0.f};

        for (int kt = 0; kt < nkt; kt++) {
            const int st = kt & 1;
            CP_WAIT0();
            __syncthreads();
            // prefetch next tile into the other stage (all warps are past
            // the compute that last read it, thanks to this barrier)
            if (kt + 1 < nkt) {
                size_t g = headbase + (size_t)((kt + 1) * 64 + pkey) * DH + pc8;
                uint32_t sk = smK[st ^ 1] + (uint32_t)(pkey * 144 + pc8 * 2);
                uint32_t sv = smV[st ^ 1] + (uint32_t)(pkey * 144 + pc8 * 2);
                cp16(sk, Khi + g); cp16(sk + 16, Khi + g + 8);
                cp16(sv, Vhi + g); cp16(sv + 16, Vhi + g + 8);
            }
            CP_COMMIT();

            const int n0 = kt * 64;
            const bool active = (n0 <= qwb + 15);
            if (active) {
                // ---- S = Qhi Khi^T ----
                float S[8][4];
#pragma unroll
                for (int nf = 0; nf < 8; nf++)
#pragma unroll
                    for (int r = 0; r < 4; r++) S[nf][r] = 0.f;

#pragma unroll
                for (int ks = 0; ks < 4; ks++) {
                    uint32_t a0, a1, a2, a3;
                    ldsm4(a0, a1, a2, a3, qoff + ks * 32);
#pragma unroll
                    for (int p = 0; p < 4; p++) {
                        uint32_t h0, h1, h2, h3;
                        ldsm4(h0, h1, h2, h3, smK[st] + kro + p * 2304 + ks * 32);
                        mma16816(S[2*p][0], S[2*p][1], S[2*p][2], S[2*p][3],
                                 a0, a1, a2, a3, h0, h2);
                        mma16816(S[2*p+1][0], S[2*p+1][1], S[2*p+1][2], S[2*p+1][3],
                                 a0, a1, a2, a3, h1, h3);
                    }
                }

                // ---- scale + causal mask ----
                const bool needmask = (n0 + 63) > qwb;
#pragma unroll
                for (int nf = 0; nf < 8; nf++)
#pragma unroll
                    for (int r = 0; r < 4; r++) {
                        float s = S[nf][r] * 0.125f;
                        if (needmask) {
                            int key = n0 + nf * 8 + tig * 2 + (r & 1);
                            int qv  = qwb + gid + ((r >> 1) ? 8 : 0);
                            if (key > qv) s = -1e30f;
                        }
                        S[nf][r] = s;
                    }

                // ---- online softmax (rid = r>>1: rows gid, gid+8) ----
                float mt[2] = {-1e30f, -1e30f};
#pragma unroll
                for (int nf = 0; nf < 8; nf++)
#pragma unroll
                    for (int r = 0; r < 4; r++)
                        mt[r >> 1] = fmaxf(mt[r >> 1], S[nf][r]);
#pragma unroll
                for (int rid = 0; rid < 2; rid++) {
                    mt[rid] = fmaxf(mt[rid], __shfl_xor_sync(0xffffffffu, mt[rid], 1));
                    mt[rid] = fmaxf(mt[rid], __shfl_xor_sync(0xffffffffu, mt[rid], 2));
                }
                float corr[2];
#pragma unroll
                for (int rid = 0; rid < 2; rid++) {
                    float nm = fmaxf(mrow[rid], mt[rid]);
                    corr[rid] = __expf(mrow[rid] - nm);
                    mrow[rid] = nm;
                }
                float rs[2] = {0.f, 0.f};
#pragma unroll
                for (int nf = 0; nf < 8; nf++)
#pragma unroll
                    for (int r = 0; r < 4; r++) {
                        float p = __expf(S[nf][r] - mrow[r >> 1]);
                        S[nf][r] = p;
                        rs[r >> 1] += p;
                    }
#pragma unroll
                for (int rid = 0; rid < 2; rid++) {
                    rs[rid] += __shfl_xor_sync(0xffffffffu, rs[rid], 1);
                    rs[rid] += __shfl_xor_sync(0xffffffffu, rs[rid], 2);
                    lrow[rid] = lrow[rid] * corr[rid] + rs[rid];
                }
#pragma unroll
                for (int nf = 0; nf < 8; nf++)
#pragma unroll
                    for (int r = 0; r < 4; r++)
                        O[nf][r] *= corr[r >> 1];

                // ---- pack P to fp16 A-fragments ----
                uint32_t ph[8][2];
#pragma unroll
                for (int nf = 0; nf < 8; nf++) {
                    __half2 hp0 = __floats2half2_rn(S[nf][0], S[nf][1]);
                    __half2 hp1 = __floats2half2_rn(S[nf][2], S[nf][3]);
                    ph[nf][0] = *(uint32_t*)&hp0;
                    ph[nf][1] = *(uint32_t*)&hp1;
                }

                // ---- O += Phi Vhi (V via ldmatrix.trans) ----
#pragma unroll
                for (int ks = 0; ks < 4; ks++) {
                    uint32_t a0 = ph[2*ks][0], a1 = ph[2*ks][1];
                    uint32_t a2 = ph[2*ks+1][0], a3 = ph[2*ks+1][1];
#pragma unroll
                    for (int p = 0; p < 4; p++) {
                        uint32_t v0, v1, v2, v3;
                        ldsm4t(v0, v1, v2, v3, smV[st] + kro + ks * 2304 + p * 32);
                        mma16816(O[2*p][0], O[2*p][1], O[2*p][2], O[2*p][3],
                                 a0, a1, a2, a3, v0, v1);
                        mma16816(O[2*p+1][0], O[2*p+1][1], O[2*p+1][2], O[2*p+1][3],
                                 a0, a1, a2, a3, v2, v3);
                    }
                }
            }
        }

        // ---- epilogue: normalize, store fp16 activations [row][512] ----
        float linv[2] = {1.0f / lrow[0], 1.0f / lrow[1]};
        const int tq0 = q0 + w * 16 + gid;
#pragma unroll
        for (int nf = 0; nf < 8; nf++) {
            int d = nf * 8 + tig * 2;
#pragma unroll
            for (int half = 0; half < 2; half++) {
                int tq = tq0 + (half ? 8 : 0);
                float o0 = O[nf][half * 2]     * linv[half];
                float o1 = O[nf][half * 2 + 1] * linv[half];
                __half2 hp = __floats2half2_rn(o0, o1);
                size_t oi = ((size_t)(b * T + tq)) * D + h * DH + d;
                *(uint32_t*)&Ohi[oi] = *(uint32_t*)&hp;
            }
        }
        CP_WAIT0();
        __syncthreads();   // all reads done + pipeline drained before next pass
    }
}

// ---------------------------------------------------------------------------
// Launcher
// Inputs: 0 q, 1 kv, 2 mask, 3 q_pos, 4 kv_pos, 5 wq, 6 bq, 7 wk, 8 bk,
//         9 wv, 10 bv, 11 scale_q, 12 scale_k, 13 wo, 14 bo
// ---------------------------------------------------------------------------
extern "C" void kernel_launch(void* const* d_in, const int* in_sizes, int n_in,
                              void* d_out, int out_size)
{
    const float* q   = (const float*)d_in[0];
    const float* kv  = (const float*)d_in[1];
    const int*   qp  = (const int*)d_in[3];
    const int*   kp  = (const int*)d_in[4];
    const float* wq  = (const float*)d_in[5];
    const float* bq  = (const float*)d_in[6];
    const float* wk  = (const float*)d_in[7];
    const float* bk  = (const float*)d_in[8];
    const float* wv  = (const float*)d_in[9];
    const float* bv  = (const float*)d_in[10];
    const float* sq  = (const float*)d_in[11];
    const float* sk  = (const float*)d_in[12];
    const float* wo  = (const float*)d_in[13];
    const float* bo  = (const float*)d_in[14];
    float* out = (float*)d_out;

    float *Qh, *Kh;
    float2 *TabQ, *TabK;
    __half *Aq, *Akv, *W4, *Qhi, *Khi, *Vhi;
    cudaGetSymbolAddress((void**)&Qh, g_Qh);
    cudaGetSymbolAddress((void**)&Kh, g_Kh);
    cudaGetSymbolAddress((void**)&Aq, g_Aq);
    cudaGetSymbolAddress((void**)&Akv, g_Akv);
    cudaGetSymbolAddress((void**)&W4, g_W4);
    cudaGetSymbolAddress((void**)&TabQ, g_TabQ);
    cudaGetSymbolAddress((void**)&TabK, g_TabK);
    cudaGetSymbolAddress((void**)&Qhi, g_Qhi);
    cudaGetSymbolAddress((void**)&Khi, g_Khi);
    cudaGetSymbolAddress((void**)&Vhi, g_Vhi);

    cudaFuncSetAttribute(attn_mma_kernel,
                         cudaFuncAttributeMaxDynamicSharedMemorySize, ATT_SMEM);
    cudaFuncSetAttribute(gemm_all_kernel,
                         cudaFuncAttributeMaxDynamicSharedMemorySize, GSMEM);

    // 1. fused prep: weight transposes + fp16 splits + RoPE tables
    prep_kernel<<<11264, 256>>>(q, kv, qp, kp, wq, wk, wv, wo,
                                Aq, Akv, W4, TabQ, TabK);
    // 2. Q/K/V projections in one launch (z = 0,1,2)
    gemm_all_kernel<<<dim3(4, 64, 3), 256, GSMEM>>>(
        0, Aq, Akv, W4, bq, bk, bv, bo, Qh, Kh, Vhi, nullptr);
    // 3. norm + rope for Q and K
    rmsropeb_kernel<<<dim3(M_ROWS, 2), 256>>>(
        Qh, Kh, sq, sk, TabQ, TabK, Qhi, Khi);
    // 4. attention (writes fp16 activations into Aq)
    attn_mma_kernel<<<dim3(8, BH), 256, ATT_SMEM>>>(Qhi, Khi, Vhi, Aq);
    // 5. output projection (z = 3)
    gemm_all_kernel<<<dim3(4, 64, 1), 256, GSMEM>>>(
        3, Aq, Akv, W4, bq, bk, bv, bo, Qh, Kh, Vhi, out);
}